// round 6
// baseline (speedup 1.0000x reference)
#include <cuda_runtime.h>
#include <cuda_bf16.h>
#include <cstdint>
#include <math.h>

#define D_MODEL 1024
#define D_STATE 16
#define D_INNER 2048
#define DT_RANK 64
#define BATCH   4
#define SEQLEN  2048
#define ROWS    (BATCH * SEQLEN)   // 8192

// ---------------- device scratch (allocation-free rule) -----------------------
__device__ __align__(16) float g_u[ROWS * D_INNER];
__device__ __align__(16) float g_z[ROWS * D_INNER];
__device__ __align__(16) float g_uc[ROWS * D_INNER];
__device__ __align__(16) float g_delta[ROWS * D_INNER];
__device__ __align__(16) float g_dtr[ROWS * DT_RANK];
__device__ __align__(16) float g_Bm[ROWS * D_STATE];
__device__ __align__(16) float g_Cm[ROWS * D_STATE];

// packed bf16 operands (hi|hi|lo along K for A; hi|lo|hi for B^T)
__device__ __align__(16) __nv_bfloat16 g_x2  [ROWS * 3 * D_MODEL];
__device__ __align__(16) __nv_bfloat16 g_Win2[(2*D_INNER) * 3 * D_MODEL];
__device__ __align__(16) __nv_bfloat16 g_uc2 [ROWS * 3 * D_INNER];
__device__ __align__(16) __nv_bfloat16 g_Wxp2[128 * 3 * D_INNER];
__device__ __align__(16) __nv_bfloat16 g_dtr2[ROWS * 3 * DT_RANK];
__device__ __align__(16) __nv_bfloat16 g_Wdt2[D_INNER * 3 * DT_RANK];
__device__ __align__(16) __nv_bfloat16 g_y2  [ROWS * 3 * D_INNER];
__device__ __align__(16) __nv_bfloat16 g_Wout2[D_MODEL * 3 * D_INNER];

// ---------------- helpers -----------------------------------------------------
__device__ __forceinline__ uint32_t smem_u32(const void* p) {
    uint32_t a;
    asm("{ .reg .u64 t; cvta.to.shared.u64 t, %1; cvt.u32.u64 %0, t; }" : "=r"(a) : "l"(p));
    return a;
}
__device__ __forceinline__ void cp16(uint32_t saddr, const void* gaddr) {
    asm volatile("cp.async.cg.shared.global [%0], [%1], 16;" :: "r"(saddr), "l"(gaddr));
}
#define SWZ(o) ((o) ^ ((((uint32_t)(o)) >> 3) & 0x70))

__device__ __forceinline__ void ldm_x4(uint32_t& r0, uint32_t& r1, uint32_t& r2, uint32_t& r3,
                                       uint32_t addr) {
    asm volatile("ldmatrix.sync.aligned.m8n8.x4.shared.b16 {%0,%1,%2,%3}, [%4];"
                 : "=r"(r0), "=r"(r1), "=r"(r2), "=r"(r3) : "r"(addr));
}
__device__ __forceinline__ void mma16816(float& c0, float& c1, float& c2, float& c3,
                                         uint32_t a0, uint32_t a1, uint32_t a2, uint32_t a3,
                                         uint32_t b0, uint32_t b1) {
    asm volatile("mma.sync.aligned.m16n8k16.row.col.f32.bf16.bf16.f32 "
                 "{%0,%1,%2,%3}, {%4,%5,%6,%7}, {%8,%9}, {%0,%1,%2,%3};"
                 : "+f"(c0), "+f"(c1), "+f"(c2), "+f"(c3)
                 : "r"(a0), "r"(a1), "r"(a2), "r"(a3), "r"(b0), "r"(b1));
}
__device__ __forceinline__ void split_bf16(float v, __nv_bfloat16& h, __nv_bfloat16& l) {
    h = __float2bfloat16(v);
    l = __float2bfloat16(v - __bfloat162float(h));
}

// ---------------- bf16 mma.sync GEMM ------------------------------------------
// C[M,N] = A[M,Kp] * Bt[N,Kp]^T, both bf16 K-major row-major, fp32 accumulate.
// BM=256, BN=128, BK=64. 512 threads = 16 warps in 4(M)x4(N), warp tile 64x32.
// 4-stage cp.async pipeline (192 KB smem). 4 warps/SMSP for latency hiding.
enum { EPI_PLAIN = 0, EPI_SPLIT = 1, EPI_SOFTPLUS = 2, EPI_XPROJ = 3 };

#define GBM 256
#define GBN 128
#define GBK 64
#define GSTAGES 4
#define GTILEA_B (GBM * GBK * 2)         // 32768
#define GTILEB_B (GBN * GBK * 2)         // 16384
#define GSTAGE_B (GTILEA_B + GTILEB_B)   // 49152
#define GEMM_SMEM (GSTAGES * GSTAGE_B)   // 196608

template <int EPI>
__global__ __launch_bounds__(512, 1)
void gemm_tc(const __nv_bfloat16* __restrict__ A, const __nv_bfloat16* __restrict__ Bt,
             int Kp, int N,
             float* __restrict__ O0, float* __restrict__ O1, float* __restrict__ O2,
             const float* __restrict__ bias)
{
    extern __shared__ char smem[];
    const uint32_t sb = smem_u32(smem);
    const int tid = threadIdx.x;
    const int wid = tid >> 5, lid = tid & 31;
    const int wr = wid & 3;          // M warp index: rows 64*wr
    const int wc = wid >> 2;         // N warp index: cols 32*wc
    const int m0 = blockIdx.y * GBM;
    const int n0 = blockIdx.x * GBN;
    const int chunks = Kp / GBK;

    const __nv_bfloat16* Ap = A + (size_t)m0 * Kp;
    const __nv_bfloat16* Bp = Bt + (size_t)n0 * Kp;

    // cp.async mapping: 512 threads = 64 rows x 8 chunk-cols per pass
    const int ldrow = tid >> 3;      // 0..63
    const int ldch  = tid & 7;

    auto load_stage = [&](int c) {
        const int s = c & (GSTAGES - 1);
        const uint32_t sa = sb + s * GSTAGE_B;
        const uint32_t sB = sa + GTILEA_B;
        const int k0 = c * GBK;
        #pragma unroll
        for (int j = 0; j < 4; ++j) {
            const int r = ldrow + j * 64;
            const uint32_t so = SWZ(r * 128 + ldch * 16);
            cp16(sa + so, Ap + (size_t)r * Kp + k0 + ldch * 8);
        }
        #pragma unroll
        for (int j = 0; j < 2; ++j) {
            const int r = ldrow + j * 64;
            const uint32_t so = SWZ(r * 128 + ldch * 16);
            cp16(sB + so, Bp + (size_t)r * Kp + k0 + ldch * 8);
        }
        asm volatile("cp.async.commit_group;" ::: "memory");
    };

    const int pre = (chunks < GSTAGES - 1) ? chunks : (GSTAGES - 1);
    for (int c = 0; c < pre; ++c) load_stage(c);

    float acc[4][4][4];
    #pragma unroll
    for (int i = 0; i < 4; ++i)
        #pragma unroll
        for (int j = 0; j < 4; ++j)
            #pragma unroll
            for (int k = 0; k < 4; ++k) acc[i][j][k] = 0.f;

    const int lrow = lid & 15;
    const int lhalf = lid >> 4;

    for (int c = 0; c < chunks; ++c) {
        // groups issued so far: min(c + GSTAGES-1, chunks); need chunk c done
        const int issued = (c + GSTAGES - 1 < chunks) ? (c + GSTAGES - 1) : chunks;
        const int allowed = issued - (c + 1);
        if (allowed >= 2)      asm volatile("cp.async.wait_group 2;" ::: "memory");
        else if (allowed == 1) asm volatile("cp.async.wait_group 1;" ::: "memory");
        else                   asm volatile("cp.async.wait_group 0;" ::: "memory");
        __syncthreads();

        if (c + GSTAGES - 1 < chunks) load_stage(c + GSTAGES - 1);

        const int s = c & (GSTAGES - 1);
        const uint32_t sa = sb + s * GSTAGE_B;
        const uint32_t sB = sa + GTILEA_B;

        #pragma unroll
        for (int kk = 0; kk < 4; ++kk) {
            uint32_t a[4][4];
            #pragma unroll
            for (int wm = 0; wm < 4; ++wm) {
                const int row = wr * 64 + wm * 16 + lrow;
                const uint32_t off = SWZ(row * 128 + (kk * 2 + lhalf) * 16);
                ldm_x4(a[wm][0], a[wm][1], a[wm][2], a[wm][3], sa + off);
            }
            uint32_t b[2][4];
            #pragma unroll
            for (int g = 0; g < 2; ++g) {
                const int row = wc * 32 + g * 16 + lrow;
                const uint32_t off = SWZ(row * 128 + (kk * 2 + lhalf) * 16);
                ldm_x4(b[g][0], b[g][1], b[g][2], b[g][3], sB + off);
            }
            #pragma unroll
            for (int wm = 0; wm < 4; ++wm)
                #pragma unroll
                for (int j = 0; j < 4; ++j) {
                    const int g = j >> 1, h = j & 1;
                    mma16816(acc[wm][j][0], acc[wm][j][1], acc[wm][j][2], acc[wm][j][3],
                             a[wm][0], a[wm][1], a[wm][2], a[wm][3],
                             b[g][h], b[g][2 + h]);
                }
        }
    }

    // ---------------- epilogue ------------------------------------------------
    const int tq = lid >> 2;
    const int tr = lid & 3;
    const int H = N >> 1;
    #pragma unroll
    for (int wm = 0; wm < 4; ++wm) {
        #pragma unroll
        for (int j = 0; j < 4; ++j) {
            #pragma unroll
            for (int half = 0; half < 2; ++half) {
                const int gr = m0 + wr * 64 + wm * 16 + tq + half * 8;
                const int gc = n0 + wc * 32 + j * 8 + tr * 2;
                float v0 = acc[wm][j][half * 2 + 0];
                float v1 = acc[wm][j][half * 2 + 1];
                if (EPI == EPI_PLAIN) {
                    float2 v = {v0, v1};
                    *(float2*)&O0[(size_t)gr * N + gc] = v;
                } else if (EPI == EPI_SPLIT) {
                    float2 v = {v0, v1};
                    if (gc < H) *(float2*)&O0[(size_t)gr * H + gc] = v;
                    else        *(float2*)&O1[(size_t)gr * H + (gc - H)] = v;
                } else if (EPI == EPI_SOFTPLUS) {
                    v0 += bias[gc]; v1 += bias[gc + 1];
                    v0 = (v0 > 20.0f) ? v0 : log1pf(__expf(v0));
                    v1 = (v1 > 20.0f) ? v1 : log1pf(__expf(v1));
                    float2 v = {v0, v1};
                    *(float2*)&O0[(size_t)gr * N + gc] = v;
                } else { // EPI_XPROJ
                    float2 v = {v0, v1};
                    if (gc < DT_RANK)           *(float2*)&O0[(size_t)gr * DT_RANK + gc] = v;
                    else if (gc < DT_RANK + 16) *(float2*)&O1[(size_t)gr * 16 + (gc - DT_RANK)] = v;
                    else if (gc < DT_RANK + 32) *(float2*)&O2[(size_t)gr * 16 + (gc - DT_RANK - 16)] = v;
                }
            }
        }
    }
}

// ---------------- packing kernels ---------------------------------------------
// flat 1D: each thread packs one float4 (4 elems) of one row
__global__ __launch_bounds__(256)
void packA_kernel(const float* __restrict__ in, __nv_bfloat16* __restrict__ out,
                  int K, int total4)
{
    const int idx = blockIdx.x * 256 + threadIdx.x;
    if (idx >= total4) return;
    const int kq = K >> 2;
    const int m = idx / kq;
    const int k = (idx - m * kq) * 4;
    const float4 v = *(const float4*)(in + (size_t)m * K + k);
    __nv_bfloat16 h0, h1, h2, h3, l0, l1, l2, l3;
    split_bf16(v.x, h0, l0);
    split_bf16(v.y, h1, l1);
    split_bf16(v.z, h2, l2);
    split_bf16(v.w, h3, l3);
    __nv_bfloat16* op = out + (size_t)m * 3 * K;
    __nv_bfloat162 hh01; hh01.x = h0; hh01.y = h1;
    __nv_bfloat162 hh23; hh23.x = h2; hh23.y = h3;
    __nv_bfloat162 ll01; ll01.x = l0; ll01.y = l1;
    __nv_bfloat162 ll23; ll23.x = l2; ll23.y = l3;
    *(__nv_bfloat162*)(op + k)             = hh01;
    *(__nv_bfloat162*)(op + k + 2)         = hh23;
    *(__nv_bfloat162*)(op + K + k)         = hh01;
    *(__nv_bfloat162*)(op + K + k + 2)     = hh23;
    *(__nv_bfloat162*)(op + 2 * K + k)     = ll01;
    *(__nv_bfloat162*)(op + 2 * K + k + 2) = ll23;
}

__global__ __launch_bounds__(256)
void packBt_kernel(const float* __restrict__ in, __nv_bfloat16* __restrict__ out,
                   int K, int N, int Np)
{
    __shared__ float s[32][33];
    const int kb = blockIdx.x * 32, nb = blockIdx.y * 32;
    const int tx = threadIdx.x & 31, ty = threadIdx.x >> 5;
    #pragma unroll
    for (int r = 0; r < 32; r += 8) {
        const int k = kb + ty + r, n = nb + tx;
        s[ty + r][tx] = (k < K && n < N) ? in[(size_t)k * N + n] : 0.0f;
    }
    __syncthreads();
    #pragma unroll
    for (int r = 0; r < 32; r += 8) {
        const int n = nb + ty + r, k = kb + tx;
        if (n < Np && k < K) {
            const float v = s[tx][ty + r];
            __nv_bfloat16 h, lo;
            split_bf16(v, h, lo);
            __nv_bfloat16* op = out + (size_t)n * 3 * K;
            op[k] = h; op[K + k] = lo; op[2 * K + k] = h;
        }
    }
}

// ---------------- causal depthwise conv (k=4) + SiLU + pack -------------------
__global__ __launch_bounds__(256)
void conv_silu_kernel(const float* __restrict__ u, const float* __restrict__ w,
                      const float* __restrict__ bias, float* __restrict__ uc,
                      __nv_bfloat16* __restrict__ uc2)
{
    constexpr int CHUNK = 16;
    int gid = blockIdx.x * blockDim.x + threadIdx.x;
    int d = gid & (D_INNER - 1);
    int rest = gid >> 11;
    int b = rest & (BATCH - 1);
    int chunk = rest >> 2;
    int l0 = chunk * CHUNK;

    const float w0 = w[d * 4 + 0], w1 = w[d * 4 + 1],
                w2 = w[d * 4 + 2], w3 = w[d * 4 + 3];
    const float bb = bias[d];

    const size_t base = ((size_t)b * SEQLEN + l0) * D_INNER + d;
    const float* up = u + base;
    float* op = uc + base;
    __nv_bfloat16* pp = uc2 + ((size_t)b * SEQLEN + l0) * 3 * D_INNER + d;

    float xm3, xm2, xm1;
    if (l0 == 0) { xm3 = 0.f; xm2 = 0.f; xm1 = 0.f; }
    else {
        xm3 = up[-3 * D_INNER];
        xm2 = up[-2 * D_INNER];
        xm1 = up[-1 * D_INNER];
    }
    #pragma unroll
    for (int i = 0; i < CHUNK; ++i) {
        float cur = up[(size_t)i * D_INNER];
        float v = fmaf(xm3, w0, fmaf(xm2, w1, fmaf(xm1, w2, fmaf(cur, w3, bb))));
        float s = v / (1.0f + __expf(-v));
        op[(size_t)i * D_INNER] = s;
        __nv_bfloat16 h, lo;
        split_bf16(s, h, lo);
        __nv_bfloat16* q = pp + (size_t)i * 3 * D_INNER;
        q[0] = h; q[D_INNER] = h; q[2 * D_INNER] = lo;
        xm3 = xm2; xm2 = xm1; xm1 = cur;
    }
}

// ---------------- selective scan ----------------------------------------------
__global__ __launch_bounds__(128)
void scan_kernel(const float* __restrict__ delta, const float* __restrict__ u,
                 const float* __restrict__ z, const float* __restrict__ Bm,
                 const float* __restrict__ Cm, const float* __restrict__ A_log,
                 const float* __restrict__ Dp, __nv_bfloat16* __restrict__ y2)
{
    const int t = blockIdx.x * blockDim.x + threadIdx.x;
    const int sub = t & 3;
    const int ch = t >> 2;
    const int d = ch & (D_INNER - 1);
    const int b = ch >> 11;
    const int n0 = sub * 4;

    const float a0 = -__expf(A_log[d * D_STATE + n0 + 0]);
    const float a1 = -__expf(A_log[d * D_STATE + n0 + 1]);
    const float a2 = -__expf(A_log[d * D_STATE + n0 + 2]);
    const float a3 = -__expf(A_log[d * D_STATE + n0 + 3]);

    const bool fast =
        fabsf(a0 + (float)(n0 + 1)) < 1e-3f * (n0 + 1) &&
        fabsf(a1 + (float)(n0 + 2)) < 1e-3f * (n0 + 2) &&
        fabsf(a2 + (float)(n0 + 3)) < 1e-3f * (n0 + 3) &&
        fabsf(a3 + (float)(n0 + 4)) < 1e-3f * (n0 + 4);

    const size_t base = (size_t)b * SEQLEN * D_INNER + d;
    const float* dp = delta + base;
    const float* up = u + base;
    const float* zp = z + base;
    __nv_bfloat16* yp = y2 + (size_t)b * SEQLEN * 3 * D_INNER + d;
    const float4* Bp = (const float4*)Bm + (size_t)b * SEQLEN * 4 + sub;
    const float4* Cp = (const float4*)Cm + (size_t)b * SEQLEN * 4 + sub;
    const float Dd = Dp[d];

    float h0 = 0.f, h1 = 0.f, h2 = 0.f, h3 = 0.f;

    if (fast) {
        #pragma unroll 2
        for (int l = 0; l < SEQLEN; ++l) {
            const float dt = dp[(size_t)l * D_INNER];
            const float uu = up[(size_t)l * D_INNER];
            const float4 Bv = Bp[(size_t)l * 4];
            const float4 Cv = Cp[(size_t)l * 4];
            const float e  = __expf(-dt);
            const float e2 = e * e;
            const float e4 = e2 * e2;
            const float e8 = e4 * e4;
            float m = 1.f;
            if (sub & 1) m = e4;
            if (sub & 2) m *= e8;
            const float dA0 = m * e;
            const float dA1 = dA0 * e;
            const float dA2 = dA1 * e;
            const float dA3 = dA2 * e;
            const float xv = dt * uu;
            h0 = fmaf(h0, dA0, xv * Bv.x);
            h1 = fmaf(h1, dA1, xv * Bv.y);
            h2 = fmaf(h2, dA2, xv * Bv.z);
            h3 = fmaf(h3, dA3, xv * Bv.w);
            float yv = h0 * Cv.x + h1 * Cv.y + h2 * Cv.z + h3 * Cv.w;
            yv += __shfl_xor_sync(0xffffffffu, yv, 1);
            yv += __shfl_xor_sync(0xffffffffu, yv, 2);
            if (sub == 0) {
                const float zz = zp[(size_t)l * D_INNER];
                const float sz = zz / (1.0f + __expf(-zz));
                const float yo = (yv + uu * Dd) * sz;
                __nv_bfloat16 h, lo;
                split_bf16(yo, h, lo);
                __nv_bfloat16* q = yp + (size_t)l * 3 * D_INNER;
                q[0] = h; q[D_INNER] = h; q[2 * D_INNER] = lo;
            }
        }
    } else {
        #pragma unroll 2
        for (int l = 0; l < SEQLEN; ++l) {
            const float dt = dp[(size_t)l * D_INNER];
            const float uu = up[(size_t)l * D_INNER];
            const float4 Bv = Bp[(size_t)l * 4];
            const float4 Cv = Cp[(size_t)l * 4];
            const float dA0 = __expf(dt * a0);
            const float dA1 = __expf(dt * a1);
            const float dA2 = __expf(dt * a2);
            const float dA3 = __expf(dt * a3);
            const float xv = dt * uu;
            h0 = fmaf(h0, dA0, xv * Bv.x);
            h1 = fmaf(h1, dA1, xv * Bv.y);
            h2 = fmaf(h2, dA2, xv * Bv.z);
            h3 = fmaf(h3, dA3, xv * Bv.w);
            float yv = h0 * Cv.x + h1 * Cv.y + h2 * Cv.z + h3 * Cv.w;
            yv += __shfl_xor_sync(0xffffffffu, yv, 1);
            yv += __shfl_xor_sync(0xffffffffu, yv, 2);
            if (sub == 0) {
                const float zz = zp[(size_t)l * D_INNER];
                const float sz = zz / (1.0f + __expf(-zz));
                const float yo = (yv + uu * Dd) * sz;
                __nv_bfloat16 h, lo;
                split_bf16(yo, h, lo);
                __nv_bfloat16* q = yp + (size_t)l * 3 * D_INNER;
                q[0] = h; q[D_INNER] = h; q[2 * D_INNER] = lo;
            }
        }
    }
}

// ---------------- launch ------------------------------------------------------
extern "C" void kernel_launch(void* const* d_in, const int* in_sizes, int n_in,
                              void* d_out, int out_size)
{
    const float* x      = (const float*)d_in[0];
    const float* W_in   = (const float*)d_in[1];
    const float* conv_w = (const float*)d_in[2];
    const float* conv_b = (const float*)d_in[3];
    const float* W_xprj = (const float*)d_in[4];
    const float* W_dt   = (const float*)d_in[5];
    const float* b_dt   = (const float*)d_in[6];
    const float* A_log  = (const float*)d_in[7];
    const float* Dp     = (const float*)d_in[8];
    const float* W_out  = (const float*)d_in[9];
    float* out = (float*)d_out;

    float *u, *z, *uc, *delta, *dtr, *Bm, *Cm;
    cudaGetSymbolAddress((void**)&u,     g_u);
    cudaGetSymbolAddress((void**)&z,     g_z);
    cudaGetSymbolAddress((void**)&uc,    g_uc);
    cudaGetSymbolAddress((void**)&delta, g_delta);
    cudaGetSymbolAddress((void**)&dtr,   g_dtr);
    cudaGetSymbolAddress((void**)&Bm,    g_Bm);
    cudaGetSymbolAddress((void**)&Cm,    g_Cm);

    __nv_bfloat16 *x2, *Win2, *uc2, *Wxp2, *dtr2, *Wdt2, *y2, *Wout2;
    cudaGetSymbolAddress((void**)&x2,    g_x2);
    cudaGetSymbolAddress((void**)&Win2,  g_Win2);
    cudaGetSymbolAddress((void**)&uc2,   g_uc2);
    cudaGetSymbolAddress((void**)&Wxp2,  g_Wxp2);
    cudaGetSymbolAddress((void**)&dtr2,  g_dtr2);
    cudaGetSymbolAddress((void**)&Wdt2,  g_Wdt2);
    cudaGetSymbolAddress((void**)&y2,    g_y2);
    cudaGetSymbolAddress((void**)&Wout2, g_Wout2);

    cudaFuncSetAttribute(gemm_tc<EPI_PLAIN>,   cudaFuncAttributeMaxDynamicSharedMemorySize, GEMM_SMEM);
    cudaFuncSetAttribute(gemm_tc<EPI_SPLIT>,   cudaFuncAttributeMaxDynamicSharedMemorySize, GEMM_SMEM);
    cudaFuncSetAttribute(gemm_tc<EPI_SOFTPLUS>,cudaFuncAttributeMaxDynamicSharedMemorySize, GEMM_SMEM);
    cudaFuncSetAttribute(gemm_tc<EPI_XPROJ>,   cudaFuncAttributeMaxDynamicSharedMemorySize, GEMM_SMEM);

    // weight packs up front (independent of activations)
    packBt_kernel<<<dim3(D_MODEL / 32, (2 * D_INNER) / 32), 256>>>(
        W_in, Win2, D_MODEL, 2 * D_INNER, 2 * D_INNER);
    packBt_kernel<<<dim3(D_INNER / 32, 128 / 32), 256>>>(
        W_xprj, Wxp2, D_INNER, DT_RANK + 2 * D_STATE, 128);
    packBt_kernel<<<dim3((DT_RANK + 31) / 32, D_INNER / 32), 256>>>(
        W_dt, Wdt2, DT_RANK, D_INNER, D_INNER);
    packBt_kernel<<<dim3(D_INNER / 32, D_MODEL / 32), 256>>>(
        W_out, Wout2, D_INNER, D_MODEL, D_MODEL);

    // ---- G1: xz = x @ W_in, split u|z --------------------------------------
    {
        const int total4 = ROWS * (D_MODEL / 4);
        packA_kernel<<<(total4 + 255) / 256, 256>>>(x, x2, D_MODEL, total4);
    }
    gemm_tc<EPI_SPLIT><<<dim3((2 * D_INNER) / GBN, ROWS / GBM), 512, GEMM_SMEM>>>(
        x2, Win2, 3 * D_MODEL, 2 * D_INNER, u, z, nullptr, nullptr);

    // ---- conv + silu + pack uc2 --------------------------------------------
    conv_silu_kernel<<<(BATCH * D_INNER * (SEQLEN / 16)) / 256, 256>>>(
        u, conv_w, conv_b, uc, uc2);

    // ---- G2: proj = uc @ W_xproj -> dtr|Bm|Cm ------------------------------
    gemm_tc<EPI_XPROJ><<<dim3(1, ROWS / GBM), 512, GEMM_SMEM>>>(
        uc2, Wxp2, 3 * D_INNER, 128, dtr, Bm, Cm, nullptr);

    // ---- G3: delta = softplus(dtr @ W_dt + b_dt) ---------------------------
    {
        const int total4 = ROWS * (DT_RANK / 4);
        packA_kernel<<<(total4 + 255) / 256, 256>>>(dtr, dtr2, DT_RANK, total4);
    }
    gemm_tc<EPI_SOFTPLUS><<<dim3(D_INNER / GBN, ROWS / GBM), 512, GEMM_SMEM>>>(
        dtr2, Wdt2, 3 * DT_RANK, D_INNER, delta, nullptr, nullptr, b_dt);

    // ---- scan + gating -> packed y2 ----------------------------------------
    scan_kernel<<<(ROWS * 4) / 128, 128>>>(delta, uc, z, Bm, Cm, A_log, Dp, y2);

    // ---- G5: out = y @ W_out ------------------------------------------------
    gemm_tc<EPI_PLAIN><<<dim3(D_MODEL / GBN, ROWS / GBM), 512, GEMM_SMEM>>>(
        y2, Wout2, 3 * D_INNER, D_MODEL, out, nullptr, nullptr, nullptr);
}

// round 7
// speedup vs baseline: 1.0926x; 1.0926x over previous
#include <cuda_runtime.h>
#include <cuda_bf16.h>
#include <cuda_fp16.h>
#include <cstdint>
#include <math.h>

#define D_MODEL 1024
#define D_STATE 16
#define D_INNER 2048
#define DT_RANK 64
#define BATCH   4
#define SEQLEN  2048
#define ROWS    (BATCH * SEQLEN)   // 8192

// ---------------- device scratch (allocation-free rule) -----------------------
__device__ __align__(16) float g_u[ROWS * D_INNER];
__device__ __align__(16) float g_z[ROWS * D_INNER];
__device__ __align__(16) float g_uc[ROWS * D_INNER];
__device__ __align__(16) float g_delta[ROWS * D_INNER];
__device__ __align__(16) float g_dtr[ROWS * DT_RANK];
__device__ __align__(16) float g_Bm[ROWS * D_STATE];
__device__ __align__(16) float g_Cm[ROWS * D_STATE];

// bf16 3-term operands (A: [hi|hi|lo], Bt: [hi|lo|hi]) — exp-sensitive path
__device__ __align__(16) __nv_bfloat16 g_x2  [ROWS * 3 * D_MODEL];       // G1u A
__device__ __align__(16) __nv_bfloat16 g_Winu2[D_INNER * 3 * D_MODEL];   // G1u B (u half)
__device__ __align__(16) __nv_bfloat16 g_uc2 [ROWS * 3 * D_INNER];       // G2 A
__device__ __align__(16) __nv_bfloat16 g_Wxp2[128 * 3 * D_INNER];        // G2 B
__device__ __align__(16) __nv_bfloat16 g_dtr2[ROWS * 3 * DT_RANK];       // G3 A
__device__ __align__(16) __nv_bfloat16 g_Wdt2[D_INNER * 3 * DT_RANK];    // G3 B

// fp16 2-term operands (A: [hi|lo], Bt: [hi|hi]) — output-side path
__device__ __align__(16) __half g_x16  [ROWS * 2 * D_MODEL];             // G1z A
__device__ __align__(16) __half g_Winz16[D_INNER * 2 * D_MODEL];         // G1z B (z half)
__device__ __align__(16) __half g_y16  [ROWS * 2 * D_INNER];             // G5 A (from scan)
__device__ __align__(16) __half g_Wout16[D_MODEL * 2 * D_INNER];         // G5 B

// ---------------- helpers -----------------------------------------------------
__device__ __forceinline__ uint32_t smem_u32(const void* p) {
    uint32_t a;
    asm("{ .reg .u64 t; cvta.to.shared.u64 t, %1; cvt.u32.u64 %0, t; }" : "=r"(a) : "l"(p));
    return a;
}
__device__ __forceinline__ void cp16(uint32_t saddr, const void* gaddr) {
    asm volatile("cp.async.cg.shared.global [%0], [%1], 16;" :: "r"(saddr), "l"(gaddr));
}
#define SWZ(o) ((o) ^ ((((uint32_t)(o)) >> 3) & 0x70))

__device__ __forceinline__ void ldm_x4(uint32_t& r0, uint32_t& r1, uint32_t& r2, uint32_t& r3,
                                       uint32_t addr) {
    asm volatile("ldmatrix.sync.aligned.m8n8.x4.shared.b16 {%0,%1,%2,%3}, [%4];"
                 : "=r"(r0), "=r"(r1), "=r"(r2), "=r"(r3) : "r"(addr));
}
__device__ __forceinline__ void mma_bf16(float& c0, float& c1, float& c2, float& c3,
                                         uint32_t a0, uint32_t a1, uint32_t a2, uint32_t a3,
                                         uint32_t b0, uint32_t b1) {
    asm volatile("mma.sync.aligned.m16n8k16.row.col.f32.bf16.bf16.f32 "
                 "{%0,%1,%2,%3}, {%4,%5,%6,%7}, {%8,%9}, {%0,%1,%2,%3};"
                 : "+f"(c0), "+f"(c1), "+f"(c2), "+f"(c3)
                 : "r"(a0), "r"(a1), "r"(a2), "r"(a3), "r"(b0), "r"(b1));
}
__device__ __forceinline__ void mma_fp16(float& c0, float& c1, float& c2, float& c3,
                                         uint32_t a0, uint32_t a1, uint32_t a2, uint32_t a3,
                                         uint32_t b0, uint32_t b1) {
    asm volatile("mma.sync.aligned.m16n8k16.row.col.f32.f16.f16.f32 "
                 "{%0,%1,%2,%3}, {%4,%5,%6,%7}, {%8,%9}, {%0,%1,%2,%3};"
                 : "+f"(c0), "+f"(c1), "+f"(c2), "+f"(c3)
                 : "r"(a0), "r"(a1), "r"(a2), "r"(a3), "r"(b0), "r"(b1));
}
__device__ __forceinline__ void split_bf16(float v, __nv_bfloat16& h, __nv_bfloat16& l) {
    h = __float2bfloat16(v);
    l = __float2bfloat16(v - __bfloat162float(h));
}
__device__ __forceinline__ void split_fp16(float v, __half& h, __half& l) {
    h = __float2half(v);
    l = __float2half(v - __half2float(h));
}

// ---------------- mma.sync GEMM (bf16 or fp16, same layout) --------------------
// C[M,N] = A[M,Kp] * Bt[N,Kp]^T, K-major row-major bf16/fp16, fp32 accumulate.
// BM=BN=128, BK=64 (128B rows, xor-swizzled), 3-stage cp.async pipeline,
// 256 threads = 8 warps in 4(m) x 2(n), warp tile 32x64.
enum { EPI_PLAIN = 0, EPI_SOFTPLUS = 2, EPI_XPROJ = 3 };

#define GBM 128
#define GBN 128
#define GBK 64
#define GSTAGES 3
#define GTILE_B (GBM * GBK * 2)          // 16384 bytes per operand tile
#define GSTAGE_B (2 * GTILE_B)           // 32768
#define GEMM_SMEM (GSTAGES * GSTAGE_B)   // 98304

template <int EPI, int FP16>
__global__ __launch_bounds__(256, 2)
void gemm_tc(const uint8_t* __restrict__ A, const uint8_t* __restrict__ Bt,
             int Kp, int N,
             float* __restrict__ O0, float* __restrict__ O1, float* __restrict__ O2,
             const float* __restrict__ bias)
{
    extern __shared__ char smem[];
    const uint32_t sb = smem_u32(smem);
    const int tid = threadIdx.x;
    const int wid = tid >> 5, lid = tid & 31;
    const int wr = wid & 3;
    const int wc = wid >> 2;
    const int m0 = blockIdx.y * GBM;
    const int n0 = blockIdx.x * GBN;
    const int chunks = Kp / GBK;

    const uint8_t* Ap = A + (size_t)m0 * Kp * 2;
    const uint8_t* Bp = Bt + (size_t)n0 * Kp * 2;

    const int ldrow = tid >> 3;
    const int ldch  = tid & 7;

    auto load_stage = [&](int c) {
        const int s = c % GSTAGES;
        const uint32_t sa = sb + s * GSTAGE_B;
        const uint32_t sB = sa + GTILE_B;
        const size_t k0b = (size_t)c * GBK * 2;
        #pragma unroll
        for (int j = 0; j < 4; ++j) {
            const int r = ldrow + j * 32;
            const uint32_t so = SWZ(r * 128 + ldch * 16);
            cp16(sa + so, Ap + (size_t)r * Kp * 2 + k0b + ldch * 16);
            cp16(sB + so, Bp + (size_t)r * Kp * 2 + k0b + ldch * 16);
        }
        asm volatile("cp.async.commit_group;" ::: "memory");
    };

    const int pre = (chunks < GSTAGES - 1) ? chunks : (GSTAGES - 1);
    for (int c = 0; c < pre; ++c) load_stage(c);

    float acc[2][8][4];
    #pragma unroll
    for (int i = 0; i < 2; ++i)
        #pragma unroll
        for (int j = 0; j < 8; ++j)
            #pragma unroll
            for (int k = 0; k < 4; ++k) acc[i][j][k] = 0.f;

    const int lrow = lid & 15;
    const int lhalf = lid >> 4;

    for (int c = 0; c < chunks; ++c) {
        const int remaining = chunks - 1 - c;
        if (remaining >= 1) asm volatile("cp.async.wait_group 1;" ::: "memory");
        else                asm volatile("cp.async.wait_group 0;" ::: "memory");
        __syncthreads();

        if (c + GSTAGES - 1 < chunks) load_stage(c + GSTAGES - 1);

        const int s = c % GSTAGES;
        const uint32_t sa = sb + s * GSTAGE_B;
        const uint32_t sB = sa + GTILE_B;

        #pragma unroll
        for (int kk = 0; kk < 4; ++kk) {
            uint32_t a[2][4];
            #pragma unroll
            for (int wm = 0; wm < 2; ++wm) {
                const int row = wr * 32 + wm * 16 + lrow;
                const uint32_t off = SWZ(row * 128 + (kk * 2 + lhalf) * 16);
                ldm_x4(a[wm][0], a[wm][1], a[wm][2], a[wm][3], sa + off);
            }
            uint32_t b[4][4];
            #pragma unroll
            for (int g = 0; g < 4; ++g) {
                const int row = wc * 64 + g * 16 + lrow;
                const uint32_t off = SWZ(row * 128 + (kk * 2 + lhalf) * 16);
                ldm_x4(b[g][0], b[g][1], b[g][2], b[g][3], sB + off);
            }
            #pragma unroll
            for (int wm = 0; wm < 2; ++wm)
                #pragma unroll
                for (int j = 0; j < 8; ++j) {
                    const int g = j >> 1, h = j & 1;
                    if (FP16)
                        mma_fp16(acc[wm][j][0], acc[wm][j][1], acc[wm][j][2], acc[wm][j][3],
                                 a[wm][0], a[wm][1], a[wm][2], a[wm][3],
                                 b[g][h], b[g][2 + h]);
                    else
                        mma_bf16(acc[wm][j][0], acc[wm][j][1], acc[wm][j][2], acc[wm][j][3],
                                 a[wm][0], a[wm][1], a[wm][2], a[wm][3],
                                 b[g][h], b[g][2 + h]);
                }
        }
    }

    // ---------------- epilogue ------------------------------------------------
    const int tq = lid >> 2;
    const int tr = lid & 3;
    #pragma unroll
    for (int wm = 0; wm < 2; ++wm) {
        #pragma unroll
        for (int j = 0; j < 8; ++j) {
            #pragma unroll
            for (int half = 0; half < 2; ++half) {
                const int gr = m0 + wr * 32 + wm * 16 + tq + half * 8;
                const int gc = n0 + wc * 64 + j * 8 + tr * 2;
                float v0 = acc[wm][j][half * 2 + 0];
                float v1 = acc[wm][j][half * 2 + 1];
                if (EPI == EPI_PLAIN) {
                    float2 v = {v0, v1};
                    *(float2*)&O0[(size_t)gr * N + gc] = v;
                } else if (EPI == EPI_SOFTPLUS) {
                    v0 += bias[gc]; v1 += bias[gc + 1];
                    v0 = (v0 > 20.0f) ? v0 : log1pf(__expf(v0));
                    v1 = (v1 > 20.0f) ? v1 : log1pf(__expf(v1));
                    float2 v = {v0, v1};
                    *(float2*)&O0[(size_t)gr * N + gc] = v;
                } else { // EPI_XPROJ: 0..63 dtr | 64..79 Bm | 80..95 Cm | pad
                    float2 v = {v0, v1};
                    if (gc < DT_RANK)           *(float2*)&O0[(size_t)gr * DT_RANK + gc] = v;
                    else if (gc < DT_RANK + 16) *(float2*)&O1[(size_t)gr * 16 + (gc - DT_RANK)] = v;
                    else if (gc < DT_RANK + 32) *(float2*)&O2[(size_t)gr * 16 + (gc - DT_RANK - 16)] = v;
                }
            }
        }
    }
}

// ---------------- packing kernels ---------------------------------------------
// bf16 3-term A: fp32[M,K] -> bf16[M,3K] = [hi | hi | lo]  (flat 1D, float4/thread)
__global__ __launch_bounds__(256)
void packA_kernel(const float* __restrict__ in, __nv_bfloat16* __restrict__ out,
                  int K, int total4)
{
    const int idx = blockIdx.x * 256 + threadIdx.x;
    if (idx >= total4) return;
    const int kq = K >> 2;
    const int m = idx / kq;
    const int k = (idx - m * kq) * 4;
    const float4 v = *(const float4*)(in + (size_t)m * K + k);
    __nv_bfloat16 h0, h1, h2, h3, l0, l1, l2, l3;
    split_bf16(v.x, h0, l0); split_bf16(v.y, h1, l1);
    split_bf16(v.z, h2, l2); split_bf16(v.w, h3, l3);
    __nv_bfloat16* op = out + (size_t)m * 3 * K;
    __nv_bfloat162 hh01; hh01.x = h0; hh01.y = h1;
    __nv_bfloat162 hh23; hh23.x = h2; hh23.y = h3;
    __nv_bfloat162 ll01; ll01.x = l0; ll01.y = l1;
    __nv_bfloat162 ll23; ll23.x = l2; ll23.y = l3;
    *(__nv_bfloat162*)(op + k)             = hh01;
    *(__nv_bfloat162*)(op + k + 2)         = hh23;
    *(__nv_bfloat162*)(op + K + k)         = hh01;
    *(__nv_bfloat162*)(op + K + k + 2)     = hh23;
    *(__nv_bfloat162*)(op + 2 * K + k)     = ll01;
    *(__nv_bfloat162*)(op + 2 * K + k + 2) = ll23;
}

// fp16 2-term A: fp32[M,K] -> fp16[M,2K] = [hi | lo]
__global__ __launch_bounds__(256)
void packA16_kernel(const float* __restrict__ in, __half* __restrict__ out,
                    int K, int total4)
{
    const int idx = blockIdx.x * 256 + threadIdx.x;
    if (idx >= total4) return;
    const int kq = K >> 2;
    const int m = idx / kq;
    const int k = (idx - m * kq) * 4;
    const float4 v = *(const float4*)(in + (size_t)m * K + k);
    __half h0, h1, h2, h3, l0, l1, l2, l3;
    split_fp16(v.x, h0, l0); split_fp16(v.y, h1, l1);
    split_fp16(v.z, h2, l2); split_fp16(v.w, h3, l3);
    __half* op = out + (size_t)m * 2 * K;
    __half2 hh01; hh01.x = h0; hh01.y = h1;
    __half2 hh23; hh23.x = h2; hh23.y = h3;
    __half2 ll01; ll01.x = l0; ll01.y = l1;
    __half2 ll23; ll23.x = l2; ll23.y = l3;
    *(__half2*)(op + k)         = hh01;
    *(__half2*)(op + k + 2)     = hh23;
    *(__half2*)(op + K + k)     = ll01;
    *(__half2*)(op + K + k + 2) = ll23;
}

// bf16 3-term Bt: fp32[K, ldn] cols [ncol0, ncol0+Nv) -> bf16[Np, 3K] = [hi|lo|hi]
__global__ __launch_bounds__(256)
void packBt_kernel(const float* __restrict__ in, __nv_bfloat16* __restrict__ out,
                   int K, int Nv, int Np, int ldn, int ncol0)
{
    __shared__ float s[32][33];
    const int kb = blockIdx.x * 32, nb = blockIdx.y * 32;
    const int tx = threadIdx.x & 31, ty = threadIdx.x >> 5;
    #pragma unroll
    for (int r = 0; r < 32; r += 8) {
        const int k = kb + ty + r, n = nb + tx;
        s[ty + r][tx] = (k < K && n < Nv) ? in[(size_t)k * ldn + ncol0 + n] : 0.0f;
    }
    __syncthreads();
    #pragma unroll
    for (int r = 0; r < 32; r += 8) {
        const int n = nb + ty + r, k = kb + tx;
        if (n < Np && k < K) {
            const float v = s[tx][ty + r];
            __nv_bfloat16 h, lo;
            split_bf16(v, h, lo);
            __nv_bfloat16* op = out + (size_t)n * 3 * K;
            op[k] = h; op[K + k] = lo; op[2 * K + k] = h;
        }
    }
}

// fp16 dup Bt: fp32[K, ldn] cols [ncol0, ncol0+Nv) -> fp16[Np, 2K] = [hi|hi]
__global__ __launch_bounds__(256)
void packBt16_kernel(const float* __restrict__ in, __half* __restrict__ out,
                     int K, int Nv, int Np, int ldn, int ncol0)
{
    __shared__ float s[32][33];
    const int kb = blockIdx.x * 32, nb = blockIdx.y * 32;
    const int tx = threadIdx.x & 31, ty = threadIdx.x >> 5;
    #pragma unroll
    for (int r = 0; r < 32; r += 8) {
        const int k = kb + ty + r, n = nb + tx;
        s[ty + r][tx] = (k < K && n < Nv) ? in[(size_t)k * ldn + ncol0 + n] : 0.0f;
    }
    __syncthreads();
    #pragma unroll
    for (int r = 0; r < 32; r += 8) {
        const int n = nb + ty + r, k = kb + tx;
        if (n < Np && k < K) {
            const __half h = __float2half(s[tx][ty + r]);
            __half* op = out + (size_t)n * 2 * K;
            op[k] = h; op[K + k] = h;
        }
    }
}

// ---------------- causal depthwise conv (k=4) + SiLU + pack -------------------
__global__ __launch_bounds__(256)
void conv_silu_kernel(const float* __restrict__ u, const float* __restrict__ w,
                      const float* __restrict__ bias, float* __restrict__ uc,
                      __nv_bfloat16* __restrict__ uc2)
{
    constexpr int CHUNK = 16;
    int gid = blockIdx.x * blockDim.x + threadIdx.x;
    int d = gid & (D_INNER - 1);
    int rest = gid >> 11;
    int b = rest & (BATCH - 1);
    int chunk = rest >> 2;
    int l0 = chunk * CHUNK;

    const float w0 = w[d * 4 + 0], w1 = w[d * 4 + 1],
                w2 = w[d * 4 + 2], w3 = w[d * 4 + 3];
    const float bb = bias[d];

    const size_t base = ((size_t)b * SEQLEN + l0) * D_INNER + d;
    const float* up = u + base;
    float* op = uc + base;
    __nv_bfloat16* pp = uc2 + ((size_t)b * SEQLEN + l0) * 3 * D_INNER + d;

    float xm3, xm2, xm1;
    if (l0 == 0) { xm3 = 0.f; xm2 = 0.f; xm1 = 0.f; }
    else {
        xm3 = up[-3 * D_INNER];
        xm2 = up[-2 * D_INNER];
        xm1 = up[-1 * D_INNER];
    }
    #pragma unroll
    for (int i = 0; i < CHUNK; ++i) {
        float cur = up[(size_t)i * D_INNER];
        float v = fmaf(xm3, w0, fmaf(xm2, w1, fmaf(xm1, w2, fmaf(cur, w3, bb))));
        float s = v / (1.0f + __expf(-v));
        op[(size_t)i * D_INNER] = s;
        __nv_bfloat16 h, lo;
        split_bf16(s, h, lo);
        __nv_bfloat16* q = pp + (size_t)i * 3 * D_INNER;
        q[0] = h; q[D_INNER] = h; q[2 * D_INNER] = lo;
        xm3 = xm2; xm2 = xm1; xm1 = cur;
    }
}

// ---------------- selective scan (emits fp16 [hi|lo] y for G5) ----------------
__global__ __launch_bounds__(128)
void scan_kernel(const float* __restrict__ delta, const float* __restrict__ u,
                 const float* __restrict__ z, const float* __restrict__ Bm,
                 const float* __restrict__ Cm, const float* __restrict__ A_log,
                 const float* __restrict__ Dp, __half* __restrict__ y16)
{
    const int t = blockIdx.x * blockDim.x + threadIdx.x;
    const int sub = t & 3;
    const int ch = t >> 2;
    const int d = ch & (D_INNER - 1);
    const int b = ch >> 11;
    const int n0 = sub * 4;

    const float a0 = -__expf(A_log[d * D_STATE + n0 + 0]);
    const float a1 = -__expf(A_log[d * D_STATE + n0 + 1]);
    const float a2 = -__expf(A_log[d * D_STATE + n0 + 2]);
    const float a3 = -__expf(A_log[d * D_STATE + n0 + 3]);

    const bool fast =
        fabsf(a0 + (float)(n0 + 1)) < 1e-3f * (n0 + 1) &&
        fabsf(a1 + (float)(n0 + 2)) < 1e-3f * (n0 + 2) &&
        fabsf(a2 + (float)(n0 + 3)) < 1e-3f * (n0 + 3) &&
        fabsf(a3 + (float)(n0 + 4)) < 1e-3f * (n0 + 4);

    const size_t base = (size_t)b * SEQLEN * D_INNER + d;
    const float* dp = delta + base;
    const float* up = u + base;
    const float* zp = z + base;
    __half* yp = y16 + (size_t)b * SEQLEN * 2 * D_INNER + d;
    const float4* Bp = (const float4*)Bm + (size_t)b * SEQLEN * 4 + sub;
    const float4* Cp = (const float4*)Cm + (size_t)b * SEQLEN * 4 + sub;
    const float Dd = Dp[d];

    float h0 = 0.f, h1 = 0.f, h2 = 0.f, h3 = 0.f;

    if (fast) {
        #pragma unroll 2
        for (int l = 0; l < SEQLEN; ++l) {
            const float dt = dp[(size_t)l * D_INNER];
            const float uu = up[(size_t)l * D_INNER];
            const float4 Bv = Bp[(size_t)l * 4];
            const float4 Cv = Cp[(size_t)l * 4];
            const float e  = __expf(-dt);
            const float e2 = e * e;
            const float e4 = e2 * e2;
            const float e8 = e4 * e4;
            float m = 1.f;
            if (sub & 1) m = e4;
            if (sub & 2) m *= e8;
            const float dA0 = m * e;
            const float dA1 = dA0 * e;
            const float dA2 = dA1 * e;
            const float dA3 = dA2 * e;
            const float xv = dt * uu;
            h0 = fmaf(h0, dA0, xv * Bv.x);
            h1 = fmaf(h1, dA1, xv * Bv.y);
            h2 = fmaf(h2, dA2, xv * Bv.z);
            h3 = fmaf(h3, dA3, xv * Bv.w);
            float yv = h0 * Cv.x + h1 * Cv.y + h2 * Cv.z + h3 * Cv.w;
            yv += __shfl_xor_sync(0xffffffffu, yv, 1);
            yv += __shfl_xor_sync(0xffffffffu, yv, 2);
            if (sub == 0) {
                const float zz = zp[(size_t)l * D_INNER];
                const float sz = zz / (1.0f + __expf(-zz));
                const float yo = (yv + uu * Dd) * sz;
                __half h, lo;
                split_fp16(yo, h, lo);
                __half* q = yp + (size_t)l * 2 * D_INNER;
                q[0] = h; q[D_INNER] = lo;
            }
        }
    } else {
        #pragma unroll 2
        for (int l = 0; l < SEQLEN; ++l) {
            const float dt = dp[(size_t)l * D_INNER];
            const float uu = up[(size_t)l * D_INNER];
            const float4 Bv = Bp[(size_t)l * 4];
            const float4 Cv = Cp[(size_t)l * 4];
            const float dA0 = __expf(dt * a0);
            const float dA1 = __expf(dt * a1);
            const float dA2 = __expf(dt * a2);
            const float dA3 = __expf(dt * a3);
            const float xv = dt * uu;
            h0 = fmaf(h0, dA0, xv * Bv.x);
            h1 = fmaf(h1, dA1, xv * Bv.y);
            h2 = fmaf(h2, dA2, xv * Bv.z);
            h3 = fmaf(h3, dA3, xv * Bv.w);
            float yv = h0 * Cv.x + h1 * Cv.y + h2 * Cv.z + h3 * Cv.w;
            yv += __shfl_xor_sync(0xffffffffu, yv, 1);
            yv += __shfl_xor_sync(0xffffffffu, yv, 2);
            if (sub == 0) {
                const float zz = zp[(size_t)l * D_INNER];
                const float sz = zz / (1.0f + __expf(-zz));
                const float yo = (yv + uu * Dd) * sz;
                __half h, lo;
                split_fp16(yo, h, lo);
                __half* q = yp + (size_t)l * 2 * D_INNER;
                q[0] = h; q[D_INNER] = lo;
            }
        }
    }
}

// ---------------- launch ------------------------------------------------------
extern "C" void kernel_launch(void* const* d_in, const int* in_sizes, int n_in,
                              void* d_out, int out_size)
{
    const float* x      = (const float*)d_in[0];
    const float* W_in   = (const float*)d_in[1];
    const float* conv_w = (const float*)d_in[2];
    const float* conv_b = (const float*)d_in[3];
    const float* W_xprj = (const float*)d_in[4];
    const float* W_dt   = (const float*)d_in[5];
    const float* b_dt   = (const float*)d_in[6];
    const float* A_log  = (const float*)d_in[7];
    const float* Dp     = (const float*)d_in[8];
    const float* W_out  = (const float*)d_in[9];
    float* out = (float*)d_out;

    float *u, *z, *uc, *delta, *dtr, *Bm, *Cm;
    cudaGetSymbolAddress((void**)&u,     g_u);
    cudaGetSymbolAddress((void**)&z,     g_z);
    cudaGetSymbolAddress((void**)&uc,    g_uc);
    cudaGetSymbolAddress((void**)&delta, g_delta);
    cudaGetSymbolAddress((void**)&dtr,   g_dtr);
    cudaGetSymbolAddress((void**)&Bm,    g_Bm);
    cudaGetSymbolAddress((void**)&Cm,    g_Cm);

    __nv_bfloat16 *x2, *Winu2, *uc2, *Wxp2, *dtr2, *Wdt2;
    __half *x16, *Winz16, *y16, *Wout16;
    cudaGetSymbolAddress((void**)&x2,     g_x2);
    cudaGetSymbolAddress((void**)&Winu2,  g_Winu2);
    cudaGetSymbolAddress((void**)&uc2,    g_uc2);
    cudaGetSymbolAddress((void**)&Wxp2,   g_Wxp2);
    cudaGetSymbolAddress((void**)&dtr2,   g_dtr2);
    cudaGetSymbolAddress((void**)&Wdt2,   g_Wdt2);
    cudaGetSymbolAddress((void**)&x16,    g_x16);
    cudaGetSymbolAddress((void**)&Winz16, g_Winz16);
    cudaGetSymbolAddress((void**)&y16,    g_y16);
    cudaGetSymbolAddress((void**)&Wout16, g_Wout16);

    cudaFuncSetAttribute(gemm_tc<EPI_PLAIN, 0>,    cudaFuncAttributeMaxDynamicSharedMemorySize, GEMM_SMEM);
    cudaFuncSetAttribute(gemm_tc<EPI_PLAIN, 1>,    cudaFuncAttributeMaxDynamicSharedMemorySize, GEMM_SMEM);
    cudaFuncSetAttribute(gemm_tc<EPI_SOFTPLUS, 0>, cudaFuncAttributeMaxDynamicSharedMemorySize, GEMM_SMEM);
    cudaFuncSetAttribute(gemm_tc<EPI_XPROJ, 0>,    cudaFuncAttributeMaxDynamicSharedMemorySize, GEMM_SMEM);

    // weight packs up front (independent of activations)
    packBt_kernel<<<dim3(D_MODEL / 32, D_INNER / 32), 256>>>(
        W_in, Winu2, D_MODEL, D_INNER, D_INNER, 2 * D_INNER, 0);          // u half
    packBt16_kernel<<<dim3(D_MODEL / 32, D_INNER / 32), 256>>>(
        W_in, Winz16, D_MODEL, D_INNER, D_INNER, 2 * D_INNER, D_INNER);   // z half
    packBt_kernel<<<dim3(D_INNER / 32, 128 / 32), 256>>>(
        W_xprj, Wxp2, D_INNER, DT_RANK + 2 * D_STATE, 128, DT_RANK + 2 * D_STATE, 0);
    packBt_kernel<<<dim3((DT_RANK + 31) / 32, D_INNER / 32), 256>>>(
        W_dt, Wdt2, DT_RANK, D_INNER, D_INNER, D_INNER, 0);
    packBt16_kernel<<<dim3(D_INNER / 32, D_MODEL / 32), 256>>>(
        W_out, Wout16, D_INNER, D_MODEL, D_MODEL, D_MODEL, 0);

    // activation packs for G1
    {
        const int total4 = ROWS * (D_MODEL / 4);
        packA_kernel<<<(total4 + 255) / 256, 256>>>(x, x2, D_MODEL, total4);
        packA16_kernel<<<(total4 + 255) / 256, 256>>>(x, x16, D_MODEL, total4);
    }

    // ---- G1u: u = x @ W_in[:, :2048]  (bf16 3-term) ------------------------
    gemm_tc<EPI_PLAIN, 0><<<dim3(D_INNER / GBN, ROWS / GBM), 256, GEMM_SMEM>>>(
        (const uint8_t*)x2, (const uint8_t*)Winu2, 3 * D_MODEL, D_INNER,
        u, nullptr, nullptr, nullptr);
    // ---- G1z: z = x @ W_in[:, 2048:]  (fp16 2-term) ------------------------
    gemm_tc<EPI_PLAIN, 1><<<dim3(D_INNER / GBN, ROWS / GBM), 256, GEMM_SMEM>>>(
        (const uint8_t*)x16, (const uint8_t*)Winz16, 2 * D_MODEL, D_INNER,
        z, nullptr, nullptr, nullptr);

    // ---- conv + silu + pack uc2 --------------------------------------------
    conv_silu_kernel<<<(BATCH * D_INNER * (SEQLEN / 16)) / 256, 256>>>(
        u, conv_w, conv_b, uc, uc2);

    // ---- G2: proj = uc @ W_xproj -> dtr|Bm|Cm (bf16 3-term) ----------------
    gemm_tc<EPI_XPROJ, 0><<<dim3(1, ROWS / GBM), 256, GEMM_SMEM>>>(
        (const uint8_t*)uc2, (const uint8_t*)Wxp2, 3 * D_INNER, 128,
        dtr, Bm, Cm, nullptr);

    // ---- G3: delta = softplus(dtr @ W_dt + b_dt) (bf16 3-term) -------------
    {
        const int total4 = ROWS * (DT_RANK / 4);
        packA_kernel<<<(total4 + 255) / 256, 256>>>(dtr, dtr2, DT_RANK, total4);
    }
    gemm_tc<EPI_SOFTPLUS, 0><<<dim3(D_INNER / GBN, ROWS / GBM), 256, GEMM_SMEM>>>(
        (const uint8_t*)dtr2, (const uint8_t*)Wdt2, 3 * DT_RANK, D_INNER,
        delta, nullptr, nullptr, b_dt);

    // ---- scan + gating -> fp16 [hi|lo] y -----------------------------------
    scan_kernel<<<(ROWS * 4) / 128, 128>>>(delta, uc, z, Bm, Cm, A_log, Dp, y16);

    // ---- G5: out = y @ W_out (fp16 2-term) ---------------------------------
    gemm_tc<EPI_PLAIN, 1><<<dim3(D_MODEL / GBN, ROWS / GBM), 256, GEMM_SMEM>>>(
        (const uint8_t*)y16, (const uint8_t*)Wout16, 2 * D_INNER, D_MODEL,
        out, nullptr, nullptr, nullptr);
}

// round 8
// speedup vs baseline: 1.0934x; 1.0007x over previous
#include <cuda_runtime.h>
#include <cuda_bf16.h>
#include <cuda_fp16.h>
#include <cstdint>
#include <math.h>

#define D_MODEL 1024
#define D_STATE 16
#define D_INNER 2048
#define DT_RANK 64
#define BATCH   4
#define SEQLEN  2048
#define ROWS    (BATCH * SEQLEN)   // 8192

// ---------------- device scratch (allocation-free rule) -----------------------
__device__ __align__(16) float g_u[ROWS * D_INNER];
__device__ __align__(16) float g_z[ROWS * D_INNER];
__device__ __align__(16) float g_uc[ROWS * D_INNER];
__device__ __align__(16) float g_delta[ROWS * D_INNER];
__device__ __align__(16) float g_dtr[ROWS * DT_RANK];
__device__ __align__(16) float g_Bm[ROWS * D_STATE];
__device__ __align__(16) float g_Cm[ROWS * D_STATE];

// bf16 3-term operands (A: [hi|hi|lo], Bt: [hi|lo|hi]) — exp-sensitive path
__device__ __align__(16) __nv_bfloat16 g_x2  [ROWS * 3 * D_MODEL];       // G1u A
__device__ __align__(16) __nv_bfloat16 g_Winu2[D_INNER * 3 * D_MODEL];   // G1u B (u half)
__device__ __align__(16) __nv_bfloat16 g_uc2 [ROWS * 3 * D_INNER];       // G2 A
__device__ __align__(16) __nv_bfloat16 g_Wxp2[128 * 3 * D_INNER];        // G2 B
__device__ __align__(16) __nv_bfloat16 g_dtr2[ROWS * 3 * DT_RANK];       // G3 A
__device__ __align__(16) __nv_bfloat16 g_Wdt2[D_INNER * 3 * DT_RANK];    // G3 B

// fp16 2-term operands (A: [hi|lo], Bt: [hi|hi]) — output-side path
__device__ __align__(16) __half g_x16  [ROWS * 2 * D_MODEL];             // G1z A
__device__ __align__(16) __half g_Winz16[D_INNER * 2 * D_MODEL];         // G1z B (z half)
__device__ __align__(16) __half g_y16  [ROWS * 2 * D_INNER];             // G5 A (from scan)
__device__ __align__(16) __half g_Wout16[D_MODEL * 2 * D_INNER];         // G5 B

// ---------------- helpers -----------------------------------------------------
__device__ __forceinline__ uint32_t smem_u32(const void* p) {
    uint32_t a;
    asm("{ .reg .u64 t; cvta.to.shared.u64 t, %1; cvt.u32.u64 %0, t; }" : "=r"(a) : "l"(p));
    return a;
}
__device__ __forceinline__ void cp16(uint32_t saddr, const void* gaddr) {
    asm volatile("cp.async.cg.shared.global [%0], [%1], 16;" :: "r"(saddr), "l"(gaddr));
}
#define SWZ(o) ((o) ^ ((((uint32_t)(o)) >> 3) & 0x70))

__device__ __forceinline__ void ldm_x4(uint32_t& r0, uint32_t& r1, uint32_t& r2, uint32_t& r3,
                                       uint32_t addr) {
    asm volatile("ldmatrix.sync.aligned.m8n8.x4.shared.b16 {%0,%1,%2,%3}, [%4];"
                 : "=r"(r0), "=r"(r1), "=r"(r2), "=r"(r3) : "r"(addr));
}
__device__ __forceinline__ void mma_bf16(float& c0, float& c1, float& c2, float& c3,
                                         uint32_t a0, uint32_t a1, uint32_t a2, uint32_t a3,
                                         uint32_t b0, uint32_t b1) {
    asm volatile("mma.sync.aligned.m16n8k16.row.col.f32.bf16.bf16.f32 "
                 "{%0,%1,%2,%3}, {%4,%5,%6,%7}, {%8,%9}, {%0,%1,%2,%3};"
                 : "+f"(c0), "+f"(c1), "+f"(c2), "+f"(c3)
                 : "r"(a0), "r"(a1), "r"(a2), "r"(a3), "r"(b0), "r"(b1));
}
__device__ __forceinline__ void mma_fp16(float& c0, float& c1, float& c2, float& c3,
                                         uint32_t a0, uint32_t a1, uint32_t a2, uint32_t a3,
                                         uint32_t b0, uint32_t b1) {
    asm volatile("mma.sync.aligned.m16n8k16.row.col.f32.f16.f16.f32 "
                 "{%0,%1,%2,%3}, {%4,%5,%6,%7}, {%8,%9}, {%0,%1,%2,%3};"
                 : "+f"(c0), "+f"(c1), "+f"(c2), "+f"(c3)
                 : "r"(a0), "r"(a1), "r"(a2), "r"(a3), "r"(b0), "r"(b1));
}
__device__ __forceinline__ void split_bf16(float v, __nv_bfloat16& h, __nv_bfloat16& l) {
    h = __float2bfloat16(v);
    l = __float2bfloat16(v - __bfloat162float(h));
}
__device__ __forceinline__ void split_fp16(float v, __half& h, __half& l) {
    h = __float2half(v);
    l = __float2half(v - __half2float(h));
}

// ---------------- mma.sync GEMM (bf16 or fp16, same layout) --------------------
// C[M,N] = A[M,Kp] * Bt[N,Kp]^T, K-major row-major bf16/fp16, fp32 accumulate.
// BM=BN=128, BK=64 (128B rows, xor-swizzled), 3-stage cp.async pipeline,
// 256 threads = 8 warps in 4(m) x 2(n), warp tile 32x64.
enum { EPI_PLAIN = 0, EPI_SOFTPLUS = 2, EPI_XPROJ = 3 };

#define GBM 128
#define GBN 128
#define GBK 64
#define GSTAGES 3
#define GTILE_B (GBM * GBK * 2)          // 16384 bytes per operand tile
#define GSTAGE_B (2 * GTILE_B)           // 32768
#define GEMM_SMEM (GSTAGES * GSTAGE_B)   // 98304

template <int EPI, int FP16>
__global__ __launch_bounds__(256, 2)
void gemm_tc(const uint8_t* __restrict__ A, const uint8_t* __restrict__ Bt,
             int Kp, int N,
             float* __restrict__ O0, float* __restrict__ O1, float* __restrict__ O2,
             const float* __restrict__ bias)
{
    extern __shared__ char smem[];
    const uint32_t sb = smem_u32(smem);
    const int tid = threadIdx.x;
    const int wid = tid >> 5, lid = tid & 31;
    const int wr = wid & 3;
    const int wc = wid >> 2;
    const int m0 = blockIdx.y * GBM;
    const int n0 = blockIdx.x * GBN;
    const int chunks = Kp / GBK;

    const uint8_t* Ap = A + (size_t)m0 * Kp * 2;
    const uint8_t* Bp = Bt + (size_t)n0 * Kp * 2;

    const int ldrow = tid >> 3;
    const int ldch  = tid & 7;

    auto load_stage = [&](int c) {
        const int s = c % GSTAGES;
        const uint32_t sa = sb + s * GSTAGE_B;
        const uint32_t sB = sa + GTILE_B;
        const size_t k0b = (size_t)c * GBK * 2;
        #pragma unroll
        for (int j = 0; j < 4; ++j) {
            const int r = ldrow + j * 32;
            const uint32_t so = SWZ(r * 128 + ldch * 16);
            cp16(sa + so, Ap + (size_t)r * Kp * 2 + k0b + ldch * 16);
            cp16(sB + so, Bp + (size_t)r * Kp * 2 + k0b + ldch * 16);
        }
        asm volatile("cp.async.commit_group;" ::: "memory");
    };

    const int pre = (chunks < GSTAGES - 1) ? chunks : (GSTAGES - 1);
    for (int c = 0; c < pre; ++c) load_stage(c);

    float acc[2][8][4];
    #pragma unroll
    for (int i = 0; i < 2; ++i)
        #pragma unroll
        for (int j = 0; j < 8; ++j)
            #pragma unroll
            for (int k = 0; k < 4; ++k) acc[i][j][k] = 0.f;

    const int lrow = lid & 15;
    const int lhalf = lid >> 4;

    for (int c = 0; c < chunks; ++c) {
        const int remaining = chunks - 1 - c;
        if (remaining >= 1) asm volatile("cp.async.wait_group 1;" ::: "memory");
        else                asm volatile("cp.async.wait_group 0;" ::: "memory");
        __syncthreads();

        if (c + GSTAGES - 1 < chunks) load_stage(c + GSTAGES - 1);

        const int s = c % GSTAGES;
        const uint32_t sa = sb + s * GSTAGE_B;
        const uint32_t sB = sa + GTILE_B;

        #pragma unroll
        for (int kk = 0; kk < 4; ++kk) {
            uint32_t a[2][4];
            #pragma unroll
            for (int wm = 0; wm < 2; ++wm) {
                const int row = wr * 32 + wm * 16 + lrow;
                const uint32_t off = SWZ(row * 128 + (kk * 2 + lhalf) * 16);
                ldm_x4(a[wm][0], a[wm][1], a[wm][2], a[wm][3], sa + off);
            }
            uint32_t b[4][4];
            #pragma unroll
            for (int g = 0; g < 4; ++g) {
                const int row = wc * 64 + g * 16 + lrow;
                const uint32_t off = SWZ(row * 128 + (kk * 2 + lhalf) * 16);
                ldm_x4(b[g][0], b[g][1], b[g][2], b[g][3], sB + off);
            }
            #pragma unroll
            for (int wm = 0; wm < 2; ++wm)
                #pragma unroll
                for (int j = 0; j < 8; ++j) {
                    const int g = j >> 1, h = j & 1;
                    if (FP16)
                        mma_fp16(acc[wm][j][0], acc[wm][j][1], acc[wm][j][2], acc[wm][j][3],
                                 a[wm][0], a[wm][1], a[wm][2], a[wm][3],
                                 b[g][h], b[g][2 + h]);
                    else
                        mma_bf16(acc[wm][j][0], acc[wm][j][1], acc[wm][j][2], acc[wm][j][3],
                                 a[wm][0], a[wm][1], a[wm][2], a[wm][3],
                                 b[g][h], b[g][2 + h]);
                }
        }
    }

    // ---------------- epilogue ------------------------------------------------
    const int tq = lid >> 2;
    const int tr = lid & 3;
    #pragma unroll
    for (int wm = 0; wm < 2; ++wm) {
        #pragma unroll
        for (int j = 0; j < 8; ++j) {
            #pragma unroll
            for (int half = 0; half < 2; ++half) {
                const int gr = m0 + wr * 32 + wm * 16 + tq + half * 8;
                const int gc = n0 + wc * 64 + j * 8 + tr * 2;
                float v0 = acc[wm][j][half * 2 + 0];
                float v1 = acc[wm][j][half * 2 + 1];
                if (EPI == EPI_PLAIN) {
                    float2 v = {v0, v1};
                    *(float2*)&O0[(size_t)gr * N + gc] = v;
                } else if (EPI == EPI_SOFTPLUS) {
                    v0 += bias[gc]; v1 += bias[gc + 1];
                    v0 = (v0 > 20.0f) ? v0 : log1pf(__expf(v0));
                    v1 = (v1 > 20.0f) ? v1 : log1pf(__expf(v1));
                    float2 v = {v0, v1};
                    *(float2*)&O0[(size_t)gr * N + gc] = v;
                } else { // EPI_XPROJ: 0..63 dtr | 64..79 Bm | 80..95 Cm | pad
                    float2 v = {v0, v1};
                    if (gc < DT_RANK)           *(float2*)&O0[(size_t)gr * DT_RANK + gc] = v;
                    else if (gc < DT_RANK + 16) *(float2*)&O1[(size_t)gr * 16 + (gc - DT_RANK)] = v;
                    else if (gc < DT_RANK + 32) *(float2*)&O2[(size_t)gr * 16 + (gc - DT_RANK - 16)] = v;
                }
            }
        }
    }
}

// ---------------- packing kernels ---------------------------------------------
// bf16 3-term A: fp32[M,K] -> bf16[M,3K] = [hi | hi | lo]  (flat 1D, float4/thread)
__global__ __launch_bounds__(256)
void packA_kernel(const float* __restrict__ in, __nv_bfloat16* __restrict__ out,
                  int K, int total4)
{
    const int idx = blockIdx.x * 256 + threadIdx.x;
    if (idx >= total4) return;
    const int kq = K >> 2;
    const int m = idx / kq;
    const int k = (idx - m * kq) * 4;
    const float4 v = *(const float4*)(in + (size_t)m * K + k);
    __nv_bfloat16 h0, h1, h2, h3, l0, l1, l2, l3;
    split_bf16(v.x, h0, l0); split_bf16(v.y, h1, l1);
    split_bf16(v.z, h2, l2); split_bf16(v.w, h3, l3);
    __nv_bfloat16* op = out + (size_t)m * 3 * K;
    __nv_bfloat162 hh01; hh01.x = h0; hh01.y = h1;
    __nv_bfloat162 hh23; hh23.x = h2; hh23.y = h3;
    __nv_bfloat162 ll01; ll01.x = l0; ll01.y = l1;
    __nv_bfloat162 ll23; ll23.x = l2; ll23.y = l3;
    *(__nv_bfloat162*)(op + k)             = hh01;
    *(__nv_bfloat162*)(op + k + 2)         = hh23;
    *(__nv_bfloat162*)(op + K + k)         = hh01;
    *(__nv_bfloat162*)(op + K + k + 2)     = hh23;
    *(__nv_bfloat162*)(op + 2 * K + k)     = ll01;
    *(__nv_bfloat162*)(op + 2 * K + k + 2) = ll23;
}

// fp16 2-term A: fp32[M,K] -> fp16[M,2K] = [hi | lo]
__global__ __launch_bounds__(256)
void packA16_kernel(const float* __restrict__ in, __half* __restrict__ out,
                    int K, int total4)
{
    const int idx = blockIdx.x * 256 + threadIdx.x;
    if (idx >= total4) return;
    const int kq = K >> 2;
    const int m = idx / kq;
    const int k = (idx - m * kq) * 4;
    const float4 v = *(const float4*)(in + (size_t)m * K + k);
    __half h0, h1, h2, h3, l0, l1, l2, l3;
    split_fp16(v.x, h0, l0); split_fp16(v.y, h1, l1);
    split_fp16(v.z, h2, l2); split_fp16(v.w, h3, l3);
    __half* op = out + (size_t)m * 2 * K;
    __half2 hh01; hh01.x = h0; hh01.y = h1;
    __half2 hh23; hh23.x = h2; hh23.y = h3;
    __half2 ll01; ll01.x = l0; ll01.y = l1;
    __half2 ll23; ll23.x = l2; ll23.y = l3;
    *(__half2*)(op + k)         = hh01;
    *(__half2*)(op + k + 2)     = hh23;
    *(__half2*)(op + K + k)     = ll01;
    *(__half2*)(op + K + k + 2) = ll23;
}

// bf16 3-term Bt: fp32[K, ldn] cols [ncol0, ncol0+Nv) -> bf16[Np, 3K] = [hi|lo|hi]
__global__ __launch_bounds__(256)
void packBt_kernel(const float* __restrict__ in, __nv_bfloat16* __restrict__ out,
                   int K, int Nv, int Np, int ldn, int ncol0)
{
    __shared__ float s[32][33];
    const int kb = blockIdx.x * 32, nb = blockIdx.y * 32;
    const int tx = threadIdx.x & 31, ty = threadIdx.x >> 5;
    #pragma unroll
    for (int r = 0; r < 32; r += 8) {
        const int k = kb + ty + r, n = nb + tx;
        s[ty + r][tx] = (k < K && n < Nv) ? in[(size_t)k * ldn + ncol0 + n] : 0.0f;
    }
    __syncthreads();
    #pragma unroll
    for (int r = 0; r < 32; r += 8) {
        const int n = nb + ty + r, k = kb + tx;
        if (n < Np && k < K) {
            const float v = s[tx][ty + r];
            __nv_bfloat16 h, lo;
            split_bf16(v, h, lo);
            __nv_bfloat16* op = out + (size_t)n * 3 * K;
            op[k] = h; op[K + k] = lo; op[2 * K + k] = h;
        }
    }
}

// fp16 dup Bt: fp32[K, ldn] cols [ncol0, ncol0+Nv) -> fp16[Np, 2K] = [hi|hi]
__global__ __launch_bounds__(256)
void packBt16_kernel(const float* __restrict__ in, __half* __restrict__ out,
                     int K, int Nv, int Np, int ldn, int ncol0)
{
    __shared__ float s[32][33];
    const int kb = blockIdx.x * 32, nb = blockIdx.y * 32;
    const int tx = threadIdx.x & 31, ty = threadIdx.x >> 5;
    #pragma unroll
    for (int r = 0; r < 32; r += 8) {
        const int k = kb + ty + r, n = nb + tx;
        s[ty + r][tx] = (k < K && n < Nv) ? in[(size_t)k * ldn + ncol0 + n] : 0.0f;
    }
    __syncthreads();
    #pragma unroll
    for (int r = 0; r < 32; r += 8) {
        const int n = nb + ty + r, k = kb + tx;
        if (n < Np && k < K) {
            const __half h = __float2half(s[tx][ty + r]);
            __half* op = out + (size_t)n * 2 * K;
            op[k] = h; op[K + k] = h;
        }
    }
}

// ---------------- causal depthwise conv (k=4) + SiLU + pack -------------------
__global__ __launch_bounds__(256)
void conv_silu_kernel(const float* __restrict__ u, const float* __restrict__ w,
                      const float* __restrict__ bias, float* __restrict__ uc,
                      __nv_bfloat16* __restrict__ uc2)
{
    constexpr int CHUNK = 16;
    int gid = blockIdx.x * blockDim.x + threadIdx.x;
    int d = gid & (D_INNER - 1);
    int rest = gid >> 11;
    int b = rest & (BATCH - 1);
    int chunk = rest >> 2;
    int l0 = chunk * CHUNK;

    const float w0 = w[d * 4 + 0], w1 = w[d * 4 + 1],
                w2 = w[d * 4 + 2], w3 = w[d * 4 + 3];
    const float bb = bias[d];

    const size_t base = ((size_t)b * SEQLEN + l0) * D_INNER + d;
    const float* up = u + base;
    float* op = uc + base;
    __nv_bfloat16* pp = uc2 + ((size_t)b * SEQLEN + l0) * 3 * D_INNER + d;

    float xm3, xm2, xm1;
    if (l0 == 0) { xm3 = 0.f; xm2 = 0.f; xm1 = 0.f; }
    else {
        xm3 = up[-3 * D_INNER];
        xm2 = up[-2 * D_INNER];
        xm1 = up[-1 * D_INNER];
    }
    #pragma unroll
    for (int i = 0; i < CHUNK; ++i) {
        float cur = up[(size_t)i * D_INNER];
        float v = fmaf(xm3, w0, fmaf(xm2, w1, fmaf(xm1, w2, fmaf(cur, w3, bb))));
        float s = v / (1.0f + __expf(-v));
        op[(size_t)i * D_INNER] = s;
        __nv_bfloat16 h, lo;
        split_bf16(s, h, lo);
        __nv_bfloat16* q = pp + (size_t)i * 3 * D_INNER;
        q[0] = h; q[D_INNER] = h; q[2 * D_INNER] = lo;
        xm3 = xm2; xm2 = xm1; xm1 = cur;
    }
}

// ---------------- selective scan (emits fp16 [hi|lo] y for G5) ----------------
__global__ __launch_bounds__(128)
void scan_kernel(const float* __restrict__ delta, const float* __restrict__ u,
                 const float* __restrict__ z, const float* __restrict__ Bm,
                 const float* __restrict__ Cm, const float* __restrict__ A_log,
                 const float* __restrict__ Dp, __half* __restrict__ y16)
{
    const int t = blockIdx.x * blockDim.x + threadIdx.x;
    const int sub = t & 3;
    const int ch = t >> 2;
    const int d = ch & (D_INNER - 1);
    const int b = ch >> 11;
    const int n0 = sub * 4;

    const float a0 = -__expf(A_log[d * D_STATE + n0 + 0]);
    const float a1 = -__expf(A_log[d * D_STATE + n0 + 1]);
    const float a2 = -__expf(A_log[d * D_STATE + n0 + 2]);
    const float a3 = -__expf(A_log[d * D_STATE + n0 + 3]);

    const bool fast =
        fabsf(a0 + (float)(n0 + 1)) < 1e-3f * (n0 + 1) &&
        fabsf(a1 + (float)(n0 + 2)) < 1e-3f * (n0 + 2) &&
        fabsf(a2 + (float)(n0 + 3)) < 1e-3f * (n0 + 3) &&
        fabsf(a3 + (float)(n0 + 4)) < 1e-3f * (n0 + 4);

    const size_t base = (size_t)b * SEQLEN * D_INNER + d;
    const float* dp = delta + base;
    const float* up = u + base;
    const float* zp = z + base;
    __half* yp = y16 + (size_t)b * SEQLEN * 2 * D_INNER + d;
    const float4* Bp = (const float4*)Bm + (size_t)b * SEQLEN * 4 + sub;
    const float4* Cp = (const float4*)Cm + (size_t)b * SEQLEN * 4 + sub;
    const float Dd = Dp[d];

    float h0 = 0.f, h1 = 0.f, h2 = 0.f, h3 = 0.f;

    if (fast) {
        #pragma unroll 2
        for (int l = 0; l < SEQLEN; ++l) {
            const float dt = dp[(size_t)l * D_INNER];
            const float uu = up[(size_t)l * D_INNER];
            const float4 Bv = Bp[(size_t)l * 4];
            const float4 Cv = Cp[(size_t)l * 4];
            const float e  = __expf(-dt);
            const float e2 = e * e;
            const float e4 = e2 * e2;
            const float e8 = e4 * e4;
            float m = 1.f;
            if (sub & 1) m = e4;
            if (sub & 2) m *= e8;
            const float dA0 = m * e;
            const float dA1 = dA0 * e;
            const float dA2 = dA1 * e;
            const float dA3 = dA2 * e;
            const float xv = dt * uu;
            h0 = fmaf(h0, dA0, xv * Bv.x);
            h1 = fmaf(h1, dA1, xv * Bv.y);
            h2 = fmaf(h2, dA2, xv * Bv.z);
            h3 = fmaf(h3, dA3, xv * Bv.w);
            float yv = h0 * Cv.x + h1 * Cv.y + h2 * Cv.z + h3 * Cv.w;
            yv += __shfl_xor_sync(0xffffffffu, yv, 1);
            yv += __shfl_xor_sync(0xffffffffu, yv, 2);
            if (sub == 0) {
                const float zz = zp[(size_t)l * D_INNER];
                const float sz = zz / (1.0f + __expf(-zz));
                const float yo = (yv + uu * Dd) * sz;
                __half h, lo;
                split_fp16(yo, h, lo);
                __half* q = yp + (size_t)l * 2 * D_INNER;
                q[0] = h; q[D_INNER] = lo;
            }
        }
    } else {
        #pragma unroll 2
        for (int l = 0; l < SEQLEN; ++l) {
            const float dt = dp[(size_t)l * D_INNER];
            const float uu = up[(size_t)l * D_INNER];
            const float4 Bv = Bp[(size_t)l * 4];
            const float4 Cv = Cp[(size_t)l * 4];
            const float dA0 = __expf(dt * a0);
            const float dA1 = __expf(dt * a1);
            const float dA2 = __expf(dt * a2);
            const float dA3 = __expf(dt * a3);
            const float xv = dt * uu;
            h0 = fmaf(h0, dA0, xv * Bv.x);
            h1 = fmaf(h1, dA1, xv * Bv.y);
            h2 = fmaf(h2, dA2, xv * Bv.z);
            h3 = fmaf(h3, dA3, xv * Bv.w);
            float yv = h0 * Cv.x + h1 * Cv.y + h2 * Cv.z + h3 * Cv.w;
            yv += __shfl_xor_sync(0xffffffffu, yv, 1);
            yv += __shfl_xor_sync(0xffffffffu, yv, 2);
            if (sub == 0) {
                const float zz = zp[(size_t)l * D_INNER];
                const float sz = zz / (1.0f + __expf(-zz));
                const float yo = (yv + uu * Dd) * sz;
                __half h, lo;
                split_fp16(yo, h, lo);
                __half* q = yp + (size_t)l * 2 * D_INNER;
                q[0] = h; q[D_INNER] = lo;
            }
        }
    }
}

// ---------------- launch ------------------------------------------------------
extern "C" void kernel_launch(void* const* d_in, const int* in_sizes, int n_in,
                              void* d_out, int out_size)
{
    const float* x      = (const float*)d_in[0];
    const float* W_in   = (const float*)d_in[1];
    const float* conv_w = (const float*)d_in[2];
    const float* conv_b = (const float*)d_in[3];
    const float* W_xprj = (const float*)d_in[4];
    const float* W_dt   = (const float*)d_in[5];
    const float* b_dt   = (const float*)d_in[6];
    const float* A_log  = (const float*)d_in[7];
    const float* Dp     = (const float*)d_in[8];
    const float* W_out  = (const float*)d_in[9];
    float* out = (float*)d_out;

    float *u, *z, *uc, *delta, *dtr, *Bm, *Cm;
    cudaGetSymbolAddress((void**)&u,     g_u);
    cudaGetSymbolAddress((void**)&z,     g_z);
    cudaGetSymbolAddress((void**)&uc,    g_uc);
    cudaGetSymbolAddress((void**)&delta, g_delta);
    cudaGetSymbolAddress((void**)&dtr,   g_dtr);
    cudaGetSymbolAddress((void**)&Bm,    g_Bm);
    cudaGetSymbolAddress((void**)&Cm,    g_Cm);

    __nv_bfloat16 *x2, *Winu2, *uc2, *Wxp2, *dtr2, *Wdt2;
    __half *x16, *Winz16, *y16, *Wout16;
    cudaGetSymbolAddress((void**)&x2,     g_x2);
    cudaGetSymbolAddress((void**)&Winu2,  g_Winu2);
    cudaGetSymbolAddress((void**)&uc2,    g_uc2);
    cudaGetSymbolAddress((void**)&Wxp2,   g_Wxp2);
    cudaGetSymbolAddress((void**)&dtr2,   g_dtr2);
    cudaGetSymbolAddress((void**)&Wdt2,   g_Wdt2);
    cudaGetSymbolAddress((void**)&x16,    g_x16);
    cudaGetSymbolAddress((void**)&Winz16, g_Winz16);
    cudaGetSymbolAddress((void**)&y16,    g_y16);
    cudaGetSymbolAddress((void**)&Wout16, g_Wout16);

    cudaFuncSetAttribute(gemm_tc<EPI_PLAIN, 0>,    cudaFuncAttributeMaxDynamicSharedMemorySize, GEMM_SMEM);
    cudaFuncSetAttribute(gemm_tc<EPI_PLAIN, 1>,    cudaFuncAttributeMaxDynamicSharedMemorySize, GEMM_SMEM);
    cudaFuncSetAttribute(gemm_tc<EPI_SOFTPLUS, 0>, cudaFuncAttributeMaxDynamicSharedMemorySize, GEMM_SMEM);
    cudaFuncSetAttribute(gemm_tc<EPI_XPROJ, 0>,    cudaFuncAttributeMaxDynamicSharedMemorySize, GEMM_SMEM);

    // weight packs up front (independent of activations)
    packBt_kernel<<<dim3(D_MODEL / 32, D_INNER / 32), 256>>>(
        W_in, Winu2, D_MODEL, D_INNER, D_INNER, 2 * D_INNER, 0);          // u half
    packBt16_kernel<<<dim3(D_MODEL / 32, D_INNER / 32), 256>>>(
        W_in, Winz16, D_MODEL, D_INNER, D_INNER, 2 * D_INNER, D_INNER);   // z half
    packBt_kernel<<<dim3(D_INNER / 32, 128 / 32), 256>>>(
        W_xprj, Wxp2, D_INNER, DT_RANK + 2 * D_STATE, 128, DT_RANK + 2 * D_STATE, 0);
    packBt_kernel<<<dim3((DT_RANK + 31) / 32, D_INNER / 32), 256>>>(
        W_dt, Wdt2, DT_RANK, D_INNER, D_INNER, D_INNER, 0);
    packBt16_kernel<<<dim3(D_INNER / 32, D_MODEL / 32), 256>>>(
        W_out, Wout16, D_INNER, D_MODEL, D_MODEL, D_MODEL, 0);

    // activation packs for G1
    {
        const int total4 = ROWS * (D_MODEL / 4);
        packA_kernel<<<(total4 + 255) / 256, 256>>>(x, x2, D_MODEL, total4);
        packA16_kernel<<<(total4 + 255) / 256, 256>>>(x, x16, D_MODEL, total4);
    }

    // ---- G1u: u = x @ W_in[:, :2048]  (bf16 3-term) ------------------------
    gemm_tc<EPI_PLAIN, 0><<<dim3(D_INNER / GBN, ROWS / GBM), 256, GEMM_SMEM>>>(
        (const uint8_t*)x2, (const uint8_t*)Winu2, 3 * D_MODEL, D_INNER,
        u, nullptr, nullptr, nullptr);
    // ---- G1z: z = x @ W_in[:, 2048:]  (fp16 2-term) ------------------------
    gemm_tc<EPI_PLAIN, 1><<<dim3(D_INNER / GBN, ROWS / GBM), 256, GEMM_SMEM>>>(
        (const uint8_t*)x16, (const uint8_t*)Winz16, 2 * D_MODEL, D_INNER,
        z, nullptr, nullptr, nullptr);

    // ---- conv + silu + pack uc2 --------------------------------------------
    conv_silu_kernel<<<(BATCH * D_INNER * (SEQLEN / 16)) / 256, 256>>>(
        u, conv_w, conv_b, uc, uc2);

    // ---- G2: proj = uc @ W_xproj -> dtr|Bm|Cm (bf16 3-term) ----------------
    gemm_tc<EPI_XPROJ, 0><<<dim3(1, ROWS / GBM), 256, GEMM_SMEM>>>(
        (const uint8_t*)uc2, (const uint8_t*)Wxp2, 3 * D_INNER, 128,
        dtr, Bm, Cm, nullptr);

    // ---- G3: delta = softplus(dtr @ W_dt + b_dt) (bf16 3-term) -------------
    {
        const int total4 = ROWS * (DT_RANK / 4);
        packA_kernel<<<(total4 + 255) / 256, 256>>>(dtr, dtr2, DT_RANK, total4);
    }
    gemm_tc<EPI_SOFTPLUS, 0><<<dim3(D_INNER / GBN, ROWS / GBM), 256, GEMM_SMEM>>>(
        (const uint8_t*)dtr2, (const uint8_t*)Wdt2, 3 * DT_RANK, D_INNER,
        delta, nullptr, nullptr, b_dt);

    // ---- scan + gating -> fp16 [hi|lo] y -----------------------------------
    scan_kernel<<<(ROWS * 4) / 128, 128>>>(delta, uc, z, Bm, Cm, A_log, Dp, y16);

    // ---- G5: out = y @ W_out (fp16 2-term) ---------------------------------
    gemm_tc<EPI_PLAIN, 1><<<dim3(D_MODEL / GBN, ROWS / GBM), 256, GEMM_SMEM>>>(
        (const uint8_t*)y16, (const uint8_t*)Wout16, 2 * D_INNER, D_MODEL,
        out, nullptr, nullptr, nullptr);
}

// round 9
// speedup vs baseline: 1.0944x; 1.0010x over previous
#include <cuda_runtime.h>
#include <cuda_bf16.h>
#include <cuda_fp16.h>
#include <cstdint>
#include <math.h>

#define D_MODEL 1024
#define D_STATE 16
#define D_INNER 2048
#define DT_RANK 64
#define BATCH   4
#define SEQLEN  2048
#define ROWS    (BATCH * SEQLEN)   // 8192

// ---------------- device scratch (allocation-free rule) -----------------------
__device__ __align__(16) float g_u[ROWS * D_INNER];
__device__ __align__(16) float g_z[ROWS * D_INNER];
__device__ __align__(16) float g_uc[ROWS * D_INNER];
__device__ __align__(16) float g_delta[ROWS * D_INNER];
__device__ __align__(16) float g_dtr[ROWS * DT_RANK];
__device__ __align__(16) float g_Bm[ROWS * D_STATE];
__device__ __align__(16) float g_Cm[ROWS * D_STATE];

// bf16 3-term operands (A: [hi|hi|lo], Bt: [hi|lo|hi]) — exp-sensitive path
__device__ __align__(16) __nv_bfloat16 g_x2  [ROWS * 3 * D_MODEL];       // G1u A
__device__ __align__(16) __nv_bfloat16 g_Winu2[D_INNER * 3 * D_MODEL];   // G1u B (u half)
__device__ __align__(16) __nv_bfloat16 g_uc2 [ROWS * 3 * D_INNER];       // G2 A
__device__ __align__(16) __nv_bfloat16 g_Wxp2[128 * 3 * D_INNER];        // G2 B
__device__ __align__(16) __nv_bfloat16 g_dtr2[ROWS * 3 * DT_RANK];       // G3 A
__device__ __align__(16) __nv_bfloat16 g_Wdt2[D_INNER * 3 * DT_RANK];    // G3 B

// fp16 2-term operands (A: [hi|lo], Bt: [hi|hi]) — output-side path
__device__ __align__(16) __half g_x16  [ROWS * 2 * D_MODEL];             // G1z A
__device__ __align__(16) __half g_Winz16[D_INNER * 2 * D_MODEL];         // G1z B (z half)
__device__ __align__(16) __half g_y16  [ROWS * 2 * D_INNER];             // G5 A (from scan)
__device__ __align__(16) __half g_Wout16[D_MODEL * 2 * D_INNER];         // G5 B

// ---------------- helpers -----------------------------------------------------
__device__ __forceinline__ uint32_t smem_u32(const void* p) {
    uint32_t a;
    asm("{ .reg .u64 t; cvta.to.shared.u64 t, %1; cvt.u32.u64 %0, t; }" : "=r"(a) : "l"(p));
    return a;
}
__device__ __forceinline__ void cp16(uint32_t saddr, const void* gaddr) {
    asm volatile("cp.async.cg.shared.global [%0], [%1], 16;" :: "r"(saddr), "l"(gaddr));
}
#define SWZ(o) ((o) ^ ((((uint32_t)(o)) >> 3) & 0x70))

__device__ __forceinline__ void ldm_x4(uint32_t& r0, uint32_t& r1, uint32_t& r2, uint32_t& r3,
                                       uint32_t addr) {
    asm volatile("ldmatrix.sync.aligned.m8n8.x4.shared.b16 {%0,%1,%2,%3}, [%4];"
                 : "=r"(r0), "=r"(r1), "=r"(r2), "=r"(r3) : "r"(addr));
}
__device__ __forceinline__ void mma_bf16(float& c0, float& c1, float& c2, float& c3,
                                         uint32_t a0, uint32_t a1, uint32_t a2, uint32_t a3,
                                         uint32_t b0, uint32_t b1) {
    asm volatile("mma.sync.aligned.m16n8k16.row.col.f32.bf16.bf16.f32 "
                 "{%0,%1,%2,%3}, {%4,%5,%6,%7}, {%8,%9}, {%0,%1,%2,%3};"
                 : "+f"(c0), "+f"(c1), "+f"(c2), "+f"(c3)
                 : "r"(a0), "r"(a1), "r"(a2), "r"(a3), "r"(b0), "r"(b1));
}
__device__ __forceinline__ void mma_fp16(float& c0, float& c1, float& c2, float& c3,
                                         uint32_t a0, uint32_t a1, uint32_t a2, uint32_t a3,
                                         uint32_t b0, uint32_t b1) {
    asm volatile("mma.sync.aligned.m16n8k16.row.col.f32.f16.f16.f32 "
                 "{%0,%1,%2,%3}, {%4,%5,%6,%7}, {%8,%9}, {%0,%1,%2,%3};"
                 : "+f"(c0), "+f"(c1), "+f"(c2), "+f"(c3)
                 : "r"(a0), "r"(a1), "r"(a2), "r"(a3), "r"(b0), "r"(b1));
}
__device__ __forceinline__ void split_bf16(float v, __nv_bfloat16& h, __nv_bfloat16& l) {
    h = __float2bfloat16(v);
    l = __float2bfloat16(v - __bfloat162float(h));
}
__device__ __forceinline__ void split_fp16(float v, __half& h, __half& l) {
    h = __float2half(v);
    l = __float2half(v - __half2float(h));
}

// ---------------- mma.sync GEMM (bf16 or fp16, same layout) --------------------
// C[M,N] = A[M,Kp] * Bt[N,Kp]^T, K-major row-major bf16/fp16, fp32 accumulate.
// BM=BN=128, BK=64 (128B rows, xor-swizzled), 3-stage cp.async pipeline,
// 256 threads = 8 warps in 4(m) x 2(n), warp tile 32x64.
enum { EPI_PLAIN = 0, EPI_SOFTPLUS = 2, EPI_XPROJ = 3 };

#define GBM 128
#define GBN 128
#define GBK 64
#define GSTAGES 3
#define GTILE_B (GBM * GBK * 2)          // 16384 bytes per operand tile
#define GSTAGE_B (2 * GTILE_B)           // 32768
#define GEMM_SMEM (GSTAGES * GSTAGE_B)   // 98304

template <int EPI, int FP16>
__global__ __launch_bounds__(256, 2)
void gemm_tc(const uint8_t* __restrict__ A, const uint8_t* __restrict__ Bt,
             int Kp, int N,
             float* __restrict__ O0, float* __restrict__ O1, float* __restrict__ O2,
             const float* __restrict__ bias)
{
    extern __shared__ char smem[];
    const uint32_t sb = smem_u32(smem);
    const int tid = threadIdx.x;
    const int wid = tid >> 5, lid = tid & 31;
    const int wr = wid & 3;
    const int wc = wid >> 2;
    const int m0 = blockIdx.y * GBM;
    const int n0 = blockIdx.x * GBN;
    const int chunks = Kp / GBK;

    const uint8_t* Ap = A + (size_t)m0 * Kp * 2;
    const uint8_t* Bp = Bt + (size_t)n0 * Kp * 2;

    const int ldrow = tid >> 3;
    const int ldch  = tid & 7;

    auto load_stage = [&](int c) {
        const int s = c % GSTAGES;
        const uint32_t sa = sb + s * GSTAGE_B;
        const uint32_t sB = sa + GTILE_B;
        const size_t k0b = (size_t)c * GBK * 2;
        #pragma unroll
        for (int j = 0; j < 4; ++j) {
            const int r = ldrow + j * 32;
            const uint32_t so = SWZ(r * 128 + ldch * 16);
            cp16(sa + so, Ap + (size_t)r * Kp * 2 + k0b + ldch * 16);
            cp16(sB + so, Bp + (size_t)r * Kp * 2 + k0b + ldch * 16);
        }
        asm volatile("cp.async.commit_group;" ::: "memory");
    };

    const int pre = (chunks < GSTAGES - 1) ? chunks : (GSTAGES - 1);
    for (int c = 0; c < pre; ++c) load_stage(c);

    float acc[2][8][4];
    #pragma unroll
    for (int i = 0; i < 2; ++i)
        #pragma unroll
        for (int j = 0; j < 8; ++j)
            #pragma unroll
            for (int k = 0; k < 4; ++k) acc[i][j][k] = 0.f;

    const int lrow = lid & 15;
    const int lhalf = lid >> 4;

    for (int c = 0; c < chunks; ++c) {
        const int remaining = chunks - 1 - c;
        if (remaining >= 1) asm volatile("cp.async.wait_group 1;" ::: "memory");
        else                asm volatile("cp.async.wait_group 0;" ::: "memory");
        __syncthreads();

        if (c + GSTAGES - 1 < chunks) load_stage(c + GSTAGES - 1);

        const int s = c % GSTAGES;
        const uint32_t sa = sb + s * GSTAGE_B;
        const uint32_t sB = sa + GTILE_B;

        #pragma unroll
        for (int kk = 0; kk < 4; ++kk) {
            uint32_t a[2][4];
            #pragma unroll
            for (int wm = 0; wm < 2; ++wm) {
                const int row = wr * 32 + wm * 16 + lrow;
                const uint32_t off = SWZ(row * 128 + (kk * 2 + lhalf) * 16);
                ldm_x4(a[wm][0], a[wm][1], a[wm][2], a[wm][3], sa + off);
            }
            uint32_t b[4][4];
            #pragma unroll
            for (int g = 0; g < 4; ++g) {
                const int row = wc * 64 + g * 16 + lrow;
                const uint32_t off = SWZ(row * 128 + (kk * 2 + lhalf) * 16);
                ldm_x4(b[g][0], b[g][1], b[g][2], b[g][3], sB + off);
            }
            #pragma unroll
            for (int wm = 0; wm < 2; ++wm)
                #pragma unroll
                for (int j = 0; j < 8; ++j) {
                    const int g = j >> 1, h = j & 1;
                    if (FP16)
                        mma_fp16(acc[wm][j][0], acc[wm][j][1], acc[wm][j][2], acc[wm][j][3],
                                 a[wm][0], a[wm][1], a[wm][2], a[wm][3],
                                 b[g][h], b[g][2 + h]);
                    else
                        mma_bf16(acc[wm][j][0], acc[wm][j][1], acc[wm][j][2], acc[wm][j][3],
                                 a[wm][0], a[wm][1], a[wm][2], a[wm][3],
                                 b[g][h], b[g][2 + h]);
                }
        }
    }

    // ---------------- epilogue ------------------------------------------------
    const int tq = lid >> 2;
    const int tr = lid & 3;
    #pragma unroll
    for (int wm = 0; wm < 2; ++wm) {
        #pragma unroll
        for (int j = 0; j < 8; ++j) {
            #pragma unroll
            for (int half = 0; half < 2; ++half) {
                const int gr = m0 + wr * 32 + wm * 16 + tq + half * 8;
                const int gc = n0 + wc * 64 + j * 8 + tr * 2;
                float v0 = acc[wm][j][half * 2 + 0];
                float v1 = acc[wm][j][half * 2 + 1];
                if (EPI == EPI_PLAIN) {
                    float2 v = {v0, v1};
                    *(float2*)&O0[(size_t)gr * N + gc] = v;
                } else if (EPI == EPI_SOFTPLUS) {
                    v0 += bias[gc]; v1 += bias[gc + 1];
                    v0 = (v0 > 20.0f) ? v0 : log1pf(__expf(v0));
                    v1 = (v1 > 20.0f) ? v1 : log1pf(__expf(v1));
                    float2 v = {v0, v1};
                    *(float2*)&O0[(size_t)gr * N + gc] = v;
                } else { // EPI_XPROJ: 0..63 dtr | 64..79 Bm | 80..95 Cm | pad
                    float2 v = {v0, v1};
                    if (gc < DT_RANK)           *(float2*)&O0[(size_t)gr * DT_RANK + gc] = v;
                    else if (gc < DT_RANK + 16) *(float2*)&O1[(size_t)gr * 16 + (gc - DT_RANK)] = v;
                    else if (gc < DT_RANK + 32) *(float2*)&O2[(size_t)gr * 16 + (gc - DT_RANK - 16)] = v;
                }
            }
        }
    }
}

// ---------------- packing kernels ---------------------------------------------
// bf16 3-term A: fp32[M,K] -> bf16[M,3K] = [hi | hi | lo]  (flat 1D, float4/thread)
__global__ __launch_bounds__(256)
void packA_kernel(const float* __restrict__ in, __nv_bfloat16* __restrict__ out,
                  int K, int total4)
{
    const int idx = blockIdx.x * 256 + threadIdx.x;
    if (idx >= total4) return;
    const int kq = K >> 2;
    const int m = idx / kq;
    const int k = (idx - m * kq) * 4;
    const float4 v = *(const float4*)(in + (size_t)m * K + k);
    __nv_bfloat16 h0, h1, h2, h3, l0, l1, l2, l3;
    split_bf16(v.x, h0, l0); split_bf16(v.y, h1, l1);
    split_bf16(v.z, h2, l2); split_bf16(v.w, h3, l3);
    __nv_bfloat16* op = out + (size_t)m * 3 * K;
    __nv_bfloat162 hh01; hh01.x = h0; hh01.y = h1;
    __nv_bfloat162 hh23; hh23.x = h2; hh23.y = h3;
    __nv_bfloat162 ll01; ll01.x = l0; ll01.y = l1;
    __nv_bfloat162 ll23; ll23.x = l2; ll23.y = l3;
    *(__nv_bfloat162*)(op + k)             = hh01;
    *(__nv_bfloat162*)(op + k + 2)         = hh23;
    *(__nv_bfloat162*)(op + K + k)         = hh01;
    *(__nv_bfloat162*)(op + K + k + 2)     = hh23;
    *(__nv_bfloat162*)(op + 2 * K + k)     = ll01;
    *(__nv_bfloat162*)(op + 2 * K + k + 2) = ll23;
}

// fp16 2-term A: fp32[M,K] -> fp16[M,2K] = [hi | lo]
__global__ __launch_bounds__(256)
void packA16_kernel(const float* __restrict__ in, __half* __restrict__ out,
                    int K, int total4)
{
    const int idx = blockIdx.x * 256 + threadIdx.x;
    if (idx >= total4) return;
    const int kq = K >> 2;
    const int m = idx / kq;
    const int k = (idx - m * kq) * 4;
    const float4 v = *(const float4*)(in + (size_t)m * K + k);
    __half h0, h1, h2, h3, l0, l1, l2, l3;
    split_fp16(v.x, h0, l0); split_fp16(v.y, h1, l1);
    split_fp16(v.z, h2, l2); split_fp16(v.w, h3, l3);
    __half* op = out + (size_t)m * 2 * K;
    __half2 hh01; hh01.x = h0; hh01.y = h1;
    __half2 hh23; hh23.x = h2; hh23.y = h3;
    __half2 ll01; ll01.x = l0; ll01.y = l1;
    __half2 ll23; ll23.x = l2; ll23.y = l3;
    *(__half2*)(op + k)         = hh01;
    *(__half2*)(op + k + 2)     = hh23;
    *(__half2*)(op + K + k)     = ll01;
    *(__half2*)(op + K + k + 2) = ll23;
}

// bf16 3-term Bt: fp32[K, ldn] cols [ncol0, ncol0+Nv) -> bf16[Np, 3K] = [hi|lo|hi]
__global__ __launch_bounds__(256)
void packBt_kernel(const float* __restrict__ in, __nv_bfloat16* __restrict__ out,
                   int K, int Nv, int Np, int ldn, int ncol0)
{
    __shared__ float s[32][33];
    const int kb = blockIdx.x * 32, nb = blockIdx.y * 32;
    const int tx = threadIdx.x & 31, ty = threadIdx.x >> 5;
    #pragma unroll
    for (int r = 0; r < 32; r += 8) {
        const int k = kb + ty + r, n = nb + tx;
        s[ty + r][tx] = (k < K && n < Nv) ? in[(size_t)k * ldn + ncol0 + n] : 0.0f;
    }
    __syncthreads();
    #pragma unroll
    for (int r = 0; r < 32; r += 8) {
        const int n = nb + ty + r, k = kb + tx;
        if (n < Np && k < K) {
            const float v = s[tx][ty + r];
            __nv_bfloat16 h, lo;
            split_bf16(v, h, lo);
            __nv_bfloat16* op = out + (size_t)n * 3 * K;
            op[k] = h; op[K + k] = lo; op[2 * K + k] = h;
        }
    }
}

// fp16 dup Bt: fp32[K, ldn] cols [ncol0, ncol0+Nv) -> fp16[Np, 2K] = [hi|hi]
__global__ __launch_bounds__(256)
void packBt16_kernel(const float* __restrict__ in, __half* __restrict__ out,
                     int K, int Nv, int Np, int ldn, int ncol0)
{
    __shared__ float s[32][33];
    const int kb = blockIdx.x * 32, nb = blockIdx.y * 32;
    const int tx = threadIdx.x & 31, ty = threadIdx.x >> 5;
    #pragma unroll
    for (int r = 0; r < 32; r += 8) {
        const int k = kb + ty + r, n = nb + tx;
        s[ty + r][tx] = (k < K && n < Nv) ? in[(size_t)k * ldn + ncol0 + n] : 0.0f;
    }
    __syncthreads();
    #pragma unroll
    for (int r = 0; r < 32; r += 8) {
        const int n = nb + ty + r, k = kb + tx;
        if (n < Np && k < K) {
            const __half h = __float2half(s[tx][ty + r]);
            __half* op = out + (size_t)n * 2 * K;
            op[k] = h; op[K + k] = h;
        }
    }
}

// ---------------- causal depthwise conv (k=4) + SiLU + pack -------------------
__global__ __launch_bounds__(256)
void conv_silu_kernel(const float* __restrict__ u, const float* __restrict__ w,
                      const float* __restrict__ bias, float* __restrict__ uc,
                      __nv_bfloat16* __restrict__ uc2)
{
    constexpr int CHUNK = 16;
    int gid = blockIdx.x * blockDim.x + threadIdx.x;
    int d = gid & (D_INNER - 1);
    int rest = gid >> 11;
    int b = rest & (BATCH - 1);
    int chunk = rest >> 2;
    int l0 = chunk * CHUNK;

    const float w0 = w[d * 4 + 0], w1 = w[d * 4 + 1],
                w2 = w[d * 4 + 2], w3 = w[d * 4 + 3];
    const float bb = bias[d];

    const size_t base = ((size_t)b * SEQLEN + l0) * D_INNER + d;
    const float* up = u + base;
    float* op = uc + base;
    __nv_bfloat16* pp = uc2 + ((size_t)b * SEQLEN + l0) * 3 * D_INNER + d;

    float xm3, xm2, xm1;
    if (l0 == 0) { xm3 = 0.f; xm2 = 0.f; xm1 = 0.f; }
    else {
        xm3 = up[-3 * D_INNER];
        xm2 = up[-2 * D_INNER];
        xm1 = up[-1 * D_INNER];
    }
    #pragma unroll
    for (int i = 0; i < CHUNK; ++i) {
        float cur = up[(size_t)i * D_INNER];
        float v = fmaf(xm3, w0, fmaf(xm2, w1, fmaf(xm1, w2, fmaf(cur, w3, bb))));
        float s = v / (1.0f + __expf(-v));
        op[(size_t)i * D_INNER] = s;
        __nv_bfloat16 h, lo;
        split_bf16(s, h, lo);
        __nv_bfloat16* q = pp + (size_t)i * 3 * D_INNER;
        q[0] = h; q[D_INNER] = h; q[2 * D_INNER] = lo;
        xm3 = xm2; xm2 = xm1; xm1 = cur;
    }
}

// ---------------- selective scan (emits fp16 [hi|lo] y for G5) ----------------
__global__ __launch_bounds__(128)
void scan_kernel(const float* __restrict__ delta, const float* __restrict__ u,
                 const float* __restrict__ z, const float* __restrict__ Bm,
                 const float* __restrict__ Cm, const float* __restrict__ A_log,
                 const float* __restrict__ Dp, __half* __restrict__ y16)
{
    const int t = blockIdx.x * blockDim.x + threadIdx.x;
    const int sub = t & 3;
    const int ch = t >> 2;
    const int d = ch & (D_INNER - 1);
    const int b = ch >> 11;
    const int n0 = sub * 4;

    const float a0 = -__expf(A_log[d * D_STATE + n0 + 0]);
    const float a1 = -__expf(A_log[d * D_STATE + n0 + 1]);
    const float a2 = -__expf(A_log[d * D_STATE + n0 + 2]);
    const float a3 = -__expf(A_log[d * D_STATE + n0 + 3]);

    const bool fast =
        fabsf(a0 + (float)(n0 + 1)) < 1e-3f * (n0 + 1) &&
        fabsf(a1 + (float)(n0 + 2)) < 1e-3f * (n0 + 2) &&
        fabsf(a2 + (float)(n0 + 3)) < 1e-3f * (n0 + 3) &&
        fabsf(a3 + (float)(n0 + 4)) < 1e-3f * (n0 + 4);

    const size_t base = (size_t)b * SEQLEN * D_INNER + d;
    const float* dp = delta + base;
    const float* up = u + base;
    const float* zp = z + base;
    __half* yp = y16 + (size_t)b * SEQLEN * 2 * D_INNER + d;
    const float4* Bp = (const float4*)Bm + (size_t)b * SEQLEN * 4 + sub;
    const float4* Cp = (const float4*)Cm + (size_t)b * SEQLEN * 4 + sub;
    const float Dd = Dp[d];

    float h0 = 0.f, h1 = 0.f, h2 = 0.f, h3 = 0.f;

    if (fast) {
        #pragma unroll 2
        for (int l = 0; l < SEQLEN; ++l) {
            const float dt = dp[(size_t)l * D_INNER];
            const float uu = up[(size_t)l * D_INNER];
            const float4 Bv = Bp[(size_t)l * 4];
            const float4 Cv = Cp[(size_t)l * 4];
            const float e  = __expf(-dt);
            const float e2 = e * e;
            const float e4 = e2 * e2;
            const float e8 = e4 * e4;
            float m = 1.f;
            if (sub & 1) m = e4;
            if (sub & 2) m *= e8;
            const float dA0 = m * e;
            const float dA1 = dA0 * e;
            const float dA2 = dA1 * e;
            const float dA3 = dA2 * e;
            const float xv = dt * uu;
            h0 = fmaf(h0, dA0, xv * Bv.x);
            h1 = fmaf(h1, dA1, xv * Bv.y);
            h2 = fmaf(h2, dA2, xv * Bv.z);
            h3 = fmaf(h3, dA3, xv * Bv.w);
            float yv = h0 * Cv.x + h1 * Cv.y + h2 * Cv.z + h3 * Cv.w;
            yv += __shfl_xor_sync(0xffffffffu, yv, 1);
            yv += __shfl_xor_sync(0xffffffffu, yv, 2);
            if (sub == 0) {
                const float zz = zp[(size_t)l * D_INNER];
                const float sz = zz / (1.0f + __expf(-zz));
                const float yo = (yv + uu * Dd) * sz;
                __half h, lo;
                split_fp16(yo, h, lo);
                __half* q = yp + (size_t)l * 2 * D_INNER;
                q[0] = h; q[D_INNER] = lo;
            }
        }
    } else {
        #pragma unroll 2
        for (int l = 0; l < SEQLEN; ++l) {
            const float dt = dp[(size_t)l * D_INNER];
            const float uu = up[(size_t)l * D_INNER];
            const float4 Bv = Bp[(size_t)l * 4];
            const float4 Cv = Cp[(size_t)l * 4];
            const float dA0 = __expf(dt * a0);
            const float dA1 = __expf(dt * a1);
            const float dA2 = __expf(dt * a2);
            const float dA3 = __expf(dt * a3);
            const float xv = dt * uu;
            h0 = fmaf(h0, dA0, xv * Bv.x);
            h1 = fmaf(h1, dA1, xv * Bv.y);
            h2 = fmaf(h2, dA2, xv * Bv.z);
            h3 = fmaf(h3, dA3, xv * Bv.w);
            float yv = h0 * Cv.x + h1 * Cv.y + h2 * Cv.z + h3 * Cv.w;
            yv += __shfl_xor_sync(0xffffffffu, yv, 1);
            yv += __shfl_xor_sync(0xffffffffu, yv, 2);
            if (sub == 0) {
                const float zz = zp[(size_t)l * D_INNER];
                const float sz = zz / (1.0f + __expf(-zz));
                const float yo = (yv + uu * Dd) * sz;
                __half h, lo;
                split_fp16(yo, h, lo);
                __half* q = yp + (size_t)l * 2 * D_INNER;
                q[0] = h; q[D_INNER] = lo;
            }
        }
    }
}

// ---------------- launch ------------------------------------------------------
extern "C" void kernel_launch(void* const* d_in, const int* in_sizes, int n_in,
                              void* d_out, int out_size)
{
    const float* x      = (const float*)d_in[0];
    const float* W_in   = (const float*)d_in[1];
    const float* conv_w = (const float*)d_in[2];
    const float* conv_b = (const float*)d_in[3];
    const float* W_xprj = (const float*)d_in[4];
    const float* W_dt   = (const float*)d_in[5];
    const float* b_dt   = (const float*)d_in[6];
    const float* A_log  = (const float*)d_in[7];
    const float* Dp     = (const float*)d_in[8];
    const float* W_out  = (const float*)d_in[9];
    float* out = (float*)d_out;

    float *u, *z, *uc, *delta, *dtr, *Bm, *Cm;
    cudaGetSymbolAddress((void**)&u,     g_u);
    cudaGetSymbolAddress((void**)&z,     g_z);
    cudaGetSymbolAddress((void**)&uc,    g_uc);
    cudaGetSymbolAddress((void**)&delta, g_delta);
    cudaGetSymbolAddress((void**)&dtr,   g_dtr);
    cudaGetSymbolAddress((void**)&Bm,    g_Bm);
    cudaGetSymbolAddress((void**)&Cm,    g_Cm);

    __nv_bfloat16 *x2, *Winu2, *uc2, *Wxp2, *dtr2, *Wdt2;
    __half *x16, *Winz16, *y16, *Wout16;
    cudaGetSymbolAddress((void**)&x2,     g_x2);
    cudaGetSymbolAddress((void**)&Winu2,  g_Winu2);
    cudaGetSymbolAddress((void**)&uc2,    g_uc2);
    cudaGetSymbolAddress((void**)&Wxp2,   g_Wxp2);
    cudaGetSymbolAddress((void**)&dtr2,   g_dtr2);
    cudaGetSymbolAddress((void**)&Wdt2,   g_Wdt2);
    cudaGetSymbolAddress((void**)&x16,    g_x16);
    cudaGetSymbolAddress((void**)&Winz16, g_Winz16);
    cudaGetSymbolAddress((void**)&y16,    g_y16);
    cudaGetSymbolAddress((void**)&Wout16, g_Wout16);

    cudaFuncSetAttribute(gemm_tc<EPI_PLAIN, 0>,    cudaFuncAttributeMaxDynamicSharedMemorySize, GEMM_SMEM);
    cudaFuncSetAttribute(gemm_tc<EPI_PLAIN, 1>,    cudaFuncAttributeMaxDynamicSharedMemorySize, GEMM_SMEM);
    cudaFuncSetAttribute(gemm_tc<EPI_SOFTPLUS, 0>, cudaFuncAttributeMaxDynamicSharedMemorySize, GEMM_SMEM);
    cudaFuncSetAttribute(gemm_tc<EPI_XPROJ, 0>,    cudaFuncAttributeMaxDynamicSharedMemorySize, GEMM_SMEM);

    // weight packs up front (independent of activations)
    packBt_kernel<<<dim3(D_MODEL / 32, D_INNER / 32), 256>>>(
        W_in, Winu2, D_MODEL, D_INNER, D_INNER, 2 * D_INNER, 0);          // u half
    packBt16_kernel<<<dim3(D_MODEL / 32, D_INNER / 32), 256>>>(
        W_in, Winz16, D_MODEL, D_INNER, D_INNER, 2 * D_INNER, D_INNER);   // z half
    packBt_kernel<<<dim3(D_INNER / 32, 128 / 32), 256>>>(
        W_xprj, Wxp2, D_INNER, DT_RANK + 2 * D_STATE, 128, DT_RANK + 2 * D_STATE, 0);
    packBt_kernel<<<dim3((DT_RANK + 31) / 32, D_INNER / 32), 256>>>(
        W_dt, Wdt2, DT_RANK, D_INNER, D_INNER, D_INNER, 0);
    packBt16_kernel<<<dim3(D_INNER / 32, D_MODEL / 32), 256>>>(
        W_out, Wout16, D_INNER, D_MODEL, D_MODEL, D_MODEL, 0);

    // activation packs for G1
    {
        const int total4 = ROWS * (D_MODEL / 4);
        packA_kernel<<<(total4 + 255) / 256, 256>>>(x, x2, D_MODEL, total4);
        packA16_kernel<<<(total4 + 255) / 256, 256>>>(x, x16, D_MODEL, total4);
    }

    // ---- G1u: u = x @ W_in[:, :2048]  (bf16 3-term) ------------------------
    gemm_tc<EPI_PLAIN, 0><<<dim3(D_INNER / GBN, ROWS / GBM), 256, GEMM_SMEM>>>(
        (const uint8_t*)x2, (const uint8_t*)Winu2, 3 * D_MODEL, D_INNER,
        u, nullptr, nullptr, nullptr);
    // ---- G1z: z = x @ W_in[:, 2048:]  (fp16 2-term) ------------------------
    gemm_tc<EPI_PLAIN, 1><<<dim3(D_INNER / GBN, ROWS / GBM), 256, GEMM_SMEM>>>(
        (const uint8_t*)x16, (const uint8_t*)Winz16, 2 * D_MODEL, D_INNER,
        z, nullptr, nullptr, nullptr);

    // ---- conv + silu + pack uc2 --------------------------------------------
    conv_silu_kernel<<<(BATCH * D_INNER * (SEQLEN / 16)) / 256, 256>>>(
        u, conv_w, conv_b, uc, uc2);

    // ---- G2: proj = uc @ W_xproj -> dtr|Bm|Cm (bf16 3-term) ----------------
    gemm_tc<EPI_XPROJ, 0><<<dim3(1, ROWS / GBM), 256, GEMM_SMEM>>>(
        (const uint8_t*)uc2, (const uint8_t*)Wxp2, 3 * D_INNER, 128,
        dtr, Bm, Cm, nullptr);

    // ---- G3: delta = softplus(dtr @ W_dt + b_dt) (bf16 3-term) -------------
    {
        const int total4 = ROWS * (DT_RANK / 4);
        packA_kernel<<<(total4 + 255) / 256, 256>>>(dtr, dtr2, DT_RANK, total4);
    }
    gemm_tc<EPI_SOFTPLUS, 0><<<dim3(D_INNER / GBN, ROWS / GBM), 256, GEMM_SMEM>>>(
        (const uint8_t*)dtr2, (const uint8_t*)Wdt2, 3 * DT_RANK, D_INNER,
        delta, nullptr, nullptr, b_dt);

    // ---- scan + gating -> fp16 [hi|lo] y -----------------------------------
    scan_kernel<<<(ROWS * 4) / 128, 128>>>(delta, uc, z, Bm, Cm, A_log, Dp, y16);

    // ---- G5: out = y @ W_out (fp16 2-term) ---------------------------------
    gemm_tc<EPI_PLAIN, 1><<<dim3(D_MODEL / GBN, ROWS / GBM), 256, GEMM_SMEM>>>(
        (const uint8_t*)y16, (const uint8_t*)Wout16, 2 * D_INNER, D_MODEL,
        out, nullptr, nullptr, nullptr);
}

// round 10
// speedup vs baseline: 1.1285x; 1.0312x over previous
#include <cuda_runtime.h>
#include <cuda_bf16.h>
#include <cuda_fp16.h>
#include <cstdint>
#include <math.h>

#define D_MODEL 1024
#define D_STATE 16
#define D_INNER 2048
#define DT_RANK 64
#define BATCH   4
#define SEQLEN  2048
#define ROWS    (BATCH * SEQLEN)   // 8192

// ---------------- device scratch (allocation-free rule) -----------------------
__device__ __align__(16) float g_u[ROWS * D_INNER];
__device__ __align__(16) float g_z[ROWS * D_INNER];
__device__ __align__(16) float g_uc[ROWS * D_INNER];
__device__ __align__(16) float g_delta[ROWS * D_INNER];
__device__ __align__(16) float g_dtr[ROWS * DT_RANK];
__device__ __align__(16) float g_Bm[ROWS * D_STATE];
__device__ __align__(16) float g_Cm[ROWS * D_STATE];

// bf16 3-term operands (A: [hi|hi|lo], Bt: [hi|lo|hi]) — exp-sensitive path
__device__ __align__(16) __nv_bfloat16 g_uc2 [ROWS * 3 * D_INNER];       // G2 A
__device__ __align__(16) __nv_bfloat16 g_Wxp2[128 * 3 * D_INNER];        // G2 B
__device__ __align__(16) __nv_bfloat16 g_dtr2[ROWS * 3 * DT_RANK];       // G3 A
__device__ __align__(16) __nv_bfloat16 g_Wdt2[D_INNER * 3 * DT_RANK];    // G3 B

// fp16 2-term operands (A: [hi|lo], Bt: [hi|hi]) — fp16-tolerant paths
__device__ __align__(16) __half g_x16  [ROWS * 2 * D_MODEL];             // G1u+G1z A
__device__ __align__(16) __half g_Winu16[D_INNER * 2 * D_MODEL];         // G1u B (u half)
__device__ __align__(16) __half g_Winz16[D_INNER * 2 * D_MODEL];         // G1z B (z half)
__device__ __align__(16) __half g_y16  [ROWS * 2 * D_INNER];             // G5 A (from scan)
__device__ __align__(16) __half g_Wout16[D_MODEL * 2 * D_INNER];         // G5 B

// ---------------- helpers -----------------------------------------------------
__device__ __forceinline__ uint32_t smem_u32(const void* p) {
    uint32_t a;
    asm("{ .reg .u64 t; cvta.to.shared.u64 t, %1; cvt.u32.u64 %0, t; }" : "=r"(a) : "l"(p));
    return a;
}
__device__ __forceinline__ void cp16(uint32_t saddr, const void* gaddr) {
    asm volatile("cp.async.cg.shared.global [%0], [%1], 16;" :: "r"(saddr), "l"(gaddr));
}
#define SWZ(o) ((o) ^ ((((uint32_t)(o)) >> 3) & 0x70))

__device__ __forceinline__ void ldm_x4(uint32_t& r0, uint32_t& r1, uint32_t& r2, uint32_t& r3,
                                       uint32_t addr) {
    asm volatile("ldmatrix.sync.aligned.m8n8.x4.shared.b16 {%0,%1,%2,%3}, [%4];"
                 : "=r"(r0), "=r"(r1), "=r"(r2), "=r"(r3) : "r"(addr));
}
__device__ __forceinline__ void mma_bf16(float& c0, float& c1, float& c2, float& c3,
                                         uint32_t a0, uint32_t a1, uint32_t a2, uint32_t a3,
                                         uint32_t b0, uint32_t b1) {
    asm volatile("mma.sync.aligned.m16n8k16.row.col.f32.bf16.bf16.f32 "
                 "{%0,%1,%2,%3}, {%4,%5,%6,%7}, {%8,%9}, {%0,%1,%2,%3};"
                 : "+f"(c0), "+f"(c1), "+f"(c2), "+f"(c3)
                 : "r"(a0), "r"(a1), "r"(a2), "r"(a3), "r"(b0), "r"(b1));
}
__device__ __forceinline__ void mma_fp16(float& c0, float& c1, float& c2, float& c3,
                                         uint32_t a0, uint32_t a1, uint32_t a2, uint32_t a3,
                                         uint32_t b0, uint32_t b1) {
    asm volatile("mma.sync.aligned.m16n8k16.row.col.f32.f16.f16.f32 "
                 "{%0,%1,%2,%3}, {%4,%5,%6,%7}, {%8,%9}, {%0,%1,%2,%3};"
                 : "+f"(c0), "+f"(c1), "+f"(c2), "+f"(c3)
                 : "r"(a0), "r"(a1), "r"(a2), "r"(a3), "r"(b0), "r"(b1));
}
__device__ __forceinline__ void split_bf16(float v, __nv_bfloat16& h, __nv_bfloat16& l) {
    h = __float2bfloat16(v);
    l = __float2bfloat16(v - __bfloat162float(h));
}
__device__ __forceinline__ void split_fp16(float v, __half& h, __half& l) {
    h = __float2half(v);
    l = __float2half(v - __half2float(h));
}

// ---------------- mma.sync GEMM (bf16 or fp16, same layout) --------------------
// C[M,N] = A[M,Kp] * Bt[N,Kp]^T, K-major row-major bf16/fp16, fp32 accumulate.
// BM=BN=128, BK=64 (128B rows, xor-swizzled), 3-stage cp.async pipeline,
// 256 threads = 8 warps in 4(m) x 2(n), warp tile 32x64.
enum { EPI_PLAIN = 0, EPI_SOFTPLUS = 2, EPI_XPROJ = 3 };

#define GBM 128
#define GBN 128
#define GBK 64
#define GSTAGES 3
#define GTILE_B (GBM * GBK * 2)          // 16384 bytes per operand tile
#define GSTAGE_B (2 * GTILE_B)           // 32768
#define GEMM_SMEM (GSTAGES * GSTAGE_B)   // 98304

template <int EPI, int FP16>
__global__ __launch_bounds__(256, 2)
void gemm_tc(const uint8_t* __restrict__ A, const uint8_t* __restrict__ Bt,
             int Kp, int N,
             float* __restrict__ O0, float* __restrict__ O1, float* __restrict__ O2,
             const float* __restrict__ bias)
{
    extern __shared__ char smem[];
    const uint32_t sb = smem_u32(smem);
    const int tid = threadIdx.x;
    const int wid = tid >> 5, lid = tid & 31;
    const int wr = wid & 3;
    const int wc = wid >> 2;
    const int m0 = blockIdx.y * GBM;
    const int n0 = blockIdx.x * GBN;
    const int chunks = Kp / GBK;

    const uint8_t* Ap = A + (size_t)m0 * Kp * 2;
    const uint8_t* Bp = Bt + (size_t)n0 * Kp * 2;

    const int ldrow = tid >> 3;
    const int ldch  = tid & 7;

    auto load_stage = [&](int c) {
        const int s = c % GSTAGES;
        const uint32_t sa = sb + s * GSTAGE_B;
        const uint32_t sB = sa + GTILE_B;
        const size_t k0b = (size_t)c * GBK * 2;
        #pragma unroll
        for (int j = 0; j < 4; ++j) {
            const int r = ldrow + j * 32;
            const uint32_t so = SWZ(r * 128 + ldch * 16);
            cp16(sa + so, Ap + (size_t)r * Kp * 2 + k0b + ldch * 16);
            cp16(sB + so, Bp + (size_t)r * Kp * 2 + k0b + ldch * 16);
        }
        asm volatile("cp.async.commit_group;" ::: "memory");
    };

    const int pre = (chunks < GSTAGES - 1) ? chunks : (GSTAGES - 1);
    for (int c = 0; c < pre; ++c) load_stage(c);

    float acc[2][8][4];
    #pragma unroll
    for (int i = 0; i < 2; ++i)
        #pragma unroll
        for (int j = 0; j < 8; ++j)
            #pragma unroll
            for (int k = 0; k < 4; ++k) acc[i][j][k] = 0.f;

    const int lrow = lid & 15;
    const int lhalf = lid >> 4;

    for (int c = 0; c < chunks; ++c) {
        const int remaining = chunks - 1 - c;
        if (remaining >= 1) asm volatile("cp.async.wait_group 1;" ::: "memory");
        else                asm volatile("cp.async.wait_group 0;" ::: "memory");
        __syncthreads();

        if (c + GSTAGES - 1 < chunks) load_stage(c + GSTAGES - 1);

        const int s = c % GSTAGES;
        const uint32_t sa = sb + s * GSTAGE_B;
        const uint32_t sB = sa + GTILE_B;

        #pragma unroll
        for (int kk = 0; kk < 4; ++kk) {
            uint32_t a[2][4];
            #pragma unroll
            for (int wm = 0; wm < 2; ++wm) {
                const int row = wr * 32 + wm * 16 + lrow;
                const uint32_t off = SWZ(row * 128 + (kk * 2 + lhalf) * 16);
                ldm_x4(a[wm][0], a[wm][1], a[wm][2], a[wm][3], sa + off);
            }
            uint32_t b[4][4];
            #pragma unroll
            for (int g = 0; g < 4; ++g) {
                const int row = wc * 64 + g * 16 + lrow;
                const uint32_t off = SWZ(row * 128 + (kk * 2 + lhalf) * 16);
                ldm_x4(b[g][0], b[g][1], b[g][2], b[g][3], sB + off);
            }
            #pragma unroll
            for (int wm = 0; wm < 2; ++wm)
                #pragma unroll
                for (int j = 0; j < 8; ++j) {
                    const int g = j >> 1, h = j & 1;
                    if (FP16)
                        mma_fp16(acc[wm][j][0], acc[wm][j][1], acc[wm][j][2], acc[wm][j][3],
                                 a[wm][0], a[wm][1], a[wm][2], a[wm][3],
                                 b[g][h], b[g][2 + h]);
                    else
                        mma_bf16(acc[wm][j][0], acc[wm][j][1], acc[wm][j][2], acc[wm][j][3],
                                 a[wm][0], a[wm][1], a[wm][2], a[wm][3],
                                 b[g][h], b[g][2 + h]);
                }
        }
    }

    // ---------------- epilogue ------------------------------------------------
    const int tq = lid >> 2;
    const int tr = lid & 3;
    #pragma unroll
    for (int wm = 0; wm < 2; ++wm) {
        #pragma unroll
        for (int j = 0; j < 8; ++j) {
            #pragma unroll
            for (int half = 0; half < 2; ++half) {
                const int gr = m0 + wr * 32 + wm * 16 + tq + half * 8;
                const int gc = n0 + wc * 64 + j * 8 + tr * 2;
                float v0 = acc[wm][j][half * 2 + 0];
                float v1 = acc[wm][j][half * 2 + 1];
                if (EPI == EPI_PLAIN) {
                    float2 v = {v0, v1};
                    *(float2*)&O0[(size_t)gr * N + gc] = v;
                } else if (EPI == EPI_SOFTPLUS) {
                    v0 += bias[gc]; v1 += bias[gc + 1];
                    v0 = (v0 > 20.0f) ? v0 : log1pf(__expf(v0));
                    v1 = (v1 > 20.0f) ? v1 : log1pf(__expf(v1));
                    float2 v = {v0, v1};
                    *(float2*)&O0[(size_t)gr * N + gc] = v;
                } else { // EPI_XPROJ: 0..63 dtr | 64..79 Bm | 80..95 Cm | pad
                    float2 v = {v0, v1};
                    if (gc < DT_RANK)           *(float2*)&O0[(size_t)gr * DT_RANK + gc] = v;
                    else if (gc < DT_RANK + 16) *(float2*)&O1[(size_t)gr * 16 + (gc - DT_RANK)] = v;
                    else if (gc < DT_RANK + 32) *(float2*)&O2[(size_t)gr * 16 + (gc - DT_RANK - 16)] = v;
                }
            }
        }
    }
}

// ---------------- packing kernels ---------------------------------------------
// bf16 3-term A: fp32[M,K] -> bf16[M,3K] = [hi | hi | lo]  (flat 1D, float4/thread)
__global__ __launch_bounds__(256)
void packA_kernel(const float* __restrict__ in, __nv_bfloat16* __restrict__ out,
                  int K, int total4)
{
    const int idx = blockIdx.x * 256 + threadIdx.x;
    if (idx >= total4) return;
    const int kq = K >> 2;
    const int m = idx / kq;
    const int k = (idx - m * kq) * 4;
    const float4 v = *(const float4*)(in + (size_t)m * K + k);
    __nv_bfloat16 h0, h1, h2, h3, l0, l1, l2, l3;
    split_bf16(v.x, h0, l0); split_bf16(v.y, h1, l1);
    split_bf16(v.z, h2, l2); split_bf16(v.w, h3, l3);
    __nv_bfloat16* op = out + (size_t)m * 3 * K;
    __nv_bfloat162 hh01; hh01.x = h0; hh01.y = h1;
    __nv_bfloat162 hh23; hh23.x = h2; hh23.y = h3;
    __nv_bfloat162 ll01; ll01.x = l0; ll01.y = l1;
    __nv_bfloat162 ll23; ll23.x = l2; ll23.y = l3;
    *(__nv_bfloat162*)(op + k)             = hh01;
    *(__nv_bfloat162*)(op + k + 2)         = hh23;
    *(__nv_bfloat162*)(op + K + k)         = hh01;
    *(__nv_bfloat162*)(op + K + k + 2)     = hh23;
    *(__nv_bfloat162*)(op + 2 * K + k)     = ll01;
    *(__nv_bfloat162*)(op + 2 * K + k + 2) = ll23;
}

// fp16 2-term A: fp32[M,K] -> fp16[M,2K] = [hi | lo]
__global__ __launch_bounds__(256)
void packA16_kernel(const float* __restrict__ in, __half* __restrict__ out,
                    int K, int total4)
{
    const int idx = blockIdx.x * 256 + threadIdx.x;
    if (idx >= total4) return;
    const int kq = K >> 2;
    const int m = idx / kq;
    const int k = (idx - m * kq) * 4;
    const float4 v = *(const float4*)(in + (size_t)m * K + k);
    __half h0, h1, h2, h3, l0, l1, l2, l3;
    split_fp16(v.x, h0, l0); split_fp16(v.y, h1, l1);
    split_fp16(v.z, h2, l2); split_fp16(v.w, h3, l3);
    __half* op = out + (size_t)m * 2 * K;
    __half2 hh01; hh01.x = h0; hh01.y = h1;
    __half2 hh23; hh23.x = h2; hh23.y = h3;
    __half2 ll01; ll01.x = l0; ll01.y = l1;
    __half2 ll23; ll23.x = l2; ll23.y = l3;
    *(__half2*)(op + k)         = hh01;
    *(__half2*)(op + k + 2)     = hh23;
    *(__half2*)(op + K + k)     = ll01;
    *(__half2*)(op + K + k + 2) = ll23;
}

// bf16 3-term Bt: fp32[K, ldn] cols [ncol0, ncol0+Nv) -> bf16[Np, 3K] = [hi|lo|hi]
__global__ __launch_bounds__(256)
void packBt_kernel(const float* __restrict__ in, __nv_bfloat16* __restrict__ out,
                   int K, int Nv, int Np, int ldn, int ncol0)
{
    __shared__ float s[32][33];
    const int kb = blockIdx.x * 32, nb = blockIdx.y * 32;
    const int tx = threadIdx.x & 31, ty = threadIdx.x >> 5;
    #pragma unroll
    for (int r = 0; r < 32; r += 8) {
        const int k = kb + ty + r, n = nb + tx;
        s[ty + r][tx] = (k < K && n < Nv) ? in[(size_t)k * ldn + ncol0 + n] : 0.0f;
    }
    __syncthreads();
    #pragma unroll
    for (int r = 0; r < 32; r += 8) {
        const int n = nb + ty + r, k = kb + tx;
        if (n < Np && k < K) {
            const float v = s[tx][ty + r];
            __nv_bfloat16 h, lo;
            split_bf16(v, h, lo);
            __nv_bfloat16* op = out + (size_t)n * 3 * K;
            op[k] = h; op[K + k] = lo; op[2 * K + k] = h;
        }
    }
}

// fp16 dup Bt: fp32[K, ldn] cols [ncol0, ncol0+Nv) -> fp16[Np, 2K] = [hi|hi]
__global__ __launch_bounds__(256)
void packBt16_kernel(const float* __restrict__ in, __half* __restrict__ out,
                     int K, int Nv, int Np, int ldn, int ncol0)
{
    __shared__ float s[32][33];
    const int kb = blockIdx.x * 32, nb = blockIdx.y * 32;
    const int tx = threadIdx.x & 31, ty = threadIdx.x >> 5;
    #pragma unroll
    for (int r = 0; r < 32; r += 8) {
        const int k = kb + ty + r, n = nb + tx;
        s[ty + r][tx] = (k < K && n < Nv) ? in[(size_t)k * ldn + ncol0 + n] : 0.0f;
    }
    __syncthreads();
    #pragma unroll
    for (int r = 0; r < 32; r += 8) {
        const int n = nb + ty + r, k = kb + tx;
        if (n < Np && k < K) {
            const __half h = __float2half(s[tx][ty + r]);
            __half* op = out + (size_t)n * 2 * K;
            op[k] = h; op[K + k] = h;
        }
    }
}

// ---------------- causal depthwise conv (k=4) + SiLU + pack -------------------
__global__ __launch_bounds__(256)
void conv_silu_kernel(const float* __restrict__ u, const float* __restrict__ w,
                      const float* __restrict__ bias, float* __restrict__ uc,
                      __nv_bfloat16* __restrict__ uc2)
{
    constexpr int CHUNK = 16;
    int gid = blockIdx.x * blockDim.x + threadIdx.x;
    int d = gid & (D_INNER - 1);
    int rest = gid >> 11;
    int b = rest & (BATCH - 1);
    int chunk = rest >> 2;
    int l0 = chunk * CHUNK;

    const float w0 = w[d * 4 + 0], w1 = w[d * 4 + 1],
                w2 = w[d * 4 + 2], w3 = w[d * 4 + 3];
    const float bb = bias[d];

    const size_t base = ((size_t)b * SEQLEN + l0) * D_INNER + d;
    const float* up = u + base;
    float* op = uc + base;
    __nv_bfloat16* pp = uc2 + ((size_t)b * SEQLEN + l0) * 3 * D_INNER + d;

    float xm3, xm2, xm1;
    if (l0 == 0) { xm3 = 0.f; xm2 = 0.f; xm1 = 0.f; }
    else {
        xm3 = up[-3 * D_INNER];
        xm2 = up[-2 * D_INNER];
        xm1 = up[-1 * D_INNER];
    }
    #pragma unroll
    for (int i = 0; i < CHUNK; ++i) {
        float cur = up[(size_t)i * D_INNER];
        float v = fmaf(xm3, w0, fmaf(xm2, w1, fmaf(xm1, w2, fmaf(cur, w3, bb))));
        float s = v / (1.0f + __expf(-v));
        op[(size_t)i * D_INNER] = s;
        __nv_bfloat16 h, lo;
        split_bf16(s, h, lo);
        __nv_bfloat16* q = pp + (size_t)i * 3 * D_INNER;
        q[0] = h; q[D_INNER] = h; q[2 * D_INNER] = lo;
        xm3 = xm2; xm2 = xm1; xm1 = cur;
    }
}

// ---------------- selective scan (emits fp16 [hi|lo] y for G5) ----------------
__global__ __launch_bounds__(128)
void scan_kernel(const float* __restrict__ delta, const float* __restrict__ u,
                 const float* __restrict__ z, const float* __restrict__ Bm,
                 const float* __restrict__ Cm, const float* __restrict__ A_log,
                 const float* __restrict__ Dp, __half* __restrict__ y16)
{
    const int t = blockIdx.x * blockDim.x + threadIdx.x;
    const int sub = t & 3;
    const int ch = t >> 2;
    const int d = ch & (D_INNER - 1);
    const int b = ch >> 11;
    const int n0 = sub * 4;

    const float a0 = -__expf(A_log[d * D_STATE + n0 + 0]);
    const float a1 = -__expf(A_log[d * D_STATE + n0 + 1]);
    const float a2 = -__expf(A_log[d * D_STATE + n0 + 2]);
    const float a3 = -__expf(A_log[d * D_STATE + n0 + 3]);

    const bool fast =
        fabsf(a0 + (float)(n0 + 1)) < 1e-3f * (n0 + 1) &&
        fabsf(a1 + (float)(n0 + 2)) < 1e-3f * (n0 + 2) &&
        fabsf(a2 + (float)(n0 + 3)) < 1e-3f * (n0 + 3) &&
        fabsf(a3 + (float)(n0 + 4)) < 1e-3f * (n0 + 4);

    const size_t base = (size_t)b * SEQLEN * D_INNER + d;
    const float* dp = delta + base;
    const float* up = u + base;
    const float* zp = z + base;
    __half* yp = y16 + (size_t)b * SEQLEN * 2 * D_INNER + d;
    const float4* Bp = (const float4*)Bm + (size_t)b * SEQLEN * 4 + sub;
    const float4* Cp = (const float4*)Cm + (size_t)b * SEQLEN * 4 + sub;
    const float Dd = Dp[d];

    float h0 = 0.f, h1 = 0.f, h2 = 0.f, h3 = 0.f;

    if (fast) {
        #pragma unroll 2
        for (int l = 0; l < SEQLEN; ++l) {
            const float dt = dp[(size_t)l * D_INNER];
            const float uu = up[(size_t)l * D_INNER];
            const float4 Bv = Bp[(size_t)l * 4];
            const float4 Cv = Cp[(size_t)l * 4];
            const float e  = __expf(-dt);
            const float e2 = e * e;
            const float e4 = e2 * e2;
            const float e8 = e4 * e4;
            float m = 1.f;
            if (sub & 1) m = e4;
            if (sub & 2) m *= e8;
            const float dA0 = m * e;
            const float dA1 = dA0 * e;
            const float dA2 = dA1 * e;
            const float dA3 = dA2 * e;
            const float xv = dt * uu;
            h0 = fmaf(h0, dA0, xv * Bv.x);
            h1 = fmaf(h1, dA1, xv * Bv.y);
            h2 = fmaf(h2, dA2, xv * Bv.z);
            h3 = fmaf(h3, dA3, xv * Bv.w);
            float yv = h0 * Cv.x + h1 * Cv.y + h2 * Cv.z + h3 * Cv.w;
            yv += __shfl_xor_sync(0xffffffffu, yv, 1);
            yv += __shfl_xor_sync(0xffffffffu, yv, 2);
            if (sub == 0) {
                const float zz = zp[(size_t)l * D_INNER];
                const float sz = zz / (1.0f + __expf(-zz));
                const float yo = (yv + uu * Dd) * sz;
                __half h, lo;
                split_fp16(yo, h, lo);
                __half* q = yp + (size_t)l * 2 * D_INNER;
                q[0] = h; q[D_INNER] = lo;
            }
        }
    } else {
        #pragma unroll 2
        for (int l = 0; l < SEQLEN; ++l) {
            const float dt = dp[(size_t)l * D_INNER];
            const float uu = up[(size_t)l * D_INNER];
            const float4 Bv = Bp[(size_t)l * 4];
            const float4 Cv = Cp[(size_t)l * 4];
            const float dA0 = __expf(dt * a0);
            const float dA1 = __expf(dt * a1);
            const float dA2 = __expf(dt * a2);
            const float dA3 = __expf(dt * a3);
            const float xv = dt * uu;
            h0 = fmaf(h0, dA0, xv * Bv.x);
            h1 = fmaf(h1, dA1, xv * Bv.y);
            h2 = fmaf(h2, dA2, xv * Bv.z);
            h3 = fmaf(h3, dA3, xv * Bv.w);
            float yv = h0 * Cv.x + h1 * Cv.y + h2 * Cv.z + h3 * Cv.w;
            yv += __shfl_xor_sync(0xffffffffu, yv, 1);
            yv += __shfl_xor_sync(0xffffffffu, yv, 2);
            if (sub == 0) {
                const float zz = zp[(size_t)l * D_INNER];
                const float sz = zz / (1.0f + __expf(-zz));
                const float yo = (yv + uu * Dd) * sz;
                __half h, lo;
                split_fp16(yo, h, lo);
                __half* q = yp + (size_t)l * 2 * D_INNER;
                q[0] = h; q[D_INNER] = lo;
            }
        }
    }
}

// ---------------- launch ------------------------------------------------------
extern "C" void kernel_launch(void* const* d_in, const int* in_sizes, int n_in,
                              void* d_out, int out_size)
{
    const float* x      = (const float*)d_in[0];
    const float* W_in   = (const float*)d_in[1];
    const float* conv_w = (const float*)d_in[2];
    const float* conv_b = (const float*)d_in[3];
    const float* W_xprj = (const float*)d_in[4];
    const float* W_dt   = (const float*)d_in[5];
    const float* b_dt   = (const float*)d_in[6];
    const float* A_log  = (const float*)d_in[7];
    const float* Dp     = (const float*)d_in[8];
    const float* W_out  = (const float*)d_in[9];
    float* out = (float*)d_out;

    float *u, *z, *uc, *delta, *dtr, *Bm, *Cm;
    cudaGetSymbolAddress((void**)&u,     g_u);
    cudaGetSymbolAddress((void**)&z,     g_z);
    cudaGetSymbolAddress((void**)&uc,    g_uc);
    cudaGetSymbolAddress((void**)&delta, g_delta);
    cudaGetSymbolAddress((void**)&dtr,   g_dtr);
    cudaGetSymbolAddress((void**)&Bm,    g_Bm);
    cudaGetSymbolAddress((void**)&Cm,    g_Cm);

    __nv_bfloat16 *uc2, *Wxp2, *dtr2, *Wdt2;
    __half *x16, *Winu16, *Winz16, *y16, *Wout16;
    cudaGetSymbolAddress((void**)&uc2,    g_uc2);
    cudaGetSymbolAddress((void**)&Wxp2,   g_Wxp2);
    cudaGetSymbolAddress((void**)&dtr2,   g_dtr2);
    cudaGetSymbolAddress((void**)&Wdt2,   g_Wdt2);
    cudaGetSymbolAddress((void**)&x16,    g_x16);
    cudaGetSymbolAddress((void**)&Winu16, g_Winu16);
    cudaGetSymbolAddress((void**)&Winz16, g_Winz16);
    cudaGetSymbolAddress((void**)&y16,    g_y16);
    cudaGetSymbolAddress((void**)&Wout16, g_Wout16);

    cudaFuncSetAttribute(gemm_tc<EPI_PLAIN, 0>,    cudaFuncAttributeMaxDynamicSharedMemorySize, GEMM_SMEM);
    cudaFuncSetAttribute(gemm_tc<EPI_PLAIN, 1>,    cudaFuncAttributeMaxDynamicSharedMemorySize, GEMM_SMEM);
    cudaFuncSetAttribute(gemm_tc<EPI_SOFTPLUS, 0>, cudaFuncAttributeMaxDynamicSharedMemorySize, GEMM_SMEM);
    cudaFuncSetAttribute(gemm_tc<EPI_XPROJ, 0>,    cudaFuncAttributeMaxDynamicSharedMemorySize, GEMM_SMEM);

    // weight packs up front (independent of activations)
    packBt16_kernel<<<dim3(D_MODEL / 32, D_INNER / 32), 256>>>(
        W_in, Winu16, D_MODEL, D_INNER, D_INNER, 2 * D_INNER, 0);         // u half
    packBt16_kernel<<<dim3(D_MODEL / 32, D_INNER / 32), 256>>>(
        W_in, Winz16, D_MODEL, D_INNER, D_INNER, 2 * D_INNER, D_INNER);   // z half
    packBt_kernel<<<dim3(D_INNER / 32, 128 / 32), 256>>>(
        W_xprj, Wxp2, D_INNER, DT_RANK + 2 * D_STATE, 128, DT_RANK + 2 * D_STATE, 0);
    packBt_kernel<<<dim3((DT_RANK + 31) / 32, D_INNER / 32), 256>>>(
        W_dt, Wdt2, DT_RANK, D_INNER, D_INNER, D_INNER, 0);
    packBt16_kernel<<<dim3(D_INNER / 32, D_MODEL / 32), 256>>>(
        W_out, Wout16, D_INNER, D_MODEL, D_MODEL, D_MODEL, 0);

    // activation pack for G1 (single fp16 [hi|lo] pack serves BOTH halves)
    {
        const int total4 = ROWS * (D_MODEL / 4);
        packA16_kernel<<<(total4 + 255) / 256, 256>>>(x, x16, D_MODEL, total4);
    }

    // ---- G1u: u = x @ W_in[:, :2048]  (fp16 2-term) ------------------------
    gemm_tc<EPI_PLAIN, 1><<<dim3(D_INNER / GBN, ROWS / GBM), 256, GEMM_SMEM>>>(
        (const uint8_t*)x16, (const uint8_t*)Winu16, 2 * D_MODEL, D_INNER,
        u, nullptr, nullptr, nullptr);
    // ---- G1z: z = x @ W_in[:, 2048:]  (fp16 2-term) ------------------------
    gemm_tc<EPI_PLAIN, 1><<<dim3(D_INNER / GBN, ROWS / GBM), 256, GEMM_SMEM>>>(
        (const uint8_t*)x16, (const uint8_t*)Winz16, 2 * D_MODEL, D_INNER,
        z, nullptr, nullptr, nullptr);

    // ---- conv + silu + pack uc2 --------------------------------------------
    conv_silu_kernel<<<(BATCH * D_INNER * (SEQLEN / 16)) / 256, 256>>>(
        u, conv_w, conv_b, uc, uc2);

    // ---- G2: proj = uc @ W_xproj -> dtr|Bm|Cm (bf16 3-term) ----------------
    gemm_tc<EPI_XPROJ, 0><<<dim3(1, ROWS / GBM), 256, GEMM_SMEM>>>(
        (const uint8_t*)uc2, (const uint8_t*)Wxp2, 3 * D_INNER, 128,
        dtr, Bm, Cm, nullptr);

    // ---- G3: delta = softplus(dtr @ W_dt + b_dt) (bf16 3-term) -------------
    {
        const int total4 = ROWS * (DT_RANK / 4);
        packA_kernel<<<(total4 + 255) / 256, 256>>>(dtr, dtr2, DT_RANK, total4);
    }
    gemm_tc<EPI_SOFTPLUS, 0><<<dim3(D_INNER / GBN, ROWS / GBM), 256, GEMM_SMEM>>>(
        (const uint8_t*)dtr2, (const uint8_t*)Wdt2, 3 * DT_RANK, D_INNER,
        delta, nullptr, nullptr, b_dt);

    // ---- scan + gating -> fp16 [hi|lo] y -----------------------------------
    scan_kernel<<<(ROWS * 4) / 128, 128>>>(delta, uc, z, Bm, Cm, A_log, Dp, y16);

    // ---- G5: out = y @ W_out (fp16 2-term) ---------------------------------
    gemm_tc<EPI_PLAIN, 1><<<dim3(D_MODEL / GBN, ROWS / GBM), 256, GEMM_SMEM>>>(
        (const uint8_t*)y16, (const uint8_t*)Wout16, 2 * D_INNER, D_MODEL,
        out, nullptr, nullptr, nullptr);
}

// round 11
// speedup vs baseline: 1.2270x; 1.0873x over previous
#include <cuda_runtime.h>
#include <cuda_bf16.h>
#include <cuda_fp16.h>
#include <cstdint>
#include <math.h>

#define D_MODEL 1024
#define D_STATE 16
#define D_INNER 2048
#define DT_RANK 64
#define BATCH   4
#define SEQLEN  2048
#define ROWS    (BATCH * SEQLEN)   // 8192

// ---------------- device scratch (allocation-free rule) -----------------------
__device__ __align__(16) float g_u[ROWS * D_INNER];
__device__ __align__(16) float g_z[ROWS * D_INNER];
__device__ __align__(16) float g_uc[ROWS * D_INNER];
__device__ __align__(16) float g_delta[ROWS * D_INNER];
__device__ __align__(16) float g_dtr[ROWS * DT_RANK];
__device__ __align__(16) float g_Bm[ROWS * D_STATE];
__device__ __align__(16) float g_Cm[ROWS * D_STATE];

// bf16 3-term operands (A: [hi|hi|lo], Bt: [hi|lo|hi]) — exp-sensitive path
__device__ __align__(16) __nv_bfloat16 g_uc2 [ROWS * 3 * D_INNER];       // G2 A
__device__ __align__(16) __nv_bfloat16 g_Wxp2[128 * 3 * D_INNER];        // G2 B
__device__ __align__(16) __nv_bfloat16 g_dtr2[ROWS * 3 * DT_RANK];       // G3 A
__device__ __align__(16) __nv_bfloat16 g_Wdt2[D_INNER * 3 * DT_RANK];    // G3 B

// fp16 operands. [hi|lo] A packs double as plain-hi packs via lda strides;
// [hi|hi] B packs double as plain-hi packs via ldb strides.
__device__ __align__(16) __half g_x16  [ROWS * 2 * D_MODEL];             // G1u(2t)+G1z(1t) A
__device__ __align__(16) __half g_Winu16[D_INNER * 2 * D_MODEL];         // G1u B [hi|hi]
__device__ __align__(16) __half g_Winz16[D_INNER * 2 * D_MODEL];         // G1z B (hi half used)
__device__ __align__(16) __half g_y16  [ROWS * 2 * D_INNER];             // G5 A (hi half used)
__device__ __align__(16) __half g_Wout16[D_MODEL * 2 * D_INNER];         // G5 B (hi half used)

// ---------------- helpers -----------------------------------------------------
__device__ __forceinline__ uint32_t smem_u32(const void* p) {
    uint32_t a;
    asm("{ .reg .u64 t; cvta.to.shared.u64 t, %1; cvt.u32.u64 %0, t; }" : "=r"(a) : "l"(p));
    return a;
}
__device__ __forceinline__ void cp16(uint32_t saddr, const void* gaddr) {
    asm volatile("cp.async.cg.shared.global [%0], [%1], 16;" :: "r"(saddr), "l"(gaddr));
}
#define SWZ(o) ((o) ^ ((((uint32_t)(o)) >> 3) & 0x70))

__device__ __forceinline__ void ldm_x4(uint32_t& r0, uint32_t& r1, uint32_t& r2, uint32_t& r3,
                                       uint32_t addr) {
    asm volatile("ldmatrix.sync.aligned.m8n8.x4.shared.b16 {%0,%1,%2,%3}, [%4];"
                 : "=r"(r0), "=r"(r1), "=r"(r2), "=r"(r3) : "r"(addr));
}
__device__ __forceinline__ void mma_bf16(float& c0, float& c1, float& c2, float& c3,
                                         uint32_t a0, uint32_t a1, uint32_t a2, uint32_t a3,
                                         uint32_t b0, uint32_t b1) {
    asm volatile("mma.sync.aligned.m16n8k16.row.col.f32.bf16.bf16.f32 "
                 "{%0,%1,%2,%3}, {%4,%5,%6,%7}, {%8,%9}, {%0,%1,%2,%3};"
                 : "+f"(c0), "+f"(c1), "+f"(c2), "+f"(c3)
                 : "r"(a0), "r"(a1), "r"(a2), "r"(a3), "r"(b0), "r"(b1));
}
__device__ __forceinline__ void mma_fp16(float& c0, float& c1, float& c2, float& c3,
                                         uint32_t a0, uint32_t a1, uint32_t a2, uint32_t a3,
                                         uint32_t b0, uint32_t b1) {
    asm volatile("mma.sync.aligned.m16n8k16.row.col.f32.f16.f16.f32 "
                 "{%0,%1,%2,%3}, {%4,%5,%6,%7}, {%8,%9}, {%0,%1,%2,%3};"
                 : "+f"(c0), "+f"(c1), "+f"(c2), "+f"(c3)
                 : "r"(a0), "r"(a1), "r"(a2), "r"(a3), "r"(b0), "r"(b1));
}
__device__ __forceinline__ void split_bf16(float v, __nv_bfloat16& h, __nv_bfloat16& l) {
    h = __float2bfloat16(v);
    l = __float2bfloat16(v - __bfloat162float(h));
}
__device__ __forceinline__ void split_fp16(float v, __half& h, __half& l) {
    h = __float2half(v);
    l = __float2half(v - __half2float(h));
}

// ---------------- mma.sync GEMM (bf16 or fp16, strided operands) ---------------
// C[M,N] = A[M,Kp] * Bt[N,Kp]^T with row strides lda/ldb (elements), fp32 accum.
// BM = WM*64, BN=128, BK=64 (128B rows, xor-swizzled), 3-stage cp.async pipeline,
// 256 threads = 8 warps in 4(m) x 2(n), warp tile (WM*16) x 64.
enum { EPI_PLAIN = 0, EPI_SOFTPLUS = 2, EPI_XPROJ = 3 };

#define GBN 128
#define GBK 64
#define GSTAGES 3
#define GTILEB_B (GBN * GBK * 2)                 // 16384 bytes (B tile)
#define GEMM_SMEM_WM(WM) (GSTAGES * ((WM) * 64 * GBK * 2 + GTILEB_B))
// WM=2: 98304, WM=1: 73728

template <int EPI, int FP16, int WM>
__global__ __launch_bounds__(256, 2)
void gemm_tc(const uint8_t* __restrict__ A, const uint8_t* __restrict__ Bt,
             int lda, int ldb, int Kp, int N,
             float* __restrict__ O0, float* __restrict__ O1, float* __restrict__ O2,
             const float* __restrict__ bias)
{
    constexpr int BM = WM * 64;
    constexpr int GTILEA_B = BM * GBK * 2;
    constexpr int GSTAGE_B = GTILEA_B + GTILEB_B;

    extern __shared__ char smem[];
    const uint32_t sb = smem_u32(smem);
    const int tid = threadIdx.x;
    const int wid = tid >> 5, lid = tid & 31;
    const int wr = wid & 3;
    const int wc = wid >> 2;
    const int m0 = blockIdx.y * BM;
    const int n0 = blockIdx.x * GBN;
    const int chunks = Kp / GBK;

    const uint8_t* Ap = A + (size_t)m0 * lda * 2;
    const uint8_t* Bp = Bt + (size_t)n0 * ldb * 2;

    const int ldrow = tid >> 3;
    const int ldch  = tid & 7;

    auto load_stage = [&](int c) {
        const int s = c % GSTAGES;
        const uint32_t sa = sb + s * GSTAGE_B;
        const uint32_t sB = sa + GTILEA_B;
        const size_t k0b = (size_t)c * GBK * 2;
        #pragma unroll
        for (int j = 0; j < BM / 32; ++j) {
            const int r = ldrow + j * 32;
            const uint32_t so = SWZ(r * 128 + ldch * 16);
            cp16(sa + so, Ap + (size_t)r * lda * 2 + k0b + ldch * 16);
        }
        #pragma unroll
        for (int j = 0; j < 4; ++j) {
            const int r = ldrow + j * 32;
            const uint32_t so = SWZ(r * 128 + ldch * 16);
            cp16(sB + so, Bp + (size_t)r * ldb * 2 + k0b + ldch * 16);
        }
        asm volatile("cp.async.commit_group;" ::: "memory");
    };

    const int pre = (chunks < GSTAGES - 1) ? chunks : (GSTAGES - 1);
    for (int c = 0; c < pre; ++c) load_stage(c);

    float acc[WM][8][4];
    #pragma unroll
    for (int i = 0; i < WM; ++i)
        #pragma unroll
        for (int j = 0; j < 8; ++j)
            #pragma unroll
            for (int k = 0; k < 4; ++k) acc[i][j][k] = 0.f;

    const int lrow = lid & 15;
    const int lhalf = lid >> 4;

    for (int c = 0; c < chunks; ++c) {
        const int remaining = chunks - 1 - c;
        if (remaining >= 1) asm volatile("cp.async.wait_group 1;" ::: "memory");
        else                asm volatile("cp.async.wait_group 0;" ::: "memory");
        __syncthreads();

        if (c + GSTAGES - 1 < chunks) load_stage(c + GSTAGES - 1);

        const int s = c % GSTAGES;
        const uint32_t sa = sb + s * GSTAGE_B;
        const uint32_t sB = sa + GTILEA_B;

        #pragma unroll
        for (int kk = 0; kk < 4; ++kk) {
            uint32_t a[WM][4];
            #pragma unroll
            for (int wm = 0; wm < WM; ++wm) {
                const int row = wr * (WM * 16) + wm * 16 + lrow;
                const uint32_t off = SWZ(row * 128 + (kk * 2 + lhalf) * 16);
                ldm_x4(a[wm][0], a[wm][1], a[wm][2], a[wm][3], sa + off);
            }
            uint32_t b[4][4];
            #pragma unroll
            for (int g = 0; g < 4; ++g) {
                const int row = wc * 64 + g * 16 + lrow;
                const uint32_t off = SWZ(row * 128 + (kk * 2 + lhalf) * 16);
                ldm_x4(b[g][0], b[g][1], b[g][2], b[g][3], sB + off);
            }
            #pragma unroll
            for (int wm = 0; wm < WM; ++wm)
                #pragma unroll
                for (int j = 0; j < 8; ++j) {
                    const int g = j >> 1, h = j & 1;
                    if (FP16)
                        mma_fp16(acc[wm][j][0], acc[wm][j][1], acc[wm][j][2], acc[wm][j][3],
                                 a[wm][0], a[wm][1], a[wm][2], a[wm][3],
                                 b[g][h], b[g][2 + h]);
                    else
                        mma_bf16(acc[wm][j][0], acc[wm][j][1], acc[wm][j][2], acc[wm][j][3],
                                 a[wm][0], a[wm][1], a[wm][2], a[wm][3],
                                 b[g][h], b[g][2 + h]);
                }
        }
    }

    // ---------------- epilogue ------------------------------------------------
    const int tq = lid >> 2;
    const int tr = lid & 3;
    #pragma unroll
    for (int wm = 0; wm < WM; ++wm) {
        #pragma unroll
        for (int j = 0; j < 8; ++j) {
            #pragma unroll
            for (int half = 0; half < 2; ++half) {
                const int gr = m0 + wr * (WM * 16) + wm * 16 + tq + half * 8;
                const int gc = n0 + wc * 64 + j * 8 + tr * 2;
                float v0 = acc[wm][j][half * 2 + 0];
                float v1 = acc[wm][j][half * 2 + 1];
                if (EPI == EPI_PLAIN) {
                    float2 v = {v0, v1};
                    *(float2*)&O0[(size_t)gr * N + gc] = v;
                } else if (EPI == EPI_SOFTPLUS) {
                    v0 += bias[gc]; v1 += bias[gc + 1];
                    v0 = (v0 > 20.0f) ? v0 : log1pf(__expf(v0));
                    v1 = (v1 > 20.0f) ? v1 : log1pf(__expf(v1));
                    float2 v = {v0, v1};
                    *(float2*)&O0[(size_t)gr * N + gc] = v;
                } else { // EPI_XPROJ: 0..63 dtr | 64..79 Bm | 80..95 Cm | pad
                    float2 v = {v0, v1};
                    if (gc < DT_RANK)           *(float2*)&O0[(size_t)gr * DT_RANK + gc] = v;
                    else if (gc < DT_RANK + 16) *(float2*)&O1[(size_t)gr * 16 + (gc - DT_RANK)] = v;
                    else if (gc < DT_RANK + 32) *(float2*)&O2[(size_t)gr * 16 + (gc - DT_RANK - 16)] = v;
                }
            }
        }
    }
}

// ---------------- packing kernels ---------------------------------------------
// bf16 3-term A: fp32[M,K] -> bf16[M,3K] = [hi | hi | lo]  (flat 1D, float4/thread)
__global__ __launch_bounds__(256)
void packA_kernel(const float* __restrict__ in, __nv_bfloat16* __restrict__ out,
                  int K, int total4)
{
    const int idx = blockIdx.x * 256 + threadIdx.x;
    if (idx >= total4) return;
    const int kq = K >> 2;
    const int m = idx / kq;
    const int k = (idx - m * kq) * 4;
    const float4 v = *(const float4*)(in + (size_t)m * K + k);
    __nv_bfloat16 h0, h1, h2, h3, l0, l1, l2, l3;
    split_bf16(v.x, h0, l0); split_bf16(v.y, h1, l1);
    split_bf16(v.z, h2, l2); split_bf16(v.w, h3, l3);
    __nv_bfloat16* op = out + (size_t)m * 3 * K;
    __nv_bfloat162 hh01; hh01.x = h0; hh01.y = h1;
    __nv_bfloat162 hh23; hh23.x = h2; hh23.y = h3;
    __nv_bfloat162 ll01; ll01.x = l0; ll01.y = l1;
    __nv_bfloat162 ll23; ll23.x = l2; ll23.y = l3;
    *(__nv_bfloat162*)(op + k)             = hh01;
    *(__nv_bfloat162*)(op + k + 2)         = hh23;
    *(__nv_bfloat162*)(op + K + k)         = hh01;
    *(__nv_bfloat162*)(op + K + k + 2)     = hh23;
    *(__nv_bfloat162*)(op + 2 * K + k)     = ll01;
    *(__nv_bfloat162*)(op + 2 * K + k + 2) = ll23;
}

// fp16 2-term A: fp32[M,K] -> fp16[M,2K] = [hi | lo]
__global__ __launch_bounds__(256)
void packA16_kernel(const float* __restrict__ in, __half* __restrict__ out,
                    int K, int total4)
{
    const int idx = blockIdx.x * 256 + threadIdx.x;
    if (idx >= total4) return;
    const int kq = K >> 2;
    const int m = idx / kq;
    const int k = (idx - m * kq) * 4;
    const float4 v = *(const float4*)(in + (size_t)m * K + k);
    __half h0, h1, h2, h3, l0, l1, l2, l3;
    split_fp16(v.x, h0, l0); split_fp16(v.y, h1, l1);
    split_fp16(v.z, h2, l2); split_fp16(v.w, h3, l3);
    __half* op = out + (size_t)m * 2 * K;
    __half2 hh01; hh01.x = h0; hh01.y = h1;
    __half2 hh23; hh23.x = h2; hh23.y = h3;
    __half2 ll01; ll01.x = l0; ll01.y = l1;
    __half2 ll23; ll23.x = l2; ll23.y = l3;
    *(__half2*)(op + k)         = hh01;
    *(__half2*)(op + k + 2)     = hh23;
    *(__half2*)(op + K + k)     = ll01;
    *(__half2*)(op + K + k + 2) = ll23;
}

// bf16 3-term Bt: fp32[K, ldn] cols [ncol0, ncol0+Nv) -> bf16[Np, 3K] = [hi|lo|hi]
__global__ __launch_bounds__(256)
void packBt_kernel(const float* __restrict__ in, __nv_bfloat16* __restrict__ out,
                   int K, int Nv, int Np, int ldn, int ncol0)
{
    __shared__ float s[32][33];
    const int kb = blockIdx.x * 32, nb = blockIdx.y * 32;
    const int tx = threadIdx.x & 31, ty = threadIdx.x >> 5;
    #pragma unroll
    for (int r = 0; r < 32; r += 8) {
        const int k = kb + ty + r, n = nb + tx;
        s[ty + r][tx] = (k < K && n < Nv) ? in[(size_t)k * ldn + ncol0 + n] : 0.0f;
    }
    __syncthreads();
    #pragma unroll
    for (int r = 0; r < 32; r += 8) {
        const int n = nb + ty + r, k = kb + tx;
        if (n < Np && k < K) {
            const float v = s[tx][ty + r];
            __nv_bfloat16 h, lo;
            split_bf16(v, h, lo);
            __nv_bfloat16* op = out + (size_t)n * 3 * K;
            op[k] = h; op[K + k] = lo; op[2 * K + k] = h;
        }
    }
}

// fp16 dup Bt: fp32[K, ldn] cols [ncol0, ncol0+Nv) -> fp16[Np, 2K] = [hi|hi]
__global__ __launch_bounds__(256)
void packBt16_kernel(const float* __restrict__ in, __half* __restrict__ out,
                     int K, int Nv, int Np, int ldn, int ncol0)
{
    __shared__ float s[32][33];
    const int kb = blockIdx.x * 32, nb = blockIdx.y * 32;
    const int tx = threadIdx.x & 31, ty = threadIdx.x >> 5;
    #pragma unroll
    for (int r = 0; r < 32; r += 8) {
        const int k = kb + ty + r, n = nb + tx;
        s[ty + r][tx] = (k < K && n < Nv) ? in[(size_t)k * ldn + ncol0 + n] : 0.0f;
    }
    __syncthreads();
    #pragma unroll
    for (int r = 0; r < 32; r += 8) {
        const int n = nb + ty + r, k = kb + tx;
        if (n < Np && k < K) {
            const __half h = __float2half(s[tx][ty + r]);
            __half* op = out + (size_t)n * 2 * K;
            op[k] = h; op[K + k] = h;
        }
    }
}

// ---------------- causal depthwise conv (k=4) + SiLU + pack -------------------
__global__ __launch_bounds__(256)
void conv_silu_kernel(const float* __restrict__ u, const float* __restrict__ w,
                      const float* __restrict__ bias, float* __restrict__ uc,
                      __nv_bfloat16* __restrict__ uc2)
{
    constexpr int CHUNK = 16;
    int gid = blockIdx.x * blockDim.x + threadIdx.x;
    int d = gid & (D_INNER - 1);
    int rest = gid >> 11;
    int b = rest & (BATCH - 1);
    int chunk = rest >> 2;
    int l0 = chunk * CHUNK;

    const float w0 = w[d * 4 + 0], w1 = w[d * 4 + 1],
                w2 = w[d * 4 + 2], w3 = w[d * 4 + 3];
    const float bb = bias[d];

    const size_t base = ((size_t)b * SEQLEN + l0) * D_INNER + d;
    const float* up = u + base;
    float* op = uc + base;
    __nv_bfloat16* pp = uc2 + ((size_t)b * SEQLEN + l0) * 3 * D_INNER + d;

    float xm3, xm2, xm1;
    if (l0 == 0) { xm3 = 0.f; xm2 = 0.f; xm1 = 0.f; }
    else {
        xm3 = up[-3 * D_INNER];
        xm2 = up[-2 * D_INNER];
        xm1 = up[-1 * D_INNER];
    }
    #pragma unroll
    for (int i = 0; i < CHUNK; ++i) {
        float cur = up[(size_t)i * D_INNER];
        float v = fmaf(xm3, w0, fmaf(xm2, w1, fmaf(xm1, w2, fmaf(cur, w3, bb))));
        float s = v / (1.0f + __expf(-v));
        op[(size_t)i * D_INNER] = s;
        __nv_bfloat16 h, lo;
        split_bf16(s, h, lo);
        __nv_bfloat16* q = pp + (size_t)i * 3 * D_INNER;
        q[0] = h; q[D_INNER] = h; q[2 * D_INNER] = lo;
        xm3 = xm2; xm2 = xm1; xm1 = cur;
    }
}

// ---------------- selective scan (emits fp16 [hi|lo] y) -----------------------
__global__ __launch_bounds__(128)
void scan_kernel(const float* __restrict__ delta, const float* __restrict__ u,
                 const float* __restrict__ z, const float* __restrict__ Bm,
                 const float* __restrict__ Cm, const float* __restrict__ A_log,
                 const float* __restrict__ Dp, __half* __restrict__ y16)
{
    const int t = blockIdx.x * blockDim.x + threadIdx.x;
    const int sub = t & 3;
    const int ch = t >> 2;
    const int d = ch & (D_INNER - 1);
    const int b = ch >> 11;
    const int n0 = sub * 4;

    const float a0 = -__expf(A_log[d * D_STATE + n0 + 0]);
    const float a1 = -__expf(A_log[d * D_STATE + n0 + 1]);
    const float a2 = -__expf(A_log[d * D_STATE + n0 + 2]);
    const float a3 = -__expf(A_log[d * D_STATE + n0 + 3]);

    const bool fast =
        fabsf(a0 + (float)(n0 + 1)) < 1e-3f * (n0 + 1) &&
        fabsf(a1 + (float)(n0 + 2)) < 1e-3f * (n0 + 2) &&
        fabsf(a2 + (float)(n0 + 3)) < 1e-3f * (n0 + 3) &&
        fabsf(a3 + (float)(n0 + 4)) < 1e-3f * (n0 + 4);

    const size_t base = (size_t)b * SEQLEN * D_INNER + d;
    const float* dp = delta + base;
    const float* up = u + base;
    const float* zp = z + base;
    __half* yp = y16 + (size_t)b * SEQLEN * 2 * D_INNER + d;
    const float4* Bp = (const float4*)Bm + (size_t)b * SEQLEN * 4 + sub;
    const float4* Cp = (const float4*)Cm + (size_t)b * SEQLEN * 4 + sub;
    const float Dd = Dp[d];

    float h0 = 0.f, h1 = 0.f, h2 = 0.f, h3 = 0.f;

    if (fast) {
        #pragma unroll 2
        for (int l = 0; l < SEQLEN; ++l) {
            const float dt = dp[(size_t)l * D_INNER];
            const float uu = up[(size_t)l * D_INNER];
            const float4 Bv = Bp[(size_t)l * 4];
            const float4 Cv = Cp[(size_t)l * 4];
            const float e  = __expf(-dt);
            const float e2 = e * e;
            const float e4 = e2 * e2;
            const float e8 = e4 * e4;
            float m = 1.f;
            if (sub & 1) m = e4;
            if (sub & 2) m *= e8;
            const float dA0 = m * e;
            const float dA1 = dA0 * e;
            const float dA2 = dA1 * e;
            const float dA3 = dA2 * e;
            const float xv = dt * uu;
            h0 = fmaf(h0, dA0, xv * Bv.x);
            h1 = fmaf(h1, dA1, xv * Bv.y);
            h2 = fmaf(h2, dA2, xv * Bv.z);
            h3 = fmaf(h3, dA3, xv * Bv.w);
            float yv = h0 * Cv.x + h1 * Cv.y + h2 * Cv.z + h3 * Cv.w;
            yv += __shfl_xor_sync(0xffffffffu, yv, 1);
            yv += __shfl_xor_sync(0xffffffffu, yv, 2);
            if (sub == 0) {
                const float zz = zp[(size_t)l * D_INNER];
                const float sz = zz / (1.0f + __expf(-zz));
                const float yo = (yv + uu * Dd) * sz;
                __half h, lo;
                split_fp16(yo, h, lo);
                __half* q = yp + (size_t)l * 2 * D_INNER;
                q[0] = h; q[D_INNER] = lo;
            }
        }
    } else {
        #pragma unroll 2
        for (int l = 0; l < SEQLEN; ++l) {
            const float dt = dp[(size_t)l * D_INNER];
            const float uu = up[(size_t)l * D_INNER];
            const float4 Bv = Bp[(size_t)l * 4];
            const float4 Cv = Cp[(size_t)l * 4];
            const float dA0 = __expf(dt * a0);
            const float dA1 = __expf(dt * a1);
            const float dA2 = __expf(dt * a2);
            const float dA3 = __expf(dt * a3);
            const float xv = dt * uu;
            h0 = fmaf(h0, dA0, xv * Bv.x);
            h1 = fmaf(h1, dA1, xv * Bv.y);
            h2 = fmaf(h2, dA2, xv * Bv.z);
            h3 = fmaf(h3, dA3, xv * Bv.w);
            float yv = h0 * Cv.x + h1 * Cv.y + h2 * Cv.z + h3 * Cv.w;
            yv += __shfl_xor_sync(0xffffffffu, yv, 1);
            yv += __shfl_xor_sync(0xffffffffu, yv, 2);
            if (sub == 0) {
                const float zz = zp[(size_t)l * D_INNER];
                const float sz = zz / (1.0f + __expf(-zz));
                const float yo = (yv + uu * Dd) * sz;
                __half h, lo;
                split_fp16(yo, h, lo);
                __half* q = yp + (size_t)l * 2 * D_INNER;
                q[0] = h; q[D_INNER] = lo;
            }
        }
    }
}

// ---------------- launch ------------------------------------------------------
extern "C" void kernel_launch(void* const* d_in, const int* in_sizes, int n_in,
                              void* d_out, int out_size)
{
    const float* x      = (const float*)d_in[0];
    const float* W_in   = (const float*)d_in[1];
    const float* conv_w = (const float*)d_in[2];
    const float* conv_b = (const float*)d_in[3];
    const float* W_xprj = (const float*)d_in[4];
    const float* W_dt   = (const float*)d_in[5];
    const float* b_dt   = (const float*)d_in[6];
    const float* A_log  = (const float*)d_in[7];
    const float* Dp     = (const float*)d_in[8];
    const float* W_out  = (const float*)d_in[9];
    float* out = (float*)d_out;

    float *u, *z, *uc, *delta, *dtr, *Bm, *Cm;
    cudaGetSymbolAddress((void**)&u,     g_u);
    cudaGetSymbolAddress((void**)&z,     g_z);
    cudaGetSymbolAddress((void**)&uc,    g_uc);
    cudaGetSymbolAddress((void**)&delta, g_delta);
    cudaGetSymbolAddress((void**)&dtr,   g_dtr);
    cudaGetSymbolAddress((void**)&Bm,    g_Bm);
    cudaGetSymbolAddress((void**)&Cm,    g_Cm);

    __nv_bfloat16 *uc2, *Wxp2, *dtr2, *Wdt2;
    __half *x16, *Winu16, *Winz16, *y16, *Wout16;
    cudaGetSymbolAddress((void**)&uc2,    g_uc2);
    cudaGetSymbolAddress((void**)&Wxp2,   g_Wxp2);
    cudaGetSymbolAddress((void**)&dtr2,   g_dtr2);
    cudaGetSymbolAddress((void**)&Wdt2,   g_Wdt2);
    cudaGetSymbolAddress((void**)&x16,    g_x16);
    cudaGetSymbolAddress((void**)&Winu16, g_Winu16);
    cudaGetSymbolAddress((void**)&Winz16, g_Winz16);
    cudaGetSymbolAddress((void**)&y16,    g_y16);
    cudaGetSymbolAddress((void**)&Wout16, g_Wout16);

    const int SM2 = GEMM_SMEM_WM(2);   // 98304
    const int SM1 = GEMM_SMEM_WM(1);   // 73728

    cudaFuncSetAttribute(gemm_tc<EPI_PLAIN, 1, 2>,    cudaFuncAttributeMaxDynamicSharedMemorySize, SM2);
    cudaFuncSetAttribute(gemm_tc<EPI_SOFTPLUS, 0, 2>, cudaFuncAttributeMaxDynamicSharedMemorySize, SM2);
    cudaFuncSetAttribute(gemm_tc<EPI_XPROJ, 0, 1>,    cudaFuncAttributeMaxDynamicSharedMemorySize, SM1);

    // weight packs up front (independent of activations)
    packBt16_kernel<<<dim3(D_MODEL / 32, D_INNER / 32), 256>>>(
        W_in, Winu16, D_MODEL, D_INNER, D_INNER, 2 * D_INNER, 0);         // u half [hi|hi]
    packBt16_kernel<<<dim3(D_MODEL / 32, D_INNER / 32), 256>>>(
        W_in, Winz16, D_MODEL, D_INNER, D_INNER, 2 * D_INNER, D_INNER);   // z half [hi|hi]
    packBt_kernel<<<dim3(D_INNER / 32, 128 / 32), 256>>>(
        W_xprj, Wxp2, D_INNER, DT_RANK + 2 * D_STATE, 128, DT_RANK + 2 * D_STATE, 0);
    packBt_kernel<<<dim3((DT_RANK + 31) / 32, D_INNER / 32), 256>>>(
        W_dt, Wdt2, DT_RANK, D_INNER, D_INNER, D_INNER, 0);
    packBt16_kernel<<<dim3(D_INNER / 32, D_MODEL / 32), 256>>>(
        W_out, Wout16, D_INNER, D_MODEL, D_MODEL, D_MODEL, 0);

    // activation pack for G1 (single fp16 [hi|lo] pack serves BOTH halves)
    {
        const int total4 = ROWS * (D_MODEL / 4);
        packA16_kernel<<<(total4 + 255) / 256, 256>>>(x, x16, D_MODEL, total4);
    }

    // ---- G1u: u = x @ W_in[:, :2048]  (fp16 2-term: Kp=2K) -----------------
    gemm_tc<EPI_PLAIN, 1, 2><<<dim3(D_INNER / GBN, ROWS / 128), 256, SM2>>>(
        (const uint8_t*)x16, (const uint8_t*)Winu16,
        2 * D_MODEL, 2 * D_MODEL, 2 * D_MODEL, D_INNER,
        u, nullptr, nullptr, nullptr);
    // ---- G1z: z = x @ W_in[:, 2048:]  (fp16 1-term: hi halves, Kp=K) -------
    gemm_tc<EPI_PLAIN, 1, 2><<<dim3(D_INNER / GBN, ROWS / 128), 256, SM2>>>(
        (const uint8_t*)x16, (const uint8_t*)Winz16,
        2 * D_MODEL, 2 * D_MODEL, D_MODEL, D_INNER,
        z, nullptr, nullptr, nullptr);

    // ---- conv + silu + pack uc2 --------------------------------------------
    conv_silu_kernel<<<(BATCH * D_INNER * (SEQLEN / 16)) / 256, 256>>>(
        u, conv_w, conv_b, uc, uc2);

    // ---- G2: proj = uc @ W_xproj -> dtr|Bm|Cm (bf16 3-term, BM=64) ---------
    gemm_tc<EPI_XPROJ, 0, 1><<<dim3(1, ROWS / 64), 256, SM1>>>(
        (const uint8_t*)uc2, (const uint8_t*)Wxp2,
        3 * D_INNER, 3 * D_INNER, 3 * D_INNER, 128,
        dtr, Bm, Cm, nullptr);

    // ---- G3: delta = softplus(dtr @ W_dt + b_dt) (bf16 3-term) -------------
    {
        const int total4 = ROWS * (DT_RANK / 4);
        packA_kernel<<<(total4 + 255) / 256, 256>>>(dtr, dtr2, DT_RANK, total4);
    }
    gemm_tc<EPI_SOFTPLUS, 0, 2><<<dim3(D_INNER / GBN, ROWS / 128), 256, SM2>>>(
        (const uint8_t*)dtr2, (const uint8_t*)Wdt2,
        3 * DT_RANK, 3 * DT_RANK, 3 * DT_RANK, D_INNER,
        delta, nullptr, nullptr, b_dt);

    // ---- scan + gating -> fp16 [hi|lo] y -----------------------------------
    scan_kernel<<<(ROWS * 4) / 128, 128>>>(delta, uc, z, Bm, Cm, A_log, Dp, y16);

    // ---- G5: out = y @ W_out (fp16 1-term: hi halves, Kp=K) ----------------
    gemm_tc<EPI_PLAIN, 1, 2><<<dim3(D_MODEL / GBN, ROWS / 128), 256, SM2>>>(
        (const uint8_t*)y16, (const uint8_t*)Wout16,
        2 * D_INNER, 2 * D_INNER, D_INNER, D_MODEL,
        out, nullptr, nullptr, nullptr);
}

// round 12
// speedup vs baseline: 1.2920x; 1.0529x over previous
#include <cuda_runtime.h>
#include <cuda_bf16.h>
#include <cuda_fp16.h>
#include <cstdint>
#include <math.h>

#define D_MODEL 1024
#define D_STATE 16
#define D_INNER 2048
#define DT_RANK 64
#define BATCH   4
#define SEQLEN  2048
#define ROWS    (BATCH * SEQLEN)   // 8192

// ---------------- device scratch (allocation-free rule) -----------------------
__device__ __align__(16) float g_u[ROWS * D_INNER];
__device__ __align__(16) float g_z[ROWS * D_INNER];
__device__ __align__(16) float g_uc[ROWS * D_INNER];
__device__ __align__(16) float g_delta[ROWS * D_INNER];
__device__ __align__(16) float g_dtr[ROWS * DT_RANK];
__device__ __align__(16) float g_Bm[ROWS * D_STATE];
__device__ __align__(16) float g_Cm[ROWS * D_STATE];

// bf16 3-term operands (A: [hi|hi|lo], Bt: [hi|lo|hi]) — G3 (exp-sensitive)
__device__ __align__(16) __nv_bfloat16 g_dtr2[ROWS * 3 * DT_RANK];       // G3 A
__device__ __align__(16) __nv_bfloat16 g_Wdt2[D_INNER * 3 * DT_RANK];    // G3 B

// fp16 operands
__device__ __align__(16) __half g_x16  [ROWS * D_MODEL];                 // G1 A (hi only)
__device__ __align__(16) __half g_Win16[(2 * D_INNER) * D_MODEL];        // G1 B (hi, full 4096 cols)
__device__ __align__(16) __half g_uc16 [ROWS * 2 * D_INNER];             // G2 A [hi|lo]
__device__ __align__(16) __half g_Wxp16[128 * 2 * D_INNER];              // G2 B [hi|hi]
__device__ __align__(16) __half g_y16  [ROWS * D_INNER];                 // G5 A (hi only)
__device__ __align__(16) __half g_Wout16[D_MODEL * D_INNER];             // G5 B (hi only)

// ---------------- helpers -----------------------------------------------------
__device__ __forceinline__ uint32_t smem_u32(const void* p) {
    uint32_t a;
    asm("{ .reg .u64 t; cvta.to.shared.u64 t, %1; cvt.u32.u64 %0, t; }" : "=r"(a) : "l"(p));
    return a;
}
__device__ __forceinline__ void cp16(uint32_t saddr, const void* gaddr) {
    asm volatile("cp.async.cg.shared.global [%0], [%1], 16;" :: "r"(saddr), "l"(gaddr));
}
#define SWZ(o) ((o) ^ ((((uint32_t)(o)) >> 3) & 0x70))

__device__ __forceinline__ void ldm_x4(uint32_t& r0, uint32_t& r1, uint32_t& r2, uint32_t& r3,
                                       uint32_t addr) {
    asm volatile("ldmatrix.sync.aligned.m8n8.x4.shared.b16 {%0,%1,%2,%3}, [%4];"
                 : "=r"(r0), "=r"(r1), "=r"(r2), "=r"(r3) : "r"(addr));
}
__device__ __forceinline__ void mma_bf16(float& c0, float& c1, float& c2, float& c3,
                                         uint32_t a0, uint32_t a1, uint32_t a2, uint32_t a3,
                                         uint32_t b0, uint32_t b1) {
    asm volatile("mma.sync.aligned.m16n8k16.row.col.f32.bf16.bf16.f32 "
                 "{%0,%1,%2,%3}, {%4,%5,%6,%7}, {%8,%9}, {%0,%1,%2,%3};"
                 : "+f"(c0), "+f"(c1), "+f"(c2), "+f"(c3)
                 : "r"(a0), "r"(a1), "r"(a2), "r"(a3), "r"(b0), "r"(b1));
}
__device__ __forceinline__ void mma_fp16(float& c0, float& c1, float& c2, float& c3,
                                         uint32_t a0, uint32_t a1, uint32_t a2, uint32_t a3,
                                         uint32_t b0, uint32_t b1) {
    asm volatile("mma.sync.aligned.m16n8k16.row.col.f32.f16.f16.f32 "
                 "{%0,%1,%2,%3}, {%4,%5,%6,%7}, {%8,%9}, {%0,%1,%2,%3};"
                 : "+f"(c0), "+f"(c1), "+f"(c2), "+f"(c3)
                 : "r"(a0), "r"(a1), "r"(a2), "r"(a3), "r"(b0), "r"(b1));
}
__device__ __forceinline__ void split_bf16(float v, __nv_bfloat16& h, __nv_bfloat16& l) {
    h = __float2bfloat16(v);
    l = __float2bfloat16(v - __bfloat162float(h));
}
__device__ __forceinline__ void split_fp16(float v, __half& h, __half& l) {
    h = __float2half(v);
    l = __float2half(v - __half2float(h));
}

// ---------------- mma.sync GEMM (bf16 or fp16, strided operands) ---------------
// C[M,N] = A[M,Kp] * Bt[N,Kp]^T with row strides lda/ldb (elements), fp32 accum.
// BM = WM*64, BN=128, BK=64 (128B rows, xor-swizzled), 3-stage cp.async pipeline,
// 256 threads = 8 warps in 4(m) x 2(n), warp tile (WM*16) x 64.
enum { EPI_PLAIN = 0, EPI_SPLIT = 1, EPI_SOFTPLUS = 2, EPI_XPROJ = 3 };

#define GBN 128
#define GBK 64
#define GSTAGES 3
#define GTILEB_B (GBN * GBK * 2)                 // 16384 bytes (B tile)
#define GEMM_SMEM_WM(WM) (GSTAGES * ((WM) * 64 * GBK * 2 + GTILEB_B))
// WM=2: 98304, WM=1: 73728

template <int EPI, int FP16, int WM>
__global__ __launch_bounds__(256, 2)
void gemm_tc(const uint8_t* __restrict__ A, const uint8_t* __restrict__ Bt,
             int lda, int ldb, int Kp, int N,
             float* __restrict__ O0, float* __restrict__ O1, float* __restrict__ O2,
             const float* __restrict__ bias)
{
    constexpr int BM = WM * 64;
    constexpr int GTILEA_B = BM * GBK * 2;
    constexpr int GSTAGE_B = GTILEA_B + GTILEB_B;

    extern __shared__ char smem[];
    const uint32_t sb = smem_u32(smem);
    const int tid = threadIdx.x;
    const int wid = tid >> 5, lid = tid & 31;
    const int wr = wid & 3;
    const int wc = wid >> 2;
    const int m0 = blockIdx.y * BM;
    const int n0 = blockIdx.x * GBN;
    const int chunks = Kp / GBK;

    const uint8_t* Ap = A + (size_t)m0 * lda * 2;
    const uint8_t* Bp = Bt + (size_t)n0 * ldb * 2;

    const int ldrow = tid >> 3;
    const int ldch  = tid & 7;

    auto load_stage = [&](int c) {
        const int s = c % GSTAGES;
        const uint32_t sa = sb + s * GSTAGE_B;
        const uint32_t sB = sa + GTILEA_B;
        const size_t k0b = (size_t)c * GBK * 2;
        #pragma unroll
        for (int j = 0; j < BM / 32; ++j) {
            const int r = ldrow + j * 32;
            const uint32_t so = SWZ(r * 128 + ldch * 16);
            cp16(sa + so, Ap + (size_t)r * lda * 2 + k0b + ldch * 16);
        }
        #pragma unroll
        for (int j = 0; j < 4; ++j) {
            const int r = ldrow + j * 32;
            const uint32_t so = SWZ(r * 128 + ldch * 16);
            cp16(sB + so, Bp + (size_t)r * ldb * 2 + k0b + ldch * 16);
        }
        asm volatile("cp.async.commit_group;" ::: "memory");
    };

    const int pre = (chunks < GSTAGES - 1) ? chunks : (GSTAGES - 1);
    for (int c = 0; c < pre; ++c) load_stage(c);

    float acc[WM][8][4];
    #pragma unroll
    for (int i = 0; i < WM; ++i)
        #pragma unroll
        for (int j = 0; j < 8; ++j)
            #pragma unroll
            for (int k = 0; k < 4; ++k) acc[i][j][k] = 0.f;

    const int lrow = lid & 15;
    const int lhalf = lid >> 4;

    for (int c = 0; c < chunks; ++c) {
        const int remaining = chunks - 1 - c;
        if (remaining >= 1) asm volatile("cp.async.wait_group 1;" ::: "memory");
        else                asm volatile("cp.async.wait_group 0;" ::: "memory");
        __syncthreads();

        if (c + GSTAGES - 1 < chunks) load_stage(c + GSTAGES - 1);

        const int s = c % GSTAGES;
        const uint32_t sa = sb + s * GSTAGE_B;
        const uint32_t sB = sa + GTILEA_B;

        #pragma unroll
        for (int kk = 0; kk < 4; ++kk) {
            uint32_t a[WM][4];
            #pragma unroll
            for (int wm = 0; wm < WM; ++wm) {
                const int row = wr * (WM * 16) + wm * 16 + lrow;
                const uint32_t off = SWZ(row * 128 + (kk * 2 + lhalf) * 16);
                ldm_x4(a[wm][0], a[wm][1], a[wm][2], a[wm][3], sa + off);
            }
            uint32_t b[4][4];
            #pragma unroll
            for (int g = 0; g < 4; ++g) {
                const int row = wc * 64 + g * 16 + lrow;
                const uint32_t off = SWZ(row * 128 + (kk * 2 + lhalf) * 16);
                ldm_x4(b[g][0], b[g][1], b[g][2], b[g][3], sB + off);
            }
            #pragma unroll
            for (int wm = 0; wm < WM; ++wm)
                #pragma unroll
                for (int j = 0; j < 8; ++j) {
                    const int g = j >> 1, h = j & 1;
                    if (FP16)
                        mma_fp16(acc[wm][j][0], acc[wm][j][1], acc[wm][j][2], acc[wm][j][3],
                                 a[wm][0], a[wm][1], a[wm][2], a[wm][3],
                                 b[g][h], b[g][2 + h]);
                    else
                        mma_bf16(acc[wm][j][0], acc[wm][j][1], acc[wm][j][2], acc[wm][j][3],
                                 a[wm][0], a[wm][1], a[wm][2], a[wm][3],
                                 b[g][h], b[g][2 + h]);
                }
        }
    }

    // ---------------- epilogue ------------------------------------------------
    const int tq = lid >> 2;
    const int tr = lid & 3;
    const int H = N >> 1;
    #pragma unroll
    for (int wm = 0; wm < WM; ++wm) {
        #pragma unroll
        for (int j = 0; j < 8; ++j) {
            #pragma unroll
            for (int half = 0; half < 2; ++half) {
                const int gr = m0 + wr * (WM * 16) + wm * 16 + tq + half * 8;
                const int gc = n0 + wc * 64 + j * 8 + tr * 2;
                float v0 = acc[wm][j][half * 2 + 0];
                float v1 = acc[wm][j][half * 2 + 1];
                if (EPI == EPI_PLAIN) {
                    float2 v = {v0, v1};
                    *(float2*)&O0[(size_t)gr * N + gc] = v;
                } else if (EPI == EPI_SPLIT) {
                    float2 v = {v0, v1};
                    if (gc < H) *(float2*)&O0[(size_t)gr * H + gc] = v;
                    else        *(float2*)&O1[(size_t)gr * H + (gc - H)] = v;
                } else if (EPI == EPI_SOFTPLUS) {
                    v0 += bias[gc]; v1 += bias[gc + 1];
                    v0 = (v0 > 20.0f) ? v0 : log1pf(__expf(v0));
                    v1 = (v1 > 20.0f) ? v1 : log1pf(__expf(v1));
                    float2 v = {v0, v1};
                    *(float2*)&O0[(size_t)gr * N + gc] = v;
                } else { // EPI_XPROJ: 0..63 dtr | 64..79 Bm | 80..95 Cm | pad
                    float2 v = {v0, v1};
                    if (gc < DT_RANK)           *(float2*)&O0[(size_t)gr * DT_RANK + gc] = v;
                    else if (gc < DT_RANK + 16) *(float2*)&O1[(size_t)gr * 16 + (gc - DT_RANK)] = v;
                    else if (gc < DT_RANK + 32) *(float2*)&O2[(size_t)gr * 16 + (gc - DT_RANK - 16)] = v;
                }
            }
        }
    }
}

// ---------------- packing kernels ---------------------------------------------
// bf16 3-term A: fp32[M,K] -> bf16[M,3K] = [hi | hi | lo]
__global__ __launch_bounds__(256)
void packA_kernel(const float* __restrict__ in, __nv_bfloat16* __restrict__ out,
                  int K, int total4)
{
    const int idx = blockIdx.x * 256 + threadIdx.x;
    if (idx >= total4) return;
    const int kq = K >> 2;
    const int m = idx / kq;
    const int k = (idx - m * kq) * 4;
    const float4 v = *(const float4*)(in + (size_t)m * K + k);
    __nv_bfloat16 h0, h1, h2, h3, l0, l1, l2, l3;
    split_bf16(v.x, h0, l0); split_bf16(v.y, h1, l1);
    split_bf16(v.z, h2, l2); split_bf16(v.w, h3, l3);
    __nv_bfloat16* op = out + (size_t)m * 3 * K;
    __nv_bfloat162 hh01; hh01.x = h0; hh01.y = h1;
    __nv_bfloat162 hh23; hh23.x = h2; hh23.y = h3;
    __nv_bfloat162 ll01; ll01.x = l0; ll01.y = l1;
    __nv_bfloat162 ll23; ll23.x = l2; ll23.y = l3;
    *(__nv_bfloat162*)(op + k)             = hh01;
    *(__nv_bfloat162*)(op + k + 2)         = hh23;
    *(__nv_bfloat162*)(op + K + k)         = hh01;
    *(__nv_bfloat162*)(op + K + k + 2)     = hh23;
    *(__nv_bfloat162*)(op + 2 * K + k)     = ll01;
    *(__nv_bfloat162*)(op + 2 * K + k + 2) = ll23;
}

// fp16 2-term A: fp32[M,K] -> fp16[M,2K] = [hi | lo]
__global__ __launch_bounds__(256)
void packA16_kernel(const float* __restrict__ in, __half* __restrict__ out,
                    int K, int total4)
{
    const int idx = blockIdx.x * 256 + threadIdx.x;
    if (idx >= total4) return;
    const int kq = K >> 2;
    const int m = idx / kq;
    const int k = (idx - m * kq) * 4;
    const float4 v = *(const float4*)(in + (size_t)m * K + k);
    __half h0, h1, h2, h3, l0, l1, l2, l3;
    split_fp16(v.x, h0, l0); split_fp16(v.y, h1, l1);
    split_fp16(v.z, h2, l2); split_fp16(v.w, h3, l3);
    __half* op = out + (size_t)m * 2 * K;
    __half2 hh01; hh01.x = h0; hh01.y = h1;
    __half2 hh23; hh23.x = h2; hh23.y = h3;
    __half2 ll01; ll01.x = l0; ll01.y = l1;
    __half2 ll23; ll23.x = l2; ll23.y = l3;
    *(__half2*)(op + k)         = hh01;
    *(__half2*)(op + k + 2)     = hh23;
    *(__half2*)(op + K + k)     = ll01;
    *(__half2*)(op + K + k + 2) = ll23;
}

// fp16 1-term A: fp32[M,K] -> fp16[M,K] (plain hi)
__global__ __launch_bounds__(256)
void packA16_1t_kernel(const float* __restrict__ in, __half* __restrict__ out,
                       int total4)
{
    const int idx = blockIdx.x * 256 + threadIdx.x;
    if (idx >= total4) return;
    const float4 v = *(const float4*)(in + (size_t)idx * 4);
    __half2 a, b;
    a.x = __float2half(v.x); a.y = __float2half(v.y);
    b.x = __float2half(v.z); b.y = __float2half(v.w);
    *(__half2*)(out + (size_t)idx * 4)     = a;
    *(__half2*)(out + (size_t)idx * 4 + 2) = b;
}

// bf16 3-term Bt: fp32[K, ldn] cols [ncol0, ncol0+Nv) -> bf16[Np, 3K] = [hi|lo|hi]
__global__ __launch_bounds__(256)
void packBt_kernel(const float* __restrict__ in, __nv_bfloat16* __restrict__ out,
                   int K, int Nv, int Np, int ldn, int ncol0)
{
    __shared__ float s[32][33];
    const int kb = blockIdx.x * 32, nb = blockIdx.y * 32;
    const int tx = threadIdx.x & 31, ty = threadIdx.x >> 5;
    #pragma unroll
    for (int r = 0; r < 32; r += 8) {
        const int k = kb + ty + r, n = nb + tx;
        s[ty + r][tx] = (k < K && n < Nv) ? in[(size_t)k * ldn + ncol0 + n] : 0.0f;
    }
    __syncthreads();
    #pragma unroll
    for (int r = 0; r < 32; r += 8) {
        const int n = nb + ty + r, k = kb + tx;
        if (n < Np && k < K) {
            const float v = s[tx][ty + r];
            __nv_bfloat16 h, lo;
            split_bf16(v, h, lo);
            __nv_bfloat16* op = out + (size_t)n * 3 * K;
            op[k] = h; op[K + k] = lo; op[2 * K + k] = h;
        }
    }
}

// fp16 dup Bt: fp32[K, ldn] cols [ncol0, ncol0+Nv) -> fp16[Np, 2K] = [hi|hi]
__global__ __launch_bounds__(256)
void packBt16_kernel(const float* __restrict__ in, __half* __restrict__ out,
                     int K, int Nv, int Np, int ldn, int ncol0)
{
    __shared__ float s[32][33];
    const int kb = blockIdx.x * 32, nb = blockIdx.y * 32;
    const int tx = threadIdx.x & 31, ty = threadIdx.x >> 5;
    #pragma unroll
    for (int r = 0; r < 32; r += 8) {
        const int k = kb + ty + r, n = nb + tx;
        s[ty + r][tx] = (k < K && n < Nv) ? in[(size_t)k * ldn + ncol0 + n] : 0.0f;
    }
    __syncthreads();
    #pragma unroll
    for (int r = 0; r < 32; r += 8) {
        const int n = nb + ty + r, k = kb + tx;
        if (n < Np && k < K) {
            const __half h = __float2half(s[tx][ty + r]);
            __half* op = out + (size_t)n * 2 * K;
            op[k] = h; op[K + k] = h;
        }
    }
}

// fp16 1-term Bt: fp32[K, ldn] cols [ncol0, ncol0+Nv) -> fp16[Np, K] (plain hi)
__global__ __launch_bounds__(256)
void packBt16_1t_kernel(const float* __restrict__ in, __half* __restrict__ out,
                        int K, int Nv, int Np, int ldn, int ncol0)
{
    __shared__ float s[32][33];
    const int kb = blockIdx.x * 32, nb = blockIdx.y * 32;
    const int tx = threadIdx.x & 31, ty = threadIdx.x >> 5;
    #pragma unroll
    for (int r = 0; r < 32; r += 8) {
        const int k = kb + ty + r, n = nb + tx;
        s[ty + r][tx] = (k < K && n < Nv) ? in[(size_t)k * ldn + ncol0 + n] : 0.0f;
    }
    __syncthreads();
    #pragma unroll
    for (int r = 0; r < 32; r += 8) {
        const int n = nb + ty + r, k = kb + tx;
        if (n < Np && k < K)
            out[(size_t)n * K + k] = __float2half(s[tx][ty + r]);
    }
}

// ---------------- causal depthwise conv (k=4) + SiLU + fp16 2-term pack -------
__global__ __launch_bounds__(256)
void conv_silu_kernel(const float* __restrict__ u, const float* __restrict__ w,
                      const float* __restrict__ bias, float* __restrict__ uc,
                      __half* __restrict__ uc16)
{
    constexpr int CHUNK = 16;
    int gid = blockIdx.x * blockDim.x + threadIdx.x;
    int d = gid & (D_INNER - 1);
    int rest = gid >> 11;
    int b = rest & (BATCH - 1);
    int chunk = rest >> 2;
    int l0 = chunk * CHUNK;

    const float w0 = w[d * 4 + 0], w1 = w[d * 4 + 1],
                w2 = w[d * 4 + 2], w3 = w[d * 4 + 3];
    const float bb = bias[d];

    const size_t base = ((size_t)b * SEQLEN + l0) * D_INNER + d;
    const float* up = u + base;
    float* op = uc + base;
    __half* pp = uc16 + ((size_t)b * SEQLEN + l0) * 2 * D_INNER + d;

    float xm3, xm2, xm1;
    if (l0 == 0) { xm3 = 0.f; xm2 = 0.f; xm1 = 0.f; }
    else {
        xm3 = up[-3 * D_INNER];
        xm2 = up[-2 * D_INNER];
        xm1 = up[-1 * D_INNER];
    }
    #pragma unroll
    for (int i = 0; i < CHUNK; ++i) {
        float cur = up[(size_t)i * D_INNER];
        float v = fmaf(xm3, w0, fmaf(xm2, w1, fmaf(xm1, w2, fmaf(cur, w3, bb))));
        float s = v / (1.0f + __expf(-v));
        op[(size_t)i * D_INNER] = s;
        __half h, lo;
        split_fp16(s, h, lo);
        __half* q = pp + (size_t)i * 2 * D_INNER;
        q[0] = h; q[D_INNER] = lo;
        xm3 = xm2; xm2 = xm1; xm1 = cur;
    }
}

// ---------------- selective scan (emits fp16 hi y) ----------------------------
__global__ __launch_bounds__(128)
void scan_kernel(const float* __restrict__ delta, const float* __restrict__ u,
                 const float* __restrict__ z, const float* __restrict__ Bm,
                 const float* __restrict__ Cm, const float* __restrict__ A_log,
                 const float* __restrict__ Dp, __half* __restrict__ y16)
{
    const int t = blockIdx.x * blockDim.x + threadIdx.x;
    const int sub = t & 3;
    const int ch = t >> 2;
    const int d = ch & (D_INNER - 1);
    const int b = ch >> 11;
    const int n0 = sub * 4;

    const float a0 = -__expf(A_log[d * D_STATE + n0 + 0]);
    const float a1 = -__expf(A_log[d * D_STATE + n0 + 1]);
    const float a2 = -__expf(A_log[d * D_STATE + n0 + 2]);
    const float a3 = -__expf(A_log[d * D_STATE + n0 + 3]);

    const bool fast =
        fabsf(a0 + (float)(n0 + 1)) < 1e-3f * (n0 + 1) &&
        fabsf(a1 + (float)(n0 + 2)) < 1e-3f * (n0 + 2) &&
        fabsf(a2 + (float)(n0 + 3)) < 1e-3f * (n0 + 3) &&
        fabsf(a3 + (float)(n0 + 4)) < 1e-3f * (n0 + 4);

    const size_t base = (size_t)b * SEQLEN * D_INNER + d;
    const float* dp = delta + base;
    const float* up = u + base;
    const float* zp = z + base;
    __half* yp = y16 + base;
    const float4* Bp = (const float4*)Bm + (size_t)b * SEQLEN * 4 + sub;
    const float4* Cp = (const float4*)Cm + (size_t)b * SEQLEN * 4 + sub;
    const float Dd = Dp[d];

    float h0 = 0.f, h1 = 0.f, h2 = 0.f, h3 = 0.f;

    if (fast) {
        #pragma unroll 2
        for (int l = 0; l < SEQLEN; ++l) {
            const float dt = dp[(size_t)l * D_INNER];
            const float uu = up[(size_t)l * D_INNER];
            const float4 Bv = Bp[(size_t)l * 4];
            const float4 Cv = Cp[(size_t)l * 4];
            const float e  = __expf(-dt);
            const float e2 = e * e;
            const float e4 = e2 * e2;
            const float e8 = e4 * e4;
            float m = 1.f;
            if (sub & 1) m = e4;
            if (sub & 2) m *= e8;
            const float dA0 = m * e;
            const float dA1 = dA0 * e;
            const float dA2 = dA1 * e;
            const float dA3 = dA2 * e;
            const float xv = dt * uu;
            h0 = fmaf(h0, dA0, xv * Bv.x);
            h1 = fmaf(h1, dA1, xv * Bv.y);
            h2 = fmaf(h2, dA2, xv * Bv.z);
            h3 = fmaf(h3, dA3, xv * Bv.w);
            float yv = h0 * Cv.x + h1 * Cv.y + h2 * Cv.z + h3 * Cv.w;
            yv += __shfl_xor_sync(0xffffffffu, yv, 1);
            yv += __shfl_xor_sync(0xffffffffu, yv, 2);
            if (sub == 0) {
                const float zz = zp[(size_t)l * D_INNER];
                const float sz = zz / (1.0f + __expf(-zz));
                yp[(size_t)l * D_INNER] = __float2half((yv + uu * Dd) * sz);
            }
        }
    } else {
        #pragma unroll 2
        for (int l = 0; l < SEQLEN; ++l) {
            const float dt = dp[(size_t)l * D_INNER];
            const float uu = up[(size_t)l * D_INNER];
            const float4 Bv = Bp[(size_t)l * 4];
            const float4 Cv = Cp[(size_t)l * 4];
            const float dA0 = __expf(dt * a0);
            const float dA1 = __expf(dt * a1);
            const float dA2 = __expf(dt * a2);
            const float dA3 = __expf(dt * a3);
            const float xv = dt * uu;
            h0 = fmaf(h0, dA0, xv * Bv.x);
            h1 = fmaf(h1, dA1, xv * Bv.y);
            h2 = fmaf(h2, dA2, xv * Bv.z);
            h3 = fmaf(h3, dA3, xv * Bv.w);
            float yv = h0 * Cv.x + h1 * Cv.y + h2 * Cv.z + h3 * Cv.w;
            yv += __shfl_xor_sync(0xffffffffu, yv, 1);
            yv += __shfl_xor_sync(0xffffffffu, yv, 2);
            if (sub == 0) {
                const float zz = zp[(size_t)l * D_INNER];
                const float sz = zz / (1.0f + __expf(-zz));
                yp[(size_t)l * D_INNER] = __float2half((yv + uu * Dd) * sz);
            }
        }
    }
}

// ---------------- launch ------------------------------------------------------
extern "C" void kernel_launch(void* const* d_in, const int* in_sizes, int n_in,
                              void* d_out, int out_size)
{
    const float* x      = (const float*)d_in[0];
    const float* W_in   = (const float*)d_in[1];
    const float* conv_w = (const float*)d_in[2];
    const float* conv_b = (const float*)d_in[3];
    const float* W_xprj = (const float*)d_in[4];
    const float* W_dt   = (const float*)d_in[5];
    const float* b_dt   = (const float*)d_in[6];
    const float* A_log  = (const float*)d_in[7];
    const float* Dp     = (const float*)d_in[8];
    const float* W_out  = (const float*)d_in[9];
    float* out = (float*)d_out;

    float *u, *z, *uc, *delta, *dtr, *Bm, *Cm;
    cudaGetSymbolAddress((void**)&u,     g_u);
    cudaGetSymbolAddress((void**)&z,     g_z);
    cudaGetSymbolAddress((void**)&uc,    g_uc);
    cudaGetSymbolAddress((void**)&delta, g_delta);
    cudaGetSymbolAddress((void**)&dtr,   g_dtr);
    cudaGetSymbolAddress((void**)&Bm,    g_Bm);
    cudaGetSymbolAddress((void**)&Cm,    g_Cm);

    __nv_bfloat16 *dtr2, *Wdt2;
    __half *x16, *Win16, *uc16, *Wxp16, *y16, *Wout16;
    cudaGetSymbolAddress((void**)&dtr2,   g_dtr2);
    cudaGetSymbolAddress((void**)&Wdt2,   g_Wdt2);
    cudaGetSymbolAddress((void**)&x16,    g_x16);
    cudaGetSymbolAddress((void**)&Win16,  g_Win16);
    cudaGetSymbolAddress((void**)&uc16,   g_uc16);
    cudaGetSymbolAddress((void**)&Wxp16,  g_Wxp16);
    cudaGetSymbolAddress((void**)&y16,    g_y16);
    cudaGetSymbolAddress((void**)&Wout16, g_Wout16);

    const int SM2 = GEMM_SMEM_WM(2);   // 98304
    const int SM1 = GEMM_SMEM_WM(1);   // 73728

    cudaFuncSetAttribute(gemm_tc<EPI_SPLIT, 1, 2>,    cudaFuncAttributeMaxDynamicSharedMemorySize, SM2);
    cudaFuncSetAttribute(gemm_tc<EPI_PLAIN, 1, 2>,    cudaFuncAttributeMaxDynamicSharedMemorySize, SM2);
    cudaFuncSetAttribute(gemm_tc<EPI_SOFTPLUS, 0, 2>, cudaFuncAttributeMaxDynamicSharedMemorySize, SM2);
    cudaFuncSetAttribute(gemm_tc<EPI_XPROJ, 1, 1>,    cudaFuncAttributeMaxDynamicSharedMemorySize, SM1);

    // weight packs up front (independent of activations)
    packBt16_1t_kernel<<<dim3(D_MODEL / 32, (2 * D_INNER) / 32), 256>>>(
        W_in, Win16, D_MODEL, 2 * D_INNER, 2 * D_INNER, 2 * D_INNER, 0);  // full [4096,1024] hi
    packBt16_kernel<<<dim3(D_INNER / 32, 128 / 32), 256>>>(
        W_xprj, Wxp16, D_INNER, DT_RANK + 2 * D_STATE, 128, DT_RANK + 2 * D_STATE, 0);
    packBt_kernel<<<dim3((DT_RANK + 31) / 32, D_INNER / 32), 256>>>(
        W_dt, Wdt2, DT_RANK, D_INNER, D_INNER, D_INNER, 0);
    packBt16_1t_kernel<<<dim3(D_INNER / 32, D_MODEL / 32), 256>>>(
        W_out, Wout16, D_INNER, D_MODEL, D_MODEL, D_MODEL, 0);

    // activation pack for G1 (plain fp16 hi)
    packA16_1t_kernel<<<(ROWS * D_MODEL / 4 + 255) / 256, 256>>>(
        x, x16, ROWS * D_MODEL / 4);

    // ---- G1 fused: [u|z] = x @ W_in  (fp16 1-term, N=4096, split epi) ------
    gemm_tc<EPI_SPLIT, 1, 2><<<dim3((2 * D_INNER) / GBN, ROWS / 128), 256, SM2>>>(
        (const uint8_t*)x16, (const uint8_t*)Win16,
        D_MODEL, D_MODEL, D_MODEL, 2 * D_INNER,
        u, z, nullptr, nullptr);

    // ---- conv + silu + fp16 [hi|lo] pack -----------------------------------
    conv_silu_kernel<<<(BATCH * D_INNER * (SEQLEN / 16)) / 256, 256>>>(
        u, conv_w, conv_b, uc, uc16);

    // ---- G2: proj = uc @ W_xproj -> dtr|Bm|Cm (fp16 2-term, BM=64) ---------
    gemm_tc<EPI_XPROJ, 1, 1><<<dim3(1, ROWS / 64), 256, SM1>>>(
        (const uint8_t*)uc16, (const uint8_t*)Wxp16,
        2 * D_INNER, 2 * D_INNER, 2 * D_INNER, 128,
        dtr, Bm, Cm, nullptr);

    // ---- G3: delta = softplus(dtr @ W_dt + b_dt) (bf16 3-term) -------------
    {
        const int total4 = ROWS * (DT_RANK / 4);
        packA_kernel<<<(total4 + 255) / 256, 256>>>(dtr, dtr2, DT_RANK, total4);
    }
    gemm_tc<EPI_SOFTPLUS, 0, 2><<<dim3(D_INNER / GBN, ROWS / 128), 256, SM2>>>(
        (const uint8_t*)dtr2, (const uint8_t*)Wdt2,
        3 * DT_RANK, 3 * DT_RANK, 3 * DT_RANK, D_INNER,
        delta, nullptr, nullptr, b_dt);

    // ---- scan + gating -> fp16 hi y ----------------------------------------
    scan_kernel<<<(ROWS * 4) / 128, 128>>>(delta, uc, z, Bm, Cm, A_log, Dp, y16);

    // ---- G5: out = y @ W_out (fp16 1-term) ---------------------------------
    gemm_tc<EPI_PLAIN, 1, 2><<<dim3(D_MODEL / GBN, ROWS / 128), 256, SM2>>>(
        (const uint8_t*)y16, (const uint8_t*)Wout16,
        D_INNER, D_INNER, D_INNER, D_MODEL,
        out, nullptr, nullptr, nullptr);
}

// round 13
// speedup vs baseline: 1.3189x; 1.0209x over previous
#include <cuda_runtime.h>
#include <cuda_bf16.h>
#include <cuda_fp16.h>
#include <cstdint>
#include <math.h>

#define D_MODEL 1024
#define D_STATE 16
#define D_INNER 2048
#define DT_RANK 64
#define BATCH   4
#define SEQLEN  2048
#define ROWS    (BATCH * SEQLEN)   // 8192

// ---------------- device scratch (allocation-free rule) -----------------------
__device__ __align__(16) float g_u[ROWS * D_INNER];
__device__ __align__(16) float g_z[ROWS * D_INNER];
__device__ __align__(16) float g_uc[ROWS * D_INNER];
__device__ __align__(16) float g_delta[ROWS * D_INNER];
__device__ __align__(16) float g_Bm[ROWS * D_STATE];
__device__ __align__(16) float g_Cm[ROWS * D_STATE];

// bf16 3-term operands (A: [hi|hi|lo], Bt: [hi|lo|hi]) — G3 (exp-sensitive)
__device__ __align__(16) __nv_bfloat16 g_dtr2[ROWS * 3 * DT_RANK];       // G3 A (written by G2 epi)
__device__ __align__(16) __nv_bfloat16 g_Wdt2[D_INNER * 3 * DT_RANK];    // G3 B

// fp16 operands (all 1-term hi except noted)
__device__ __align__(16) __half g_x16  [ROWS * D_MODEL];                 // G1 A
__device__ __align__(16) __half g_Win16[(2 * D_INNER) * D_MODEL];        // G1 B (full 4096 cols)
__device__ __align__(16) __half g_uc16 [ROWS * D_INNER];                 // G2 A (hi)
__device__ __align__(16) __half g_Wxp16[128 * D_INNER];                  // G2 B (hi)
__device__ __align__(16) __half g_y16  [ROWS * D_INNER];                 // G5 A
__device__ __align__(16) __half g_Wout16[D_MODEL * D_INNER];             // G5 B

// ---------------- helpers -----------------------------------------------------
__device__ __forceinline__ uint32_t smem_u32(const void* p) {
    uint32_t a;
    asm("{ .reg .u64 t; cvta.to.shared.u64 t, %1; cvt.u32.u64 %0, t; }" : "=r"(a) : "l"(p));
    return a;
}
__device__ __forceinline__ void cp16(uint32_t saddr, const void* gaddr) {
    asm volatile("cp.async.cg.shared.global [%0], [%1], 16;" :: "r"(saddr), "l"(gaddr));
}
#define SWZ(o) ((o) ^ ((((uint32_t)(o)) >> 3) & 0x70))

__device__ __forceinline__ void ldm_x4(uint32_t& r0, uint32_t& r1, uint32_t& r2, uint32_t& r3,
                                       uint32_t addr) {
    asm volatile("ldmatrix.sync.aligned.m8n8.x4.shared.b16 {%0,%1,%2,%3}, [%4];"
                 : "=r"(r0), "=r"(r1), "=r"(r2), "=r"(r3) : "r"(addr));
}
__device__ __forceinline__ void mma_bf16(float& c0, float& c1, float& c2, float& c3,
                                         uint32_t a0, uint32_t a1, uint32_t a2, uint32_t a3,
                                         uint32_t b0, uint32_t b1) {
    asm volatile("mma.sync.aligned.m16n8k16.row.col.f32.bf16.bf16.f32 "
                 "{%0,%1,%2,%3}, {%4,%5,%6,%7}, {%8,%9}, {%0,%1,%2,%3};"
                 : "+f"(c0), "+f"(c1), "+f"(c2), "+f"(c3)
                 : "r"(a0), "r"(a1), "r"(a2), "r"(a3), "r"(b0), "r"(b1));
}
__device__ __forceinline__ void mma_fp16(float& c0, float& c1, float& c2, float& c3,
                                         uint32_t a0, uint32_t a1, uint32_t a2, uint32_t a3,
                                         uint32_t b0, uint32_t b1) {
    asm volatile("mma.sync.aligned.m16n8k16.row.col.f32.f16.f16.f32 "
                 "{%0,%1,%2,%3}, {%4,%5,%6,%7}, {%8,%9}, {%0,%1,%2,%3};"
                 : "+f"(c0), "+f"(c1), "+f"(c2), "+f"(c3)
                 : "r"(a0), "r"(a1), "r"(a2), "r"(a3), "r"(b0), "r"(b1));
}
__device__ __forceinline__ void split_bf16(float v, __nv_bfloat16& h, __nv_bfloat16& l) {
    h = __float2bfloat16(v);
    l = __float2bfloat16(v - __bfloat162float(h));
}

// ---------------- mma.sync GEMM (bf16 or fp16, strided operands) ---------------
// C[M,N] = A[M,Kp] * Bt[N,Kp]^T with row strides lda/ldb (elements), fp32 accum.
// BM = WM*64, BN=128, BK=64 (128B rows, xor-swizzled), 3-stage cp.async pipeline,
// 256 threads = 8 warps in 4(m) x 2(n), warp tile (WM*16) x 64.
enum { EPI_PLAIN = 0, EPI_SPLIT = 1, EPI_SOFTPLUS = 2, EPI_XPROJ = 3 };

#define GBN 128
#define GBK 64
#define GSTAGES 3
#define GTILEB_B (GBN * GBK * 2)                 // 16384 bytes (B tile)
#define GEMM_SMEM_WM(WM) (GSTAGES * ((WM) * 64 * GBK * 2 + GTILEB_B))
// WM=2: 98304, WM=1: 73728

template <int EPI, int FP16, int WM>
__global__ __launch_bounds__(256, 2)
void gemm_tc(const uint8_t* __restrict__ A, const uint8_t* __restrict__ Bt,
             int lda, int ldb, int Kp, int N,
             float* __restrict__ O0, float* __restrict__ O1,
             __nv_bfloat16* __restrict__ O2,
             const float* __restrict__ bias)
{
    constexpr int BM = WM * 64;
    constexpr int GTILEA_B = BM * GBK * 2;
    constexpr int GSTAGE_B = GTILEA_B + GTILEB_B;

    extern __shared__ char smem[];
    const uint32_t sb = smem_u32(smem);
    const int tid = threadIdx.x;
    const int wid = tid >> 5, lid = tid & 31;
    const int wr = wid & 3;
    const int wc = wid >> 2;
    const int m0 = blockIdx.y * BM;
    const int n0 = blockIdx.x * GBN;
    const int chunks = Kp / GBK;

    const uint8_t* Ap = A + (size_t)m0 * lda * 2;
    const uint8_t* Bp = Bt + (size_t)n0 * ldb * 2;

    const int ldrow = tid >> 3;
    const int ldch  = tid & 7;

    auto load_stage = [&](int c) {
        const int s = c % GSTAGES;
        const uint32_t sa = sb + s * GSTAGE_B;
        const uint32_t sB = sa + GTILEA_B;
        const size_t k0b = (size_t)c * GBK * 2;
        #pragma unroll
        for (int j = 0; j < BM / 32; ++j) {
            const int r = ldrow + j * 32;
            const uint32_t so = SWZ(r * 128 + ldch * 16);
            cp16(sa + so, Ap + (size_t)r * lda * 2 + k0b + ldch * 16);
        }
        #pragma unroll
        for (int j = 0; j < 4; ++j) {
            const int r = ldrow + j * 32;
            const uint32_t so = SWZ(r * 128 + ldch * 16);
            cp16(sB + so, Bp + (size_t)r * ldb * 2 + k0b + ldch * 16);
        }
        asm volatile("cp.async.commit_group;" ::: "memory");
    };

    const int pre = (chunks < GSTAGES - 1) ? chunks : (GSTAGES - 1);
    for (int c = 0; c < pre; ++c) load_stage(c);

    float acc[WM][8][4];
    #pragma unroll
    for (int i = 0; i < WM; ++i)
        #pragma unroll
        for (int j = 0; j < 8; ++j)
            #pragma unroll
            for (int k = 0; k < 4; ++k) acc[i][j][k] = 0.f;

    const int lrow = lid & 15;
    const int lhalf = lid >> 4;

    for (int c = 0; c < chunks; ++c) {
        const int remaining = chunks - 1 - c;
        if (remaining >= 1) asm volatile("cp.async.wait_group 1;" ::: "memory");
        else                asm volatile("cp.async.wait_group 0;" ::: "memory");
        __syncthreads();

        if (c + GSTAGES - 1 < chunks) load_stage(c + GSTAGES - 1);

        const int s = c % GSTAGES;
        const uint32_t sa = sb + s * GSTAGE_B;
        const uint32_t sB = sa + GTILEA_B;

        #pragma unroll
        for (int kk = 0; kk < 4; ++kk) {
            uint32_t a[WM][4];
            #pragma unroll
            for (int wm = 0; wm < WM; ++wm) {
                const int row = wr * (WM * 16) + wm * 16 + lrow;
                const uint32_t off = SWZ(row * 128 + (kk * 2 + lhalf) * 16);
                ldm_x4(a[wm][0], a[wm][1], a[wm][2], a[wm][3], sa + off);
            }
            uint32_t b[4][4];
            #pragma unroll
            for (int g = 0; g < 4; ++g) {
                const int row = wc * 64 + g * 16 + lrow;
                const uint32_t off = SWZ(row * 128 + (kk * 2 + lhalf) * 16);
                ldm_x4(b[g][0], b[g][1], b[g][2], b[g][3], sB + off);
            }
            #pragma unroll
            for (int wm = 0; wm < WM; ++wm)
                #pragma unroll
                for (int j = 0; j < 8; ++j) {
                    const int g = j >> 1, h = j & 1;
                    if (FP16)
                        mma_fp16(acc[wm][j][0], acc[wm][j][1], acc[wm][j][2], acc[wm][j][3],
                                 a[wm][0], a[wm][1], a[wm][2], a[wm][3],
                                 b[g][h], b[g][2 + h]);
                    else
                        mma_bf16(acc[wm][j][0], acc[wm][j][1], acc[wm][j][2], acc[wm][j][3],
                                 a[wm][0], a[wm][1], a[wm][2], a[wm][3],
                                 b[g][h], b[g][2 + h]);
                }
        }
    }

    // ---------------- epilogue ------------------------------------------------
    const int tq = lid >> 2;
    const int tr = lid & 3;
    const int H = N >> 1;
    #pragma unroll
    for (int wm = 0; wm < WM; ++wm) {
        #pragma unroll
        for (int j = 0; j < 8; ++j) {
            #pragma unroll
            for (int half = 0; half < 2; ++half) {
                const int gr = m0 + wr * (WM * 16) + wm * 16 + tq + half * 8;
                const int gc = n0 + wc * 64 + j * 8 + tr * 2;
                float v0 = acc[wm][j][half * 2 + 0];
                float v1 = acc[wm][j][half * 2 + 1];
                if (EPI == EPI_PLAIN) {
                    float2 v = {v0, v1};
                    *(float2*)&O0[(size_t)gr * N + gc] = v;
                } else if (EPI == EPI_SPLIT) {
                    float2 v = {v0, v1};
                    if (gc < H) *(float2*)&O0[(size_t)gr * H + gc] = v;
                    else        *(float2*)&O1[(size_t)gr * H + (gc - H)] = v;
                } else if (EPI == EPI_SOFTPLUS) {
                    v0 += bias[gc]; v1 += bias[gc + 1];
                    v0 = (v0 > 20.0f) ? v0 : log1pf(__expf(v0));
                    v1 = (v1 > 20.0f) ? v1 : log1pf(__expf(v1));
                    float2 v = {v0, v1};
                    *(float2*)&O0[(size_t)gr * N + gc] = v;
                } else {
                    // EPI_XPROJ: cols 0..63 -> dtr2 (bf16 3-term, [M, 192])
                    //            64..79 -> Bm fp32 | 80..95 -> Cm fp32 | pad
                    if (gc < DT_RANK) {
                        __nv_bfloat16 h0, l0, h1, l1;
                        split_bf16(v0, h0, l0);
                        split_bf16(v1, h1, l1);
                        __nv_bfloat162 hh; hh.x = h0; hh.y = h1;
                        __nv_bfloat162 ll; ll.x = l0; ll.y = l1;
                        __nv_bfloat16* q = O2 + (size_t)gr * 3 * DT_RANK + gc;
                        *(__nv_bfloat162*)(q)               = hh;
                        *(__nv_bfloat162*)(q + DT_RANK)     = hh;
                        *(__nv_bfloat162*)(q + 2 * DT_RANK) = ll;
                    } else if (gc < DT_RANK + 16) {
                        float2 v = {v0, v1};
                        *(float2*)&O0[(size_t)gr * 16 + (gc - DT_RANK)] = v;
                    } else if (gc < DT_RANK + 32) {
                        float2 v = {v0, v1};
                        *(float2*)&O1[(size_t)gr * 16 + (gc - DT_RANK - 16)] = v;
                    }
                }
            }
        }
    }
}

// ---------------- packing kernels ---------------------------------------------
// bf16 3-term Bt: fp32[K, ldn] cols [ncol0, ncol0+Nv) -> bf16[Np, 3K] = [hi|lo|hi]
__global__ __launch_bounds__(256)
void packBt_kernel(const float* __restrict__ in, __nv_bfloat16* __restrict__ out,
                   int K, int Nv, int Np, int ldn, int ncol0)
{
    __shared__ float s[32][33];
    const int kb = blockIdx.x * 32, nb = blockIdx.y * 32;
    const int tx = threadIdx.x & 31, ty = threadIdx.x >> 5;
    #pragma unroll
    for (int r = 0; r < 32; r += 8) {
        const int k = kb + ty + r, n = nb + tx;
        s[ty + r][tx] = (k < K && n < Nv) ? in[(size_t)k * ldn + ncol0 + n] : 0.0f;
    }
    __syncthreads();
    #pragma unroll
    for (int r = 0; r < 32; r += 8) {
        const int n = nb + ty + r, k = kb + tx;
        if (n < Np && k < K) {
            const float v = s[tx][ty + r];
            __nv_bfloat16 h, lo;
            split_bf16(v, h, lo);
            __nv_bfloat16* op = out + (size_t)n * 3 * K;
            op[k] = h; op[K + k] = lo; op[2 * K + k] = h;
        }
    }
}

// fp16 1-term Bt: fp32[K, ldn] cols [ncol0, ncol0+Nv) -> fp16[Np, K] (plain hi)
__global__ __launch_bounds__(256)
void packBt16_1t_kernel(const float* __restrict__ in, __half* __restrict__ out,
                        int K, int Nv, int Np, int ldn, int ncol0)
{
    __shared__ float s[32][33];
    const int kb = blockIdx.x * 32, nb = blockIdx.y * 32;
    const int tx = threadIdx.x & 31, ty = threadIdx.x >> 5;
    #pragma unroll
    for (int r = 0; r < 32; r += 8) {
        const int k = kb + ty + r, n = nb + tx;
        s[ty + r][tx] = (k < K && n < Nv) ? in[(size_t)k * ldn + ncol0 + n] : 0.0f;
    }
    __syncthreads();
    #pragma unroll
    for (int r = 0; r < 32; r += 8) {
        const int n = nb + ty + r, k = kb + tx;
        if (n < Np && k < K)
            out[(size_t)n * K + k] = __float2half(s[tx][ty + r]);
    }
}

// fp16 1-term A: fp32 -> fp16 elementwise (flat, float4/thread)
__global__ __launch_bounds__(256)
void packA16_1t_kernel(const float* __restrict__ in, __half* __restrict__ out,
                       int total4)
{
    const int idx = blockIdx.x * 256 + threadIdx.x;
    if (idx >= total4) return;
    const float4 v = *(const float4*)(in + (size_t)idx * 4);
    __half2 a, b;
    a.x = __float2half(v.x); a.y = __float2half(v.y);
    b.x = __float2half(v.z); b.y = __float2half(v.w);
    *(__half2*)(out + (size_t)idx * 4)     = a;
    *(__half2*)(out + (size_t)idx * 4 + 2) = b;
}

// ---------------- causal depthwise conv (k=4) + SiLU + fp16 hi pack -----------
__global__ __launch_bounds__(256)
void conv_silu_kernel(const float* __restrict__ u, const float* __restrict__ w,
                      const float* __restrict__ bias, float* __restrict__ uc,
                      __half* __restrict__ uc16)
{
    constexpr int CHUNK = 16;
    int gid = blockIdx.x * blockDim.x + threadIdx.x;
    int d = gid & (D_INNER - 1);
    int rest = gid >> 11;
    int b = rest & (BATCH - 1);
    int chunk = rest >> 2;
    int l0 = chunk * CHUNK;

    const float w0 = w[d * 4 + 0], w1 = w[d * 4 + 1],
                w2 = w[d * 4 + 2], w3 = w[d * 4 + 3];
    const float bb = bias[d];

    const size_t base = ((size_t)b * SEQLEN + l0) * D_INNER + d;
    const float* up = u + base;
    float* op = uc + base;
    __half* pp = uc16 + base;

    float xm3, xm2, xm1;
    if (l0 == 0) { xm3 = 0.f; xm2 = 0.f; xm1 = 0.f; }
    else {
        xm3 = up[-3 * D_INNER];
        xm2 = up[-2 * D_INNER];
        xm1 = up[-1 * D_INNER];
    }
    #pragma unroll
    for (int i = 0; i < CHUNK; ++i) {
        float cur = up[(size_t)i * D_INNER];
        float v = fmaf(xm3, w0, fmaf(xm2, w1, fmaf(xm1, w2, fmaf(cur, w3, bb))));
        float s = v / (1.0f + __expf(-v));
        op[(size_t)i * D_INNER] = s;
        pp[(size_t)i * D_INNER] = __float2half(s);
        xm3 = xm2; xm2 = xm1; xm1 = cur;
    }
}

// ---------------- selective scan: 8 threads per (b,d) channel -----------------
// 2 states per thread, 3-level shfl reduction, emits fp16 hi y.
__global__ __launch_bounds__(128)
void scan_kernel(const float* __restrict__ delta, const float* __restrict__ u,
                 const float* __restrict__ z, const float* __restrict__ Bm,
                 const float* __restrict__ Cm, const float* __restrict__ A_log,
                 const float* __restrict__ Dp, __half* __restrict__ y16)
{
    const int t = blockIdx.x * blockDim.x + threadIdx.x;   // 65536 threads
    const int sub = t & 7;
    const int ch = t >> 3;
    const int d = ch & (D_INNER - 1);
    const int b = ch >> 11;
    const int n0 = sub * 2;

    const float a0 = -__expf(A_log[d * D_STATE + n0 + 0]);
    const float a1 = -__expf(A_log[d * D_STATE + n0 + 1]);

    const bool fast =
        fabsf(a0 + (float)(n0 + 1)) < 1e-3f * (n0 + 1) &&
        fabsf(a1 + (float)(n0 + 2)) < 1e-3f * (n0 + 2);

    const size_t base = (size_t)b * SEQLEN * D_INNER + d;
    const float* dp = delta + base;
    const float* up = u + base;
    const float* zp = z + base;
    __half* yp = y16 + base;
    const float2* Bp = (const float2*)Bm + (size_t)b * SEQLEN * 8 + sub;
    const float2* Cp = (const float2*)Cm + (size_t)b * SEQLEN * 8 + sub;
    const float Dd = Dp[d];

    float h0 = 0.f, h1 = 0.f;

    if (fast) {
        #pragma unroll 2
        for (int l = 0; l < SEQLEN; ++l) {
            const float dt = dp[(size_t)l * D_INNER];
            const float uu = up[(size_t)l * D_INNER];
            const float2 Bv = Bp[(size_t)l * 8];
            const float2 Cv = Cp[(size_t)l * 8];
            const float e  = __expf(-dt);
            const float e2 = e * e;
            const float e4 = e2 * e2;
            const float e8 = e4 * e4;
            float m = 1.f;
            if (sub & 1) m = e2;
            if (sub & 2) m *= e4;
            if (sub & 4) m *= e8;
            const float dA0 = m * e;
            const float dA1 = dA0 * e;
            const float xv = dt * uu;
            h0 = fmaf(h0, dA0, xv * Bv.x);
            h1 = fmaf(h1, dA1, xv * Bv.y);
            float yv = h0 * Cv.x + h1 * Cv.y;
            yv += __shfl_xor_sync(0xffffffffu, yv, 1);
            yv += __shfl_xor_sync(0xffffffffu, yv, 2);
            yv += __shfl_xor_sync(0xffffffffu, yv, 4);
            if (sub == 0) {
                const float zz = zp[(size_t)l * D_INNER];
                const float sz = zz / (1.0f + __expf(-zz));
                yp[(size_t)l * D_INNER] = __float2half((yv + uu * Dd) * sz);
            }
        }
    } else {
        #pragma unroll 2
        for (int l = 0; l < SEQLEN; ++l) {
            const float dt = dp[(size_t)l * D_INNER];
            const float uu = up[(size_t)l * D_INNER];
            const float2 Bv = Bp[(size_t)l * 8];
            const float2 Cv = Cp[(size_t)l * 8];
            const float dA0 = __expf(dt * a0);
            const float dA1 = __expf(dt * a1);
            const float xv = dt * uu;
            h0 = fmaf(h0, dA0, xv * Bv.x);
            h1 = fmaf(h1, dA1, xv * Bv.y);
            float yv = h0 * Cv.x + h1 * Cv.y;
            yv += __shfl_xor_sync(0xffffffffu, yv, 1);
            yv += __shfl_xor_sync(0xffffffffu, yv, 2);
            yv += __shfl_xor_sync(0xffffffffu, yv, 4);
            if (sub == 0) {
                const float zz = zp[(size_t)l * D_INNER];
                const float sz = zz / (1.0f + __expf(-zz));
                yp[(size_t)l * D_INNER] = __float2half((yv + uu * Dd) * sz);
            }
        }
    }
}

// ---------------- launch ------------------------------------------------------
extern "C" void kernel_launch(void* const* d_in, const int* in_sizes, int n_in,
                              void* d_out, int out_size)
{
    const float* x      = (const float*)d_in[0];
    const float* W_in   = (const float*)d_in[1];
    const float* conv_w = (const float*)d_in[2];
    const float* conv_b = (const float*)d_in[3];
    const float* W_xprj = (const float*)d_in[4];
    const float* W_dt   = (const float*)d_in[5];
    const float* b_dt   = (const float*)d_in[6];
    const float* A_log  = (const float*)d_in[7];
    const float* Dp     = (const float*)d_in[8];
    const float* W_out  = (const float*)d_in[9];
    float* out = (float*)d_out;

    float *u, *z, *uc, *delta, *Bm, *Cm;
    cudaGetSymbolAddress((void**)&u,     g_u);
    cudaGetSymbolAddress((void**)&z,     g_z);
    cudaGetSymbolAddress((void**)&uc,    g_uc);
    cudaGetSymbolAddress((void**)&delta, g_delta);
    cudaGetSymbolAddress((void**)&Bm,    g_Bm);
    cudaGetSymbolAddress((void**)&Cm,    g_Cm);

    __nv_bfloat16 *dtr2, *Wdt2;
    __half *x16, *Win16, *uc16, *Wxp16, *y16, *Wout16;
    cudaGetSymbolAddress((void**)&dtr2,   g_dtr2);
    cudaGetSymbolAddress((void**)&Wdt2,   g_Wdt2);
    cudaGetSymbolAddress((void**)&x16,    g_x16);
    cudaGetSymbolAddress((void**)&Win16,  g_Win16);
    cudaGetSymbolAddress((void**)&uc16,   g_uc16);
    cudaGetSymbolAddress((void**)&Wxp16,  g_Wxp16);
    cudaGetSymbolAddress((void**)&y16,    g_y16);
    cudaGetSymbolAddress((void**)&Wout16, g_Wout16);

    const int SM2 = GEMM_SMEM_WM(2);   // 98304
    const int SM1 = GEMM_SMEM_WM(1);   // 73728

    cudaFuncSetAttribute(gemm_tc<EPI_SPLIT, 1, 2>,    cudaFuncAttributeMaxDynamicSharedMemorySize, SM2);
    cudaFuncSetAttribute(gemm_tc<EPI_PLAIN, 1, 2>,    cudaFuncAttributeMaxDynamicSharedMemorySize, SM2);
    cudaFuncSetAttribute(gemm_tc<EPI_SOFTPLUS, 0, 2>, cudaFuncAttributeMaxDynamicSharedMemorySize, SM2);
    cudaFuncSetAttribute(gemm_tc<EPI_XPROJ, 1, 1>,    cudaFuncAttributeMaxDynamicSharedMemorySize, SM1);

    // weight packs up front (independent of activations)
    packBt16_1t_kernel<<<dim3(D_MODEL / 32, (2 * D_INNER) / 32), 256>>>(
        W_in, Win16, D_MODEL, 2 * D_INNER, 2 * D_INNER, 2 * D_INNER, 0);
    packBt16_1t_kernel<<<dim3(D_INNER / 32, 128 / 32), 256>>>(
        W_xprj, Wxp16, D_INNER, DT_RANK + 2 * D_STATE, 128, DT_RANK + 2 * D_STATE, 0);
    packBt_kernel<<<dim3((DT_RANK + 31) / 32, D_INNER / 32), 256>>>(
        W_dt, Wdt2, DT_RANK, D_INNER, D_INNER, D_INNER, 0);
    packBt16_1t_kernel<<<dim3(D_INNER / 32, D_MODEL / 32), 256>>>(
        W_out, Wout16, D_INNER, D_MODEL, D_MODEL, D_MODEL, 0);

    // activation pack for G1 (plain fp16 hi)
    packA16_1t_kernel<<<(ROWS * D_MODEL / 4 + 255) / 256, 256>>>(
        x, x16, ROWS * D_MODEL / 4);

    // ---- G1 fused: [u|z] = x @ W_in  (fp16 1-term, N=4096, split epi) ------
    gemm_tc<EPI_SPLIT, 1, 2><<<dim3((2 * D_INNER) / GBN, ROWS / 128), 256, SM2>>>(
        (const uint8_t*)x16, (const uint8_t*)Win16,
        D_MODEL, D_MODEL, D_MODEL, 2 * D_INNER,
        u, z, nullptr, nullptr);

    // ---- conv + silu + fp16 hi pack ----------------------------------------
    conv_silu_kernel<<<(BATCH * D_INNER * (SEQLEN / 16)) / 256, 256>>>(
        u, conv_w, conv_b, uc, uc16);

    // ---- G2: proj = uc @ W_xproj -> dtr2(bf16 3t)|Bm|Cm (fp16 1-term) ------
    gemm_tc<EPI_XPROJ, 1, 1><<<dim3(1, ROWS / 64), 256, SM1>>>(
        (const uint8_t*)uc16, (const uint8_t*)Wxp16,
        D_INNER, D_INNER, D_INNER, 128,
        Bm, Cm, dtr2, nullptr);

    // ---- G3: delta = softplus(dtr @ W_dt + b_dt) (bf16 3-term) -------------
    gemm_tc<EPI_SOFTPLUS, 0, 2><<<dim3(D_INNER / GBN, ROWS / 128), 256, SM2>>>(
        (const uint8_t*)dtr2, (const uint8_t*)Wdt2,
        3 * DT_RANK, 3 * DT_RANK, 3 * DT_RANK, D_INNER,
        delta, nullptr, nullptr, b_dt);

    // ---- scan + gating -> fp16 hi y (8 threads/channel) --------------------
    scan_kernel<<<(ROWS * 8) / 128, 128>>>(delta, uc, z, Bm, Cm, A_log, Dp, y16);

    // ---- G5: out = y @ W_out (fp16 1-term) ---------------------------------
    gemm_tc<EPI_PLAIN, 1, 2><<<dim3(D_MODEL / GBN, ROWS / 128), 256, SM2>>>(
        (const uint8_t*)y16, (const uint8_t*)Wout16,
        D_INNER, D_INNER, D_INNER, D_MODEL,
        out, nullptr, nullptr, nullptr);
}

// round 14
// speedup vs baseline: 1.3686x; 1.0377x over previous
#include <cuda_runtime.h>
#include <cuda_bf16.h>
#include <cuda_fp16.h>
#include <cstdint>
#include <math.h>

#define D_MODEL 1024
#define D_STATE 16
#define D_INNER 2048
#define DT_RANK 64
#define BATCH   4
#define SEQLEN  2048
#define ROWS    (BATCH * SEQLEN)   // 8192

// ---------------- device scratch (allocation-free rule) -----------------------
__device__ __align__(16) float g_delta[ROWS * D_INNER];   // fp32 (exp-amplified)
__device__ __align__(16) float g_Bm[ROWS * D_STATE];
__device__ __align__(16) float g_Cm[ROWS * D_STATE];

// fp16 operands / intermediates
__device__ __align__(16) __half g_x16  [ROWS * D_MODEL];             // G1 A
__device__ __align__(16) __half g_Win16[(2 * D_INNER) * D_MODEL];    // G1 B
__device__ __align__(16) __half g_u16  [ROWS * D_INNER];             // G1 out (u)
__device__ __align__(16) __half g_z16  [ROWS * D_INNER];             // G1 out (z)
__device__ __align__(16) __half g_uc16 [ROWS * D_INNER];             // conv out
__device__ __align__(16) __half g_Wxp16[128 * D_INNER];              // G2 B (hi)
__device__ __align__(16) __half g_dtr16[ROWS * 2 * DT_RANK];         // G2 epi out [hi|lo]
__device__ __align__(16) __half g_Wdt16[D_INNER * 2 * DT_RANK];      // G3 B [hi|hi]
__device__ __align__(16) __half g_y16  [ROWS * D_INNER];             // scan out
__device__ __align__(16) __half g_Wout16[D_MODEL * D_INNER];         // G5 B

// ---------------- helpers -----------------------------------------------------
__device__ __forceinline__ uint32_t smem_u32(const void* p) {
    uint32_t a;
    asm("{ .reg .u64 t; cvta.to.shared.u64 t, %1; cvt.u32.u64 %0, t; }" : "=r"(a) : "l"(p));
    return a;
}
__device__ __forceinline__ void cp16(uint32_t saddr, const void* gaddr) {
    asm volatile("cp.async.cg.shared.global [%0], [%1], 16;" :: "r"(saddr), "l"(gaddr));
}
#define SWZ(o) ((o) ^ ((((uint32_t)(o)) >> 3) & 0x70))

__device__ __forceinline__ void ldm_x4(uint32_t& r0, uint32_t& r1, uint32_t& r2, uint32_t& r3,
                                       uint32_t addr) {
    asm volatile("ldmatrix.sync.aligned.m8n8.x4.shared.b16 {%0,%1,%2,%3}, [%4];"
                 : "=r"(r0), "=r"(r1), "=r"(r2), "=r"(r3) : "r"(addr));
}
__device__ __forceinline__ void mma_fp16(float& c0, float& c1, float& c2, float& c3,
                                         uint32_t a0, uint32_t a1, uint32_t a2, uint32_t a3,
                                         uint32_t b0, uint32_t b1) {
    asm volatile("mma.sync.aligned.m16n8k16.row.col.f32.f16.f16.f32 "
                 "{%0,%1,%2,%3}, {%4,%5,%6,%7}, {%8,%9}, {%0,%1,%2,%3};"
                 : "+f"(c0), "+f"(c1), "+f"(c2), "+f"(c3)
                 : "r"(a0), "r"(a1), "r"(a2), "r"(a3), "r"(b0), "r"(b1));
}
__device__ __forceinline__ void split_fp16(float v, __half& h, __half& l) {
    h = __float2half(v);
    l = __float2half(v - __half2float(h));
}

// ---------------- mma.sync fp16 GEMM (strided operands) ------------------------
// C[M,N] = A[M,Kp] * Bt[N,Kp]^T with row strides lda/ldb (elements), fp32 accum.
// BM = WM*64, BN=128, BK=64 (128B rows, xor-swizzled), 3-stage cp.async pipeline,
// 256 threads = 8 warps in 4(m) x 2(n), warp tile (WM*16) x 64.
enum { EPI_PLAIN = 0, EPI_SPLIT16 = 1, EPI_SOFTPLUS = 2, EPI_XPROJ = 3 };

#define GBN 128
#define GBK 64
#define GSTAGES 3
#define GTILEB_B (GBN * GBK * 2)                 // 16384 bytes (B tile)
#define GEMM_SMEM_WM(WM) (GSTAGES * ((WM) * 64 * GBK * 2 + GTILEB_B))
// WM=2: 98304, WM=1: 73728

template <int EPI, int WM>
__global__ __launch_bounds__(256, 2)
void gemm_tc(const uint8_t* __restrict__ A, const uint8_t* __restrict__ Bt,
             int lda, int ldb, int Kp, int N,
             float* __restrict__ O0, float* __restrict__ O1,
             __half* __restrict__ H0, __half* __restrict__ H1,
             const float* __restrict__ bias)
{
    constexpr int BM = WM * 64;
    constexpr int GTILEA_B = BM * GBK * 2;
    constexpr int GSTAGE_B = GTILEA_B + GTILEB_B;

    extern __shared__ char smem[];
    const uint32_t sb = smem_u32(smem);
    const int tid = threadIdx.x;
    const int wid = tid >> 5, lid = tid & 31;
    const int wr = wid & 3;
    const int wc = wid >> 2;
    const int m0 = blockIdx.y * BM;
    const int n0 = blockIdx.x * GBN;
    const int chunks = Kp / GBK;

    const uint8_t* Ap = A + (size_t)m0 * lda * 2;
    const uint8_t* Bp = Bt + (size_t)n0 * ldb * 2;

    const int ldrow = tid >> 3;
    const int ldch  = tid & 7;

    auto load_stage = [&](int c) {
        const int s = c % GSTAGES;
        const uint32_t sa = sb + s * GSTAGE_B;
        const uint32_t sB = sa + GTILEA_B;
        const size_t k0b = (size_t)c * GBK * 2;
        #pragma unroll
        for (int j = 0; j < BM / 32; ++j) {
            const int r = ldrow + j * 32;
            const uint32_t so = SWZ(r * 128 + ldch * 16);
            cp16(sa + so, Ap + (size_t)r * lda * 2 + k0b + ldch * 16);
        }
        #pragma unroll
        for (int j = 0; j < 4; ++j) {
            const int r = ldrow + j * 32;
            const uint32_t so = SWZ(r * 128 + ldch * 16);
            cp16(sB + so, Bp + (size_t)r * ldb * 2 + k0b + ldch * 16);
        }
        asm volatile("cp.async.commit_group;" ::: "memory");
    };

    const int pre = (chunks < GSTAGES - 1) ? chunks : (GSTAGES - 1);
    for (int c = 0; c < pre; ++c) load_stage(c);

    float acc[WM][8][4];
    #pragma unroll
    for (int i = 0; i < WM; ++i)
        #pragma unroll
        for (int j = 0; j < 8; ++j)
            #pragma unroll
            for (int k = 0; k < 4; ++k) acc[i][j][k] = 0.f;

    const int lrow = lid & 15;
    const int lhalf = lid >> 4;

    for (int c = 0; c < chunks; ++c) {
        const int remaining = chunks - 1 - c;
        if (remaining >= 1) asm volatile("cp.async.wait_group 1;" ::: "memory");
        else                asm volatile("cp.async.wait_group 0;" ::: "memory");
        __syncthreads();

        if (c + GSTAGES - 1 < chunks) load_stage(c + GSTAGES - 1);

        const int s = c % GSTAGES;
        const uint32_t sa = sb + s * GSTAGE_B;
        const uint32_t sB = sa + GTILEA_B;

        #pragma unroll
        for (int kk = 0; kk < 4; ++kk) {
            uint32_t a[WM][4];
            #pragma unroll
            for (int wm = 0; wm < WM; ++wm) {
                const int row = wr * (WM * 16) + wm * 16 + lrow;
                const uint32_t off = SWZ(row * 128 + (kk * 2 + lhalf) * 16);
                ldm_x4(a[wm][0], a[wm][1], a[wm][2], a[wm][3], sa + off);
            }
            uint32_t b[4][4];
            #pragma unroll
            for (int g = 0; g < 4; ++g) {
                const int row = wc * 64 + g * 16 + lrow;
                const uint32_t off = SWZ(row * 128 + (kk * 2 + lhalf) * 16);
                ldm_x4(b[g][0], b[g][1], b[g][2], b[g][3], sB + off);
            }
            #pragma unroll
            for (int wm = 0; wm < WM; ++wm)
                #pragma unroll
                for (int j = 0; j < 8; ++j) {
                    const int g = j >> 1, h = j & 1;
                    mma_fp16(acc[wm][j][0], acc[wm][j][1], acc[wm][j][2], acc[wm][j][3],
                             a[wm][0], a[wm][1], a[wm][2], a[wm][3],
                             b[g][h], b[g][2 + h]);
                }
        }
    }

    // ---------------- epilogue ------------------------------------------------
    const int tq = lid >> 2;
    const int tr = lid & 3;
    const int H = N >> 1;
    #pragma unroll
    for (int wm = 0; wm < WM; ++wm) {
        #pragma unroll
        for (int j = 0; j < 8; ++j) {
            #pragma unroll
            for (int half = 0; half < 2; ++half) {
                const int gr = m0 + wr * (WM * 16) + wm * 16 + tq + half * 8;
                const int gc = n0 + wc * 64 + j * 8 + tr * 2;
                float v0 = acc[wm][j][half * 2 + 0];
                float v1 = acc[wm][j][half * 2 + 1];
                if (EPI == EPI_PLAIN) {
                    float2 v = {v0, v1};
                    *(float2*)&O0[(size_t)gr * N + gc] = v;
                } else if (EPI == EPI_SPLIT16) {
                    __half2 v; v.x = __float2half(v0); v.y = __float2half(v1);
                    if (gc < H) *(__half2*)&H0[(size_t)gr * H + gc] = v;
                    else        *(__half2*)&H1[(size_t)gr * H + (gc - H)] = v;
                } else if (EPI == EPI_SOFTPLUS) {
                    v0 += bias[gc]; v1 += bias[gc + 1];
                    v0 = (v0 > 20.0f) ? v0 : log1pf(__expf(v0));
                    v1 = (v1 > 20.0f) ? v1 : log1pf(__expf(v1));
                    float2 v = {v0, v1};
                    *(float2*)&O0[(size_t)gr * N + gc] = v;
                } else {
                    // EPI_XPROJ: 0..63 -> dtr16 fp16 [hi|lo] | 64..79 Bm | 80..95 Cm
                    if (gc < DT_RANK) {
                        __half h0, l0, h1, l1;
                        split_fp16(v0, h0, l0);
                        split_fp16(v1, h1, l1);
                        __half2 hh; hh.x = h0; hh.y = h1;
                        __half2 ll; ll.x = l0; ll.y = l1;
                        __half* q = H0 + (size_t)gr * 2 * DT_RANK + gc;
                        *(__half2*)(q)           = hh;
                        *(__half2*)(q + DT_RANK) = ll;
                    } else if (gc < DT_RANK + 16) {
                        float2 v = {v0, v1};
                        *(float2*)&O0[(size_t)gr * 16 + (gc - DT_RANK)] = v;
                    } else if (gc < DT_RANK + 32) {
                        float2 v = {v0, v1};
                        *(float2*)&O1[(size_t)gr * 16 + (gc - DT_RANK - 16)] = v;
                    }
                }
            }
        }
    }
}

// ---------------- packing kernels ---------------------------------------------
// fp16 1-term Bt: fp32[K, ldn] cols [ncol0, ncol0+Nv) -> fp16[Np, K] (plain hi)
__global__ __launch_bounds__(256)
void packBt16_1t_kernel(const float* __restrict__ in, __half* __restrict__ out,
                        int K, int Nv, int Np, int ldn, int ncol0)
{
    __shared__ float s[32][33];
    const int kb = blockIdx.x * 32, nb = blockIdx.y * 32;
    const int tx = threadIdx.x & 31, ty = threadIdx.x >> 5;
    #pragma unroll
    for (int r = 0; r < 32; r += 8) {
        const int k = kb + ty + r, n = nb + tx;
        s[ty + r][tx] = (k < K && n < Nv) ? in[(size_t)k * ldn + ncol0 + n] : 0.0f;
    }
    __syncthreads();
    #pragma unroll
    for (int r = 0; r < 32; r += 8) {
        const int n = nb + ty + r, k = kb + tx;
        if (n < Np && k < K)
            out[(size_t)n * K + k] = __float2half(s[tx][ty + r]);
    }
}

// fp16 dup Bt: fp32[K, ldn] cols [ncol0, ncol0+Nv) -> fp16[Np, 2K] = [hi|hi]
__global__ __launch_bounds__(256)
void packBt16_dup_kernel(const float* __restrict__ in, __half* __restrict__ out,
                         int K, int Nv, int Np, int ldn, int ncol0)
{
    __shared__ float s[32][33];
    const int kb = blockIdx.x * 32, nb = blockIdx.y * 32;
    const int tx = threadIdx.x & 31, ty = threadIdx.x >> 5;
    #pragma unroll
    for (int r = 0; r < 32; r += 8) {
        const int k = kb + ty + r, n = nb + tx;
        s[ty + r][tx] = (k < K && n < Nv) ? in[(size_t)k * ldn + ncol0 + n] : 0.0f;
    }
    __syncthreads();
    #pragma unroll
    for (int r = 0; r < 32; r += 8) {
        const int n = nb + ty + r, k = kb + tx;
        if (n < Np && k < K) {
            const __half h = __float2half(s[tx][ty + r]);
            __half* op = out + (size_t)n * 2 * K;
            op[k] = h; op[K + k] = h;
        }
    }
}

// fp16 1-term A: fp32 -> fp16 elementwise (flat, float4/thread)
__global__ __launch_bounds__(256)
void packA16_1t_kernel(const float* __restrict__ in, __half* __restrict__ out,
                       int total4)
{
    const int idx = blockIdx.x * 256 + threadIdx.x;
    if (idx >= total4) return;
    const float4 v = *(const float4*)(in + (size_t)idx * 4);
    __half2 a, b;
    a.x = __float2half(v.x); a.y = __float2half(v.y);
    b.x = __float2half(v.z); b.y = __float2half(v.w);
    *(__half2*)(out + (size_t)idx * 4)     = a;
    *(__half2*)(out + (size_t)idx * 4 + 2) = b;
}

// ---------------- causal depthwise conv (k=4) + SiLU (fp16 in/out) ------------
__global__ __launch_bounds__(256)
void conv_silu_kernel(const __half* __restrict__ u16, const float* __restrict__ w,
                      const float* __restrict__ bias, __half* __restrict__ uc16)
{
    constexpr int CHUNK = 16;
    int gid = blockIdx.x * blockDim.x + threadIdx.x;
    int d = gid & (D_INNER - 1);
    int rest = gid >> 11;
    int b = rest & (BATCH - 1);
    int chunk = rest >> 2;
    int l0 = chunk * CHUNK;

    const float w0 = w[d * 4 + 0], w1 = w[d * 4 + 1],
                w2 = w[d * 4 + 2], w3 = w[d * 4 + 3];
    const float bb = bias[d];

    const size_t base = ((size_t)b * SEQLEN + l0) * D_INNER + d;
    const __half* up = u16 + base;
    __half* op = uc16 + base;

    float xm3, xm2, xm1;
    if (l0 == 0) { xm3 = 0.f; xm2 = 0.f; xm1 = 0.f; }
    else {
        xm3 = __half2float(up[-3 * D_INNER]);
        xm2 = __half2float(up[-2 * D_INNER]);
        xm1 = __half2float(up[-1 * D_INNER]);
    }
    #pragma unroll
    for (int i = 0; i < CHUNK; ++i) {
        float cur = __half2float(up[(size_t)i * D_INNER]);
        float v = fmaf(xm3, w0, fmaf(xm2, w1, fmaf(xm1, w2, fmaf(cur, w3, bb))));
        float s = v / (1.0f + __expf(-v));
        op[(size_t)i * D_INNER] = __float2half(s);
        xm3 = xm2; xm2 = xm1; xm1 = cur;
    }
}

// ---------------- selective scan: 8 threads per (b,d) channel -----------------
// 2 states per thread, 3-level shfl reduction. Reads uc16/z16 fp16, delta fp32.
__global__ __launch_bounds__(128)
void scan_kernel(const float* __restrict__ delta, const __half* __restrict__ uc16,
                 const __half* __restrict__ z16, const float* __restrict__ Bm,
                 const float* __restrict__ Cm, const float* __restrict__ A_log,
                 const float* __restrict__ Dp, __half* __restrict__ y16)
{
    const int t = blockIdx.x * blockDim.x + threadIdx.x;   // 65536 threads
    const int sub = t & 7;
    const int ch = t >> 3;
    const int d = ch & (D_INNER - 1);
    const int b = ch >> 11;
    const int n0 = sub * 2;

    const float a0 = -__expf(A_log[d * D_STATE + n0 + 0]);
    const float a1 = -__expf(A_log[d * D_STATE + n0 + 1]);

    const bool fast =
        fabsf(a0 + (float)(n0 + 1)) < 1e-3f * (n0 + 1) &&
        fabsf(a1 + (float)(n0 + 2)) < 1e-3f * (n0 + 2);

    const size_t base = (size_t)b * SEQLEN * D_INNER + d;
    const float* dp = delta + base;
    const __half* up = uc16 + base;
    const __half* zp = z16 + base;
    __half* yp = y16 + base;
    const float2* Bp = (const float2*)Bm + (size_t)b * SEQLEN * 8 + sub;
    const float2* Cp = (const float2*)Cm + (size_t)b * SEQLEN * 8 + sub;
    const float Dd = Dp[d];

    float h0 = 0.f, h1 = 0.f;

    if (fast) {
        #pragma unroll 2
        for (int l = 0; l < SEQLEN; ++l) {
            const float dt = dp[(size_t)l * D_INNER];
            const float uu = __half2float(up[(size_t)l * D_INNER]);
            const float2 Bv = Bp[(size_t)l * 8];
            const float2 Cv = Cp[(size_t)l * 8];
            const float e  = __expf(-dt);
            const float e2 = e * e;
            const float e4 = e2 * e2;
            const float e8 = e4 * e4;
            float m = 1.f;
            if (sub & 1) m = e2;
            if (sub & 2) m *= e4;
            if (sub & 4) m *= e8;
            const float dA0 = m * e;
            const float dA1 = dA0 * e;
            const float xv = dt * uu;
            h0 = fmaf(h0, dA0, xv * Bv.x);
            h1 = fmaf(h1, dA1, xv * Bv.y);
            float yv = h0 * Cv.x + h1 * Cv.y;
            yv += __shfl_xor_sync(0xffffffffu, yv, 1);
            yv += __shfl_xor_sync(0xffffffffu, yv, 2);
            yv += __shfl_xor_sync(0xffffffffu, yv, 4);
            if (sub == 0) {
                const float zz = __half2float(zp[(size_t)l * D_INNER]);
                const float sz = zz / (1.0f + __expf(-zz));
                yp[(size_t)l * D_INNER] = __float2half((yv + uu * Dd) * sz);
            }
        }
    } else {
        #pragma unroll 2
        for (int l = 0; l < SEQLEN; ++l) {
            const float dt = dp[(size_t)l * D_INNER];
            const float uu = __half2float(up[(size_t)l * D_INNER]);
            const float2 Bv = Bp[(size_t)l * 8];
            const float2 Cv = Cp[(size_t)l * 8];
            const float dA0 = __expf(dt * a0);
            const float dA1 = __expf(dt * a1);
            const float xv = dt * uu;
            h0 = fmaf(h0, dA0, xv * Bv.x);
            h1 = fmaf(h1, dA1, xv * Bv.y);
            float yv = h0 * Cv.x + h1 * Cv.y;
            yv += __shfl_xor_sync(0xffffffffu, yv, 1);
            yv += __shfl_xor_sync(0xffffffffu, yv, 2);
            yv += __shfl_xor_sync(0xffffffffu, yv, 4);
            if (sub == 0) {
                const float zz = __half2float(zp[(size_t)l * D_INNER]);
                const float sz = zz / (1.0f + __expf(-zz));
                yp[(size_t)l * D_INNER] = __float2half((yv + uu * Dd) * sz);
            }
        }
    }
}

// ---------------- launch ------------------------------------------------------
extern "C" void kernel_launch(void* const* d_in, const int* in_sizes, int n_in,
                              void* d_out, int out_size)
{
    const float* x      = (const float*)d_in[0];
    const float* W_in   = (const float*)d_in[1];
    const float* conv_w = (const float*)d_in[2];
    const float* conv_b = (const float*)d_in[3];
    const float* W_xprj = (const float*)d_in[4];
    const float* W_dt   = (const float*)d_in[5];
    const float* b_dt   = (const float*)d_in[6];
    const float* A_log  = (const float*)d_in[7];
    const float* Dp     = (const float*)d_in[8];
    const float* W_out  = (const float*)d_in[9];
    float* out = (float*)d_out;

    float *delta, *Bm, *Cm;
    cudaGetSymbolAddress((void**)&delta, g_delta);
    cudaGetSymbolAddress((void**)&Bm,    g_Bm);
    cudaGetSymbolAddress((void**)&Cm,    g_Cm);

    __half *x16, *Win16, *u16, *z16, *uc16, *Wxp16, *dtr16, *Wdt16, *y16, *Wout16;
    cudaGetSymbolAddress((void**)&x16,    g_x16);
    cudaGetSymbolAddress((void**)&Win16,  g_Win16);
    cudaGetSymbolAddress((void**)&u16,    g_u16);
    cudaGetSymbolAddress((void**)&z16,    g_z16);
    cudaGetSymbolAddress((void**)&uc16,   g_uc16);
    cudaGetSymbolAddress((void**)&Wxp16,  g_Wxp16);
    cudaGetSymbolAddress((void**)&dtr16,  g_dtr16);
    cudaGetSymbolAddress((void**)&Wdt16,  g_Wdt16);
    cudaGetSymbolAddress((void**)&y16,    g_y16);
    cudaGetSymbolAddress((void**)&Wout16, g_Wout16);

    const int SM2 = GEMM_SMEM_WM(2);   // 98304
    const int SM1 = GEMM_SMEM_WM(1);   // 73728

    cudaFuncSetAttribute(gemm_tc<EPI_SPLIT16, 2>,  cudaFuncAttributeMaxDynamicSharedMemorySize, SM2);
    cudaFuncSetAttribute(gemm_tc<EPI_PLAIN, 2>,    cudaFuncAttributeMaxDynamicSharedMemorySize, SM2);
    cudaFuncSetAttribute(gemm_tc<EPI_SOFTPLUS, 2>, cudaFuncAttributeMaxDynamicSharedMemorySize, SM2);
    cudaFuncSetAttribute(gemm_tc<EPI_XPROJ, 1>,    cudaFuncAttributeMaxDynamicSharedMemorySize, SM1);

    // weight packs up front (independent of activations)
    packBt16_1t_kernel<<<dim3(D_MODEL / 32, (2 * D_INNER) / 32), 256>>>(
        W_in, Win16, D_MODEL, 2 * D_INNER, 2 * D_INNER, 2 * D_INNER, 0);
    packBt16_1t_kernel<<<dim3(D_INNER / 32, 128 / 32), 256>>>(
        W_xprj, Wxp16, D_INNER, DT_RANK + 2 * D_STATE, 128, DT_RANK + 2 * D_STATE, 0);
    packBt16_dup_kernel<<<dim3((DT_RANK + 31) / 32, D_INNER / 32), 256>>>(
        W_dt, Wdt16, DT_RANK, D_INNER, D_INNER, D_INNER, 0);
    packBt16_1t_kernel<<<dim3(D_INNER / 32, D_MODEL / 32), 256>>>(
        W_out, Wout16, D_INNER, D_MODEL, D_MODEL, D_MODEL, 0);

    // activation pack for G1 (plain fp16 hi)
    packA16_1t_kernel<<<(ROWS * D_MODEL / 4 + 255) / 256, 256>>>(
        x, x16, ROWS * D_MODEL / 4);

    // ---- G1 fused: [u16|z16] = x @ W_in  (fp16, N=4096, fp16 split epi) ----
    gemm_tc<EPI_SPLIT16, 2><<<dim3((2 * D_INNER) / GBN, ROWS / 128), 256, SM2>>>(
        (const uint8_t*)x16, (const uint8_t*)Win16,
        D_MODEL, D_MODEL, D_MODEL, 2 * D_INNER,
        nullptr, nullptr, u16, z16, nullptr);

    // ---- conv + silu (fp16 -> fp16) ----------------------------------------
    conv_silu_kernel<<<(BATCH * D_INNER * (SEQLEN / 16)) / 256, 256>>>(
        u16, conv_w, conv_b, uc16);

    // ---- G2: proj = uc @ W_xproj -> dtr16(fp16 2t)|Bm|Cm -------------------
    gemm_tc<EPI_XPROJ, 1><<<dim3(1, ROWS / 64), 256, SM1>>>(
        (const uint8_t*)uc16, (const uint8_t*)Wxp16,
        D_INNER, D_INNER, D_INNER, 128,
        Bm, Cm, dtr16, nullptr, nullptr);

    // ---- G3: delta = softplus(dtr @ W_dt + b_dt) (fp16 2-term, Kp=128) -----
    gemm_tc<EPI_SOFTPLUS, 2><<<dim3(D_INNER / GBN, ROWS / 128), 256, SM2>>>(
        (const uint8_t*)dtr16, (const uint8_t*)Wdt16,
        2 * DT_RANK, 2 * DT_RANK, 2 * DT_RANK, D_INNER,
        delta, nullptr, nullptr, nullptr, b_dt);

    // ---- scan + gating -> fp16 y (8 threads/channel) -----------------------
    scan_kernel<<<(ROWS * 8) / 128, 128>>>(delta, uc16, z16, Bm, Cm, A_log, Dp, y16);

    // ---- G5: out = y @ W_out (fp16 1-term) ---------------------------------
    gemm_tc<EPI_PLAIN, 2><<<dim3(D_MODEL / GBN, ROWS / 128), 256, SM2>>>(
        (const uint8_t*)y16, (const uint8_t*)Wout16,
        D_INNER, D_INNER, D_INNER, D_MODEL,
        out, nullptr, nullptr, nullptr, nullptr);
}

// round 15
// speedup vs baseline: 1.4002x; 1.0230x over previous
#include <cuda_runtime.h>
#include <cuda_bf16.h>
#include <cuda_fp16.h>
#include <cstdint>
#include <math.h>

#define D_MODEL 1024
#define D_STATE 16
#define D_INNER 2048
#define DT_RANK 64
#define BATCH   4
#define SEQLEN  2048
#define ROWS    (BATCH * SEQLEN)   // 8192

// ---------------- device scratch (allocation-free rule) -----------------------
__device__ __align__(16) float g_delta[ROWS * D_INNER];   // fp32 (exp-amplified)
__device__ __align__(16) float g_Bm[ROWS * D_STATE];
__device__ __align__(16) float g_Cm[ROWS * D_STATE];

// fp16 operands / intermediates
__device__ __align__(16) __half g_x16  [ROWS * D_MODEL];             // G1 A
__device__ __align__(16) __half g_Win16[(2 * D_INNER) * D_MODEL];    // G1 B
__device__ __align__(16) __half g_u16  [ROWS * D_INNER];             // G1 out (u)
__device__ __align__(16) __half g_z16  [ROWS * D_INNER];             // G1 out (z)
__device__ __align__(16) __half g_uc16 [ROWS * D_INNER];             // conv out
__device__ __align__(16) __half g_Wxp16[128 * D_INNER];              // G2 B (hi)
__device__ __align__(16) __half g_dtr16[ROWS * 2 * DT_RANK];         // G2 epi out [hi|lo]
__device__ __align__(16) __half g_Wdt16[D_INNER * 2 * DT_RANK];      // G3 B [hi|hi]
__device__ __align__(16) __half g_y16  [ROWS * D_INNER];             // scan out
__device__ __align__(16) __half g_Wout16[D_MODEL * D_INNER];         // G5 B

// ---------------- helpers -----------------------------------------------------
__device__ __forceinline__ uint32_t smem_u32(const void* p) {
    uint32_t a;
    asm("{ .reg .u64 t; cvta.to.shared.u64 t, %1; cvt.u32.u64 %0, t; }" : "=r"(a) : "l"(p));
    return a;
}
__device__ __forceinline__ void cp16(uint32_t saddr, const void* gaddr) {
    asm volatile("cp.async.cg.shared.global [%0], [%1], 16;" :: "r"(saddr), "l"(gaddr));
}
#define SWZ(o) ((o) ^ ((((uint32_t)(o)) >> 3) & 0x70))

__device__ __forceinline__ void ldm_x4(uint32_t& r0, uint32_t& r1, uint32_t& r2, uint32_t& r3,
                                       uint32_t addr) {
    asm volatile("ldmatrix.sync.aligned.m8n8.x4.shared.b16 {%0,%1,%2,%3}, [%4];"
                 : "=r"(r0), "=r"(r1), "=r"(r2), "=r"(r3) : "r"(addr));
}
__device__ __forceinline__ void mma_fp16(float& c0, float& c1, float& c2, float& c3,
                                         uint32_t a0, uint32_t a1, uint32_t a2, uint32_t a3,
                                         uint32_t b0, uint32_t b1) {
    asm volatile("mma.sync.aligned.m16n8k16.row.col.f32.f16.f16.f32 "
                 "{%0,%1,%2,%3}, {%4,%5,%6,%7}, {%8,%9}, {%0,%1,%2,%3};"
                 : "+f"(c0), "+f"(c1), "+f"(c2), "+f"(c3)
                 : "r"(a0), "r"(a1), "r"(a2), "r"(a3), "r"(b0), "r"(b1));
}
__device__ __forceinline__ void split_fp16(float v, __half& h, __half& l) {
    h = __float2half(v);
    l = __float2half(v - __half2float(h));
}

// ---------------- mma.sync fp16 GEMM (strided operands) ------------------------
// C[M,N] = A[M,Kp] * Bt[N,Kp]^T with row strides lda/ldb (elements), fp32 accum.
// BM = WM*64, BN=128, BK=64 (128B rows, xor-swizzled), 3-stage cp.async pipeline,
// 256 threads = 8 warps in 4(m) x 2(n), warp tile (WM*16) x 64.
enum { EPI_PLAIN = 0, EPI_SPLIT16 = 1, EPI_SOFTPLUS = 2, EPI_XPROJ = 3 };

#define GBN 128
#define GBK 64
#define GSTAGES 3
#define GTILEB_B (GBN * GBK * 2)                 // 16384 bytes (B tile)
#define GEMM_SMEM_WM(WM) (GSTAGES * ((WM) * 64 * GBK * 2 + GTILEB_B))
// WM=2: 98304, WM=1: 73728

template <int EPI, int WM>
__global__ __launch_bounds__(256, 2)
void gemm_tc(const uint8_t* __restrict__ A, const uint8_t* __restrict__ Bt,
             int lda, int ldb, int Kp, int N,
             float* __restrict__ O0, float* __restrict__ O1,
             __half* __restrict__ H0, __half* __restrict__ H1,
             const float* __restrict__ bias)
{
    constexpr int BM = WM * 64;
    constexpr int GTILEA_B = BM * GBK * 2;
    constexpr int GSTAGE_B = GTILEA_B + GTILEB_B;

    extern __shared__ char smem[];
    const uint32_t sb = smem_u32(smem);
    const int tid = threadIdx.x;
    const int wid = tid >> 5, lid = tid & 31;
    const int wr = wid & 3;
    const int wc = wid >> 2;
    const int m0 = blockIdx.y * BM;
    const int n0 = blockIdx.x * GBN;
    const int chunks = Kp / GBK;

    const uint8_t* Ap = A + (size_t)m0 * lda * 2;
    const uint8_t* Bp = Bt + (size_t)n0 * ldb * 2;

    const int ldrow = tid >> 3;
    const int ldch  = tid & 7;

    auto load_stage = [&](int c) {
        const int s = c % GSTAGES;
        const uint32_t sa = sb + s * GSTAGE_B;
        const uint32_t sB = sa + GTILEA_B;
        const size_t k0b = (size_t)c * GBK * 2;
        #pragma unroll
        for (int j = 0; j < BM / 32; ++j) {
            const int r = ldrow + j * 32;
            const uint32_t so = SWZ(r * 128 + ldch * 16);
            cp16(sa + so, Ap + (size_t)r * lda * 2 + k0b + ldch * 16);
        }
        #pragma unroll
        for (int j = 0; j < 4; ++j) {
            const int r = ldrow + j * 32;
            const uint32_t so = SWZ(r * 128 + ldch * 16);
            cp16(sB + so, Bp + (size_t)r * ldb * 2 + k0b + ldch * 16);
        }
        asm volatile("cp.async.commit_group;" ::: "memory");
    };

    const int pre = (chunks < GSTAGES - 1) ? chunks : (GSTAGES - 1);
    for (int c = 0; c < pre; ++c) load_stage(c);

    float acc[WM][8][4];
    #pragma unroll
    for (int i = 0; i < WM; ++i)
        #pragma unroll
        for (int j = 0; j < 8; ++j)
            #pragma unroll
            for (int k = 0; k < 4; ++k) acc[i][j][k] = 0.f;

    const int lrow = lid & 15;
    const int lhalf = lid >> 4;

    for (int c = 0; c < chunks; ++c) {
        const int remaining = chunks - 1 - c;
        if (remaining >= 1) asm volatile("cp.async.wait_group 1;" ::: "memory");
        else                asm volatile("cp.async.wait_group 0;" ::: "memory");
        __syncthreads();

        if (c + GSTAGES - 1 < chunks) load_stage(c + GSTAGES - 1);

        const int s = c % GSTAGES;
        const uint32_t sa = sb + s * GSTAGE_B;
        const uint32_t sB = sa + GTILEA_B;

        #pragma unroll
        for (int kk = 0; kk < 4; ++kk) {
            uint32_t a[WM][4];
            #pragma unroll
            for (int wm = 0; wm < WM; ++wm) {
                const int row = wr * (WM * 16) + wm * 16 + lrow;
                const uint32_t off = SWZ(row * 128 + (kk * 2 + lhalf) * 16);
                ldm_x4(a[wm][0], a[wm][1], a[wm][2], a[wm][3], sa + off);
            }
            uint32_t b[4][4];
            #pragma unroll
            for (int g = 0; g < 4; ++g) {
                const int row = wc * 64 + g * 16 + lrow;
                const uint32_t off = SWZ(row * 128 + (kk * 2 + lhalf) * 16);
                ldm_x4(b[g][0], b[g][1], b[g][2], b[g][3], sB + off);
            }
            #pragma unroll
            for (int wm = 0; wm < WM; ++wm)
                #pragma unroll
                for (int j = 0; j < 8; ++j) {
                    const int g = j >> 1, h = j & 1;
                    mma_fp16(acc[wm][j][0], acc[wm][j][1], acc[wm][j][2], acc[wm][j][3],
                             a[wm][0], a[wm][1], a[wm][2], a[wm][3],
                             b[g][h], b[g][2 + h]);
                }
        }
    }

    // ---------------- epilogue ------------------------------------------------
    const int tq = lid >> 2;
    const int tr = lid & 3;
    const int H = N >> 1;
    #pragma unroll
    for (int wm = 0; wm < WM; ++wm) {
        #pragma unroll
        for (int j = 0; j < 8; ++j) {
            #pragma unroll
            for (int half = 0; half < 2; ++half) {
                const int gr = m0 + wr * (WM * 16) + wm * 16 + tq + half * 8;
                const int gc = n0 + wc * 64 + j * 8 + tr * 2;
                float v0 = acc[wm][j][half * 2 + 0];
                float v1 = acc[wm][j][half * 2 + 1];
                if (EPI == EPI_PLAIN) {
                    float2 v = {v0, v1};
                    *(float2*)&O0[(size_t)gr * N + gc] = v;
                } else if (EPI == EPI_SPLIT16) {
                    __half2 v; v.x = __float2half(v0); v.y = __float2half(v1);
                    if (gc < H) *(__half2*)&H0[(size_t)gr * H + gc] = v;
                    else        *(__half2*)&H1[(size_t)gr * H + (gc - H)] = v;
                } else if (EPI == EPI_SOFTPLUS) {
                    v0 += bias[gc]; v1 += bias[gc + 1];
                    v0 = (v0 > 20.0f) ? v0 : log1pf(__expf(v0));
                    v1 = (v1 > 20.0f) ? v1 : log1pf(__expf(v1));
                    float2 v = {v0, v1};
                    *(float2*)&O0[(size_t)gr * N + gc] = v;
                } else {
                    // EPI_XPROJ: 0..63 -> dtr16 fp16 [hi|lo] | 64..79 Bm | 80..95 Cm
                    if (gc < DT_RANK) {
                        __half h0, l0, h1, l1;
                        split_fp16(v0, h0, l0);
                        split_fp16(v1, h1, l1);
                        __half2 hh; hh.x = h0; hh.y = h1;
                        __half2 ll; ll.x = l0; ll.y = l1;
                        __half* q = H0 + (size_t)gr * 2 * DT_RANK + gc;
                        *(__half2*)(q)           = hh;
                        *(__half2*)(q + DT_RANK) = ll;
                    } else if (gc < DT_RANK + 16) {
                        float2 v = {v0, v1};
                        *(float2*)&O0[(size_t)gr * 16 + (gc - DT_RANK)] = v;
                    } else if (gc < DT_RANK + 32) {
                        float2 v = {v0, v1};
                        *(float2*)&O1[(size_t)gr * 16 + (gc - DT_RANK - 16)] = v;
                    }
                }
            }
        }
    }
}

// ---------------- packing kernels ---------------------------------------------
// fp16 1-term Bt: fp32[K, ldn] cols [ncol0, ncol0+Nv) -> fp16[Np, K] (plain hi)
__global__ __launch_bounds__(256)
void packBt16_1t_kernel(const float* __restrict__ in, __half* __restrict__ out,
                        int K, int Nv, int Np, int ldn, int ncol0)
{
    __shared__ float s[32][33];
    const int kb = blockIdx.x * 32, nb = blockIdx.y * 32;
    const int tx = threadIdx.x & 31, ty = threadIdx.x >> 5;
    #pragma unroll
    for (int r = 0; r < 32; r += 8) {
        const int k = kb + ty + r, n = nb + tx;
        s[ty + r][tx] = (k < K && n < Nv) ? in[(size_t)k * ldn + ncol0 + n] : 0.0f;
    }
    __syncthreads();
    #pragma unroll
    for (int r = 0; r < 32; r += 8) {
        const int n = nb + ty + r, k = kb + tx;
        if (n < Np && k < K)
            out[(size_t)n * K + k] = __float2half(s[tx][ty + r]);
    }
}

// fp16 dup Bt: fp32[K, ldn] cols [ncol0, ncol0+Nv) -> fp16[Np, 2K] = [hi|hi]
__global__ __launch_bounds__(256)
void packBt16_dup_kernel(const float* __restrict__ in, __half* __restrict__ out,
                         int K, int Nv, int Np, int ldn, int ncol0)
{
    __shared__ float s[32][33];
    const int kb = blockIdx.x * 32, nb = blockIdx.y * 32;
    const int tx = threadIdx.x & 31, ty = threadIdx.x >> 5;
    #pragma unroll
    for (int r = 0; r < 32; r += 8) {
        const int k = kb + ty + r, n = nb + tx;
        s[ty + r][tx] = (k < K && n < Nv) ? in[(size_t)k * ldn + ncol0 + n] : 0.0f;
    }
    __syncthreads();
    #pragma unroll
    for (int r = 0; r < 32; r += 8) {
        const int n = nb + ty + r, k = kb + tx;
        if (n < Np && k < K) {
            const __half h = __float2half(s[tx][ty + r]);
            __half* op = out + (size_t)n * 2 * K;
            op[k] = h; op[K + k] = h;
        }
    }
}

// fp16 1-term A: fp32 -> fp16 elementwise (flat, float4/thread)
__global__ __launch_bounds__(256)
void packA16_1t_kernel(const float* __restrict__ in, __half* __restrict__ out,
                       int total4)
{
    const int idx = blockIdx.x * 256 + threadIdx.x;
    if (idx >= total4) return;
    const float4 v = *(const float4*)(in + (size_t)idx * 4);
    __half2 a, b;
    a.x = __float2half(v.x); a.y = __float2half(v.y);
    b.x = __float2half(v.z); b.y = __float2half(v.w);
    *(__half2*)(out + (size_t)idx * 4)     = a;
    *(__half2*)(out + (size_t)idx * 4 + 2) = b;
}

// ---------------- causal depthwise conv (k=4) + SiLU (fp16 in/out) ------------
__global__ __launch_bounds__(256)
void conv_silu_kernel(const __half* __restrict__ u16, const float* __restrict__ w,
                      const float* __restrict__ bias, __half* __restrict__ uc16)
{
    constexpr int CHUNK = 16;
    int gid = blockIdx.x * blockDim.x + threadIdx.x;
    int d = gid & (D_INNER - 1);
    int rest = gid >> 11;
    int b = rest & (BATCH - 1);
    int chunk = rest >> 2;
    int l0 = chunk * CHUNK;

    const float w0 = w[d * 4 + 0], w1 = w[d * 4 + 1],
                w2 = w[d * 4 + 2], w3 = w[d * 4 + 3];
    const float bb = bias[d];

    const size_t base = ((size_t)b * SEQLEN + l0) * D_INNER + d;
    const __half* up = u16 + base;
    __half* op = uc16 + base;

    float xm3, xm2, xm1;
    if (l0 == 0) { xm3 = 0.f; xm2 = 0.f; xm1 = 0.f; }
    else {
        xm3 = __half2float(up[-3 * D_INNER]);
        xm2 = __half2float(up[-2 * D_INNER]);
        xm1 = __half2float(up[-1 * D_INNER]);
    }
    #pragma unroll
    for (int i = 0; i < CHUNK; ++i) {
        float cur = __half2float(up[(size_t)i * D_INNER]);
        float v = fmaf(xm3, w0, fmaf(xm2, w1, fmaf(xm1, w2, fmaf(cur, w3, bb))));
        float s = v / (1.0f + __expf(-v));
        op[(size_t)i * D_INNER] = __float2half(s);
        xm3 = xm2; xm2 = xm1; xm1 = cur;
    }
}

// ---------------- selective scan: 8 threads per (b,d) channel -----------------
// 2 states per thread, 3-level shfl reduction, software-pipelined loads.
__global__ __launch_bounds__(128)
void scan_kernel(const float* __restrict__ delta, const __half* __restrict__ uc16,
                 const __half* __restrict__ z16, const float* __restrict__ Bm,
                 const float* __restrict__ Cm, const float* __restrict__ A_log,
                 const float* __restrict__ Dp, __half* __restrict__ y16)
{
    const int t = blockIdx.x * blockDim.x + threadIdx.x;   // 65536 threads
    const int sub = t & 7;
    const int ch = t >> 3;
    const int d = ch & (D_INNER - 1);
    const int b = ch >> 11;
    const int n0 = sub * 2;

    const float a0 = -__expf(A_log[d * D_STATE + n0 + 0]);
    const float a1 = -__expf(A_log[d * D_STATE + n0 + 1]);

    const bool fast =
        fabsf(a0 + (float)(n0 + 1)) < 1e-3f * (n0 + 1) &&
        fabsf(a1 + (float)(n0 + 2)) < 1e-3f * (n0 + 2);

    const size_t base = (size_t)b * SEQLEN * D_INNER + d;
    const float* dp = delta + base;
    const __half* up = uc16 + base;
    const __half* zp = z16 + base;
    __half* yp = y16 + base;
    const float2* Bp = (const float2*)Bm + (size_t)b * SEQLEN * 8 + sub;
    const float2* Cp = (const float2*)Cm + (size_t)b * SEQLEN * 8 + sub;
    const float Dd = Dp[d];

    float h0 = 0.f, h1 = 0.f;

    // software pipeline: current values in regs, prefetch l+1 during compute
    float dt = dp[0];
    float uu = __half2float(up[0]);
    float2 Bv = Bp[0];
    float2 Cv = Cp[0];

    if (fast) {
        #pragma unroll 2
        for (int l = 0; l < SEQLEN; ++l) {
            const int ln = (l + 1 < SEQLEN) ? (l + 1) : (SEQLEN - 1);
            const float  dt_n = dp[(size_t)ln * D_INNER];
            const float  uu_n = __half2float(up[(size_t)ln * D_INNER]);
            const float2 Bv_n = Bp[(size_t)ln * 8];
            const float2 Cv_n = Cp[(size_t)ln * 8];

            const float e  = __expf(-dt);
            const float e2 = e * e;
            const float e4 = e2 * e2;
            const float e8 = e4 * e4;
            float m = 1.f;
            if (sub & 1) m = e2;
            if (sub & 2) m *= e4;
            if (sub & 4) m *= e8;
            const float dA0 = m * e;
            const float dA1 = dA0 * e;
            const float xv = dt * uu;
            h0 = fmaf(h0, dA0, xv * Bv.x);
            h1 = fmaf(h1, dA1, xv * Bv.y);
            float yv = h0 * Cv.x + h1 * Cv.y;
            yv += __shfl_xor_sync(0xffffffffu, yv, 1);
            yv += __shfl_xor_sync(0xffffffffu, yv, 2);
            yv += __shfl_xor_sync(0xffffffffu, yv, 4);
            if (sub == 0) {
                const float zz = __half2float(zp[(size_t)l * D_INNER]);
                const float sz = zz / (1.0f + __expf(-zz));
                yp[(size_t)l * D_INNER] = __float2half((yv + uu * Dd) * sz);
            }
            dt = dt_n; uu = uu_n; Bv = Bv_n; Cv = Cv_n;
        }
    } else {
        #pragma unroll 2
        for (int l = 0; l < SEQLEN; ++l) {
            const int ln = (l + 1 < SEQLEN) ? (l + 1) : (SEQLEN - 1);
            const float  dt_n = dp[(size_t)ln * D_INNER];
            const float  uu_n = __half2float(up[(size_t)ln * D_INNER]);
            const float2 Bv_n = Bp[(size_t)ln * 8];
            const float2 Cv_n = Cp[(size_t)ln * 8];

            const float dA0 = __expf(dt * a0);
            const float dA1 = __expf(dt * a1);
            const float xv = dt * uu;
            h0 = fmaf(h0, dA0, xv * Bv.x);
            h1 = fmaf(h1, dA1, xv * Bv.y);
            float yv = h0 * Cv.x + h1 * Cv.y;
            yv += __shfl_xor_sync(0xffffffffu, yv, 1);
            yv += __shfl_xor_sync(0xffffffffu, yv, 2);
            yv += __shfl_xor_sync(0xffffffffu, yv, 4);
            if (sub == 0) {
                const float zz = __half2float(zp[(size_t)l * D_INNER]);
                const float sz = zz / (1.0f + __expf(-zz));
                yp[(size_t)l * D_INNER] = __float2half((yv + uu * Dd) * sz);
            }
            dt = dt_n; uu = uu_n; Bv = Bv_n; Cv = Cv_n;
        }
    }
}

// ---------------- launch ------------------------------------------------------
extern "C" void kernel_launch(void* const* d_in, const int* in_sizes, int n_in,
                              void* d_out, int out_size)
{
    const float* x      = (const float*)d_in[0];
    const float* W_in   = (const float*)d_in[1];
    const float* conv_w = (const float*)d_in[2];
    const float* conv_b = (const float*)d_in[3];
    const float* W_xprj = (const float*)d_in[4];
    const float* W_dt   = (const float*)d_in[5];
    const float* b_dt   = (const float*)d_in[6];
    const float* A_log  = (const float*)d_in[7];
    const float* Dp     = (const float*)d_in[8];
    const float* W_out  = (const float*)d_in[9];
    float* out = (float*)d_out;

    float *delta, *Bm, *Cm;
    cudaGetSymbolAddress((void**)&delta, g_delta);
    cudaGetSymbolAddress((void**)&Bm,    g_Bm);
    cudaGetSymbolAddress((void**)&Cm,    g_Cm);

    __half *x16, *Win16, *u16, *z16, *uc16, *Wxp16, *dtr16, *Wdt16, *y16, *Wout16;
    cudaGetSymbolAddress((void**)&x16,    g_x16);
    cudaGetSymbolAddress((void**)&Win16,  g_Win16);
    cudaGetSymbolAddress((void**)&u16,    g_u16);
    cudaGetSymbolAddress((void**)&z16,    g_z16);
    cudaGetSymbolAddress((void**)&uc16,   g_uc16);
    cudaGetSymbolAddress((void**)&Wxp16,  g_Wxp16);
    cudaGetSymbolAddress((void**)&dtr16,  g_dtr16);
    cudaGetSymbolAddress((void**)&Wdt16,  g_Wdt16);
    cudaGetSymbolAddress((void**)&y16,    g_y16);
    cudaGetSymbolAddress((void**)&Wout16, g_Wout16);

    const int SM2 = GEMM_SMEM_WM(2);   // 98304
    const int SM1 = GEMM_SMEM_WM(1);   // 73728

    cudaFuncSetAttribute(gemm_tc<EPI_SPLIT16, 2>,  cudaFuncAttributeMaxDynamicSharedMemorySize, SM2);
    cudaFuncSetAttribute(gemm_tc<EPI_PLAIN, 1>,    cudaFuncAttributeMaxDynamicSharedMemorySize, SM1);
    cudaFuncSetAttribute(gemm_tc<EPI_SOFTPLUS, 1>, cudaFuncAttributeMaxDynamicSharedMemorySize, SM1);
    cudaFuncSetAttribute(gemm_tc<EPI_XPROJ, 1>,    cudaFuncAttributeMaxDynamicSharedMemorySize, SM1);

    // weight packs up front (independent of activations)
    packBt16_1t_kernel<<<dim3(D_MODEL / 32, (2 * D_INNER) / 32), 256>>>(
        W_in, Win16, D_MODEL, 2 * D_INNER, 2 * D_INNER, 2 * D_INNER, 0);
    packBt16_1t_kernel<<<dim3(D_INNER / 32, 128 / 32), 256>>>(
        W_xprj, Wxp16, D_INNER, DT_RANK + 2 * D_STATE, 128, DT_RANK + 2 * D_STATE, 0);
    packBt16_dup_kernel<<<dim3((DT_RANK + 31) / 32, D_INNER / 32), 256>>>(
        W_dt, Wdt16, DT_RANK, D_INNER, D_INNER, D_INNER, 0);
    packBt16_1t_kernel<<<dim3(D_INNER / 32, D_MODEL / 32), 256>>>(
        W_out, Wout16, D_INNER, D_MODEL, D_MODEL, D_MODEL, 0);

    // activation pack for G1 (plain fp16 hi)
    packA16_1t_kernel<<<(ROWS * D_MODEL / 4 + 255) / 256, 256>>>(
        x, x16, ROWS * D_MODEL / 4);

    // ---- G1 fused: [u16|z16] = x @ W_in  (fp16, N=4096, fp16 split epi) ----
    gemm_tc<EPI_SPLIT16, 2><<<dim3((2 * D_INNER) / GBN, ROWS / 128), 256, SM2>>>(
        (const uint8_t*)x16, (const uint8_t*)Win16,
        D_MODEL, D_MODEL, D_MODEL, 2 * D_INNER,
        nullptr, nullptr, u16, z16, nullptr);

    // ---- conv + silu (fp16 -> fp16) ----------------------------------------
    conv_silu_kernel<<<(BATCH * D_INNER * (SEQLEN / 16)) / 256, 256>>>(
        u16, conv_w, conv_b, uc16);

    // ---- G2: proj = uc @ W_xproj -> dtr16(fp16 2t)|Bm|Cm -------------------
    gemm_tc<EPI_XPROJ, 1><<<dim3(1, ROWS / 64), 256, SM1>>>(
        (const uint8_t*)uc16, (const uint8_t*)Wxp16,
        D_INNER, D_INNER, D_INNER, 128,
        Bm, Cm, dtr16, nullptr, nullptr);

    // ---- G3: delta = softplus(dtr @ W_dt + b_dt) (fp16 2t, BM=64) ----------
    gemm_tc<EPI_SOFTPLUS, 1><<<dim3(D_INNER / GBN, ROWS / 64), 256, SM1>>>(
        (const uint8_t*)dtr16, (const uint8_t*)Wdt16,
        2 * DT_RANK, 2 * DT_RANK, 2 * DT_RANK, D_INNER,
        delta, nullptr, nullptr, nullptr, b_dt);

    // ---- scan + gating -> fp16 y (8 threads/channel, pipelined) ------------
    scan_kernel<<<(ROWS * 8) / 128, 128>>>(delta, uc16, z16, Bm, Cm, A_log, Dp, y16);

    // ---- G5: out = y @ W_out (fp16 1-term, BM=64) --------------------------
    gemm_tc<EPI_PLAIN, 1><<<dim3(D_MODEL / GBN, ROWS / 64), 256, SM1>>>(
        (const uint8_t*)y16, (const uint8_t*)Wout16,
        D_INNER, D_INNER, D_INNER, D_MODEL,
        out, nullptr, nullptr, nullptr, nullptr);
}